// round 1
// baseline (speedup 1.0000x reference)
#include <cuda_runtime.h>
#include <math.h>

#define D_MODEL 1024
#define NHEAD   16
#define D_K     64
#define BATCH   4
#define SEQ     2048
#define M_TOT   (BATCH * SEQ)   // 8192

// ---------------- scratch (device globals: allocation-free rule) ----------------
__device__ float g_Q[M_TOT * D_MODEL];
__device__ float g_K[M_TOT * D_MODEL];
__device__ float g_V[M_TOT * D_MODEL];
__device__ float g_C[M_TOT * D_MODEL];

// =================================================================================
// SGEMM: C[M,N] = A[M,K] @ W[N,K]^T + bias[N]
// Block tile 128x128, K-tile 8, 256 threads, 8x8 micro-tile per thread.
// All dims are multiples of tile sizes (M=8192, N=1024, K=1024) -> no bounds checks.
// =================================================================================
#define BM 128
#define BN 128
#define BK 8
#define SG_PAD 4   // smem row padding (floats) to break bank conflicts

__global__ __launch_bounds__(256, 2)
void sgemm_bias_kernel(const float* __restrict__ A, const float* __restrict__ W,
                       const float* __restrict__ bias, float* __restrict__ C,
                       int M, int N, int K)
{
    __shared__ float As[BK][BM + SG_PAD];
    __shared__ float Ws[BK][BN + SG_PAD];

    const int tid = threadIdx.x;
    const int tx  = tid & 15;       // 0..15 -> col group
    const int ty  = tid >> 4;       // 0..15 -> row group

    const int lr = tid >> 1;        // 0..127 : row within tile for loading
    const int lc = (tid & 1) << 2;  // 0 or 4 : k offset for float4 load

    const float* Aptr = A + (size_t)(blockIdx.y * BM + lr) * K + lc;
    const float* Wptr = W + (size_t)(blockIdx.x * BN + lr) * K + lc;

    float acc[8][8];
#pragma unroll
    for (int i = 0; i < 8; i++)
#pragma unroll
        for (int j = 0; j < 8; j++) acc[i][j] = 0.f;

    for (int k0 = 0; k0 < K; k0 += BK) {
        // prefetch before barrier
        float4 av = *(const float4*)(Aptr + k0);
        float4 wv = *(const float4*)(Wptr + k0);

        __syncthreads();   // protect previous iteration's smem reads
        As[lc + 0][lr] = av.x; As[lc + 1][lr] = av.y;
        As[lc + 2][lr] = av.z; As[lc + 3][lr] = av.w;
        Ws[lc + 0][lr] = wv.x; Ws[lc + 1][lr] = wv.y;
        Ws[lc + 2][lr] = wv.z; Ws[lc + 3][lr] = wv.w;
        __syncthreads();

#pragma unroll
        for (int kk = 0; kk < BK; kk++) {
            float a[8], b[8];
            float4 a0 = *(const float4*)&As[kk][ty * 8 + 0];
            float4 a1 = *(const float4*)&As[kk][ty * 8 + 4];
            float4 b0 = *(const float4*)&Ws[kk][tx * 8 + 0];
            float4 b1 = *(const float4*)&Ws[kk][tx * 8 + 4];
            a[0]=a0.x;a[1]=a0.y;a[2]=a0.z;a[3]=a0.w;a[4]=a1.x;a[5]=a1.y;a[6]=a1.z;a[7]=a1.w;
            b[0]=b0.x;b[1]=b0.y;b[2]=b0.z;b[3]=b0.w;b[4]=b1.x;b[5]=b1.y;b[6]=b1.z;b[7]=b1.w;
#pragma unroll
            for (int i = 0; i < 8; i++)
#pragma unroll
                for (int j = 0; j < 8; j++)
                    acc[i][j] = fmaf(a[i], b[j], acc[i][j]);
        }
    }

    const int row0 = blockIdx.y * BM + ty * 8;
    const int col0 = blockIdx.x * BN + tx * 8;
    float4 bv0 = *(const float4*)(bias + col0);
    float4 bv1 = *(const float4*)(bias + col0 + 4);
    float bb[8] = {bv0.x, bv0.y, bv0.z, bv0.w, bv1.x, bv1.y, bv1.z, bv1.w};

#pragma unroll
    for (int i = 0; i < 8; i++) {
        float4 o0, o1;
        o0.x = acc[i][0] + bb[0]; o0.y = acc[i][1] + bb[1];
        o0.z = acc[i][2] + bb[2]; o0.w = acc[i][3] + bb[3];
        o1.x = acc[i][4] + bb[4]; o1.y = acc[i][5] + bb[5];
        o1.z = acc[i][6] + bb[6]; o1.w = acc[i][7] + bb[7];
        *(float4*)(C + (size_t)(row0 + i) * N + col0)     = o0;
        *(float4*)(C + (size_t)(row0 + i) * N + col0 + 4) = o1;
    }
}

// =================================================================================
// Flash attention (fp32): grid (S/64, B*H), 256 threads.
// 64-row Q tile per block, stream over K/V in 64-row tiles, online softmax.
// Each thread: 4x4 micro-tile (ty*4+i rows, tx*4+j cols). Head dim = 64.
// =================================================================================
#define AST 65   // smem row stride (floats): odd -> conflict-free strided rows

__global__ __launch_bounds__(256, 2)
void attention_kernel(const float* __restrict__ Q, const float* __restrict__ K,
                      const float* __restrict__ V, float* __restrict__ O)
{
    extern __shared__ float sm[];
    float* sQ = sm;                 // [64][AST]  row = q,  col = d
    float* sK = sQ + 64 * AST;      // [64][AST]  row = d,  col = kv  (transposed)
    float* sV = sK + 64 * AST;      // [64][AST]  row = kv, col = d
    float* sP = sV + 64 * AST;      // [64][AST]  row = q,  col = kv

    const int tid = threadIdx.x;
    const int tx = tid & 15, ty = tid >> 4;
    const int bh = blockIdx.y;
    const int b = bh >> 4, h = bh & 15;
    const int q0 = blockIdx.x * 64;
    const float scale = 0.125f;   // 1/sqrt(64)

    const float* Qb = Q + (size_t)(b * SEQ + q0) * D_MODEL + h * D_K;
    const float* Kb = K + (size_t)(b * SEQ) * D_MODEL + h * D_K;
    const float* Vb = V + (size_t)(b * SEQ) * D_MODEL + h * D_K;

    // load Q tile (scaled)
    for (int i = tid; i < 64 * 16; i += 256) {
        int r = i >> 4, c4 = (i & 15) << 2;
        float4 v4 = *(const float4*)(Qb + (size_t)r * D_MODEL + c4);
        float* dst = sQ + r * AST + c4;
        dst[0] = v4.x * scale; dst[1] = v4.y * scale;
        dst[2] = v4.z * scale; dst[3] = v4.w * scale;
    }

    float m_i[4], l_i[4], o[4][4];
#pragma unroll
    for (int i = 0; i < 4; i++) {
        m_i[i] = -1e30f; l_i[i] = 0.f;
#pragma unroll
        for (int j = 0; j < 4; j++) o[i][j] = 0.f;
    }

    for (int kv0 = 0; kv0 < SEQ; kv0 += 64) {
        __syncthreads();   // prior iteration done with sK/sV
        for (int i = tid; i < 64 * 16; i += 256) {
            int r = i >> 4, c4 = (i & 15) << 2;
            float4 k4 = *(const float4*)(Kb + (size_t)(kv0 + r) * D_MODEL + c4);
            sK[(c4 + 0) * AST + r] = k4.x;   // transposed store
            sK[(c4 + 1) * AST + r] = k4.y;
            sK[(c4 + 2) * AST + r] = k4.z;
            sK[(c4 + 3) * AST + r] = k4.w;
            float4 v4 = *(const float4*)(Vb + (size_t)(kv0 + r) * D_MODEL + c4);
            float* dst = sV + r * AST + c4;
            dst[0] = v4.x; dst[1] = v4.y; dst[2] = v4.z; dst[3] = v4.w;
        }
        __syncthreads();

        // S = Q @ K^T (scaled)
        float s[4][4];
#pragma unroll
        for (int i = 0; i < 4; i++)
#pragma unroll
            for (int j = 0; j < 4; j++) s[i][j] = 0.f;

#pragma unroll 8
        for (int k = 0; k < 64; k++) {
            float qa[4], kb[4];
#pragma unroll
            for (int i = 0; i < 4; i++) qa[i] = sQ[(ty * 4 + i) * AST + k];
#pragma unroll
            for (int j = 0; j < 4; j++) kb[j] = sK[k * AST + tx * 4 + j];
#pragma unroll
            for (int i = 0; i < 4; i++)
#pragma unroll
                for (int j = 0; j < 4; j++)
                    s[i][j] = fmaf(qa[i], kb[j], s[i][j]);
        }

        // online softmax update per row
#pragma unroll
        for (int i = 0; i < 4; i++) {
            float rm = s[i][0];
#pragma unroll
            for (int j = 1; j < 4; j++) rm = fmaxf(rm, s[i][j]);
#pragma unroll
            for (int off = 8; off > 0; off >>= 1)
                rm = fmaxf(rm, __shfl_xor_sync(0xffffffffu, rm, off));
            float mn = fmaxf(m_i[i], rm);
            float alpha = __expf(m_i[i] - mn);
            m_i[i] = mn;
            float rs = 0.f;
#pragma unroll
            for (int j = 0; j < 4; j++) {
                s[i][j] = __expf(s[i][j] - mn);
                rs += s[i][j];
            }
#pragma unroll
            for (int off = 8; off > 0; off >>= 1)
                rs += __shfl_xor_sync(0xffffffffu, rs, off);
            l_i[i] = l_i[i] * alpha + rs;
#pragma unroll
            for (int j = 0; j < 4; j++) o[i][j] *= alpha;
            float* dst = sP + (ty * 4 + i) * AST + tx * 4;
            dst[0] = s[i][0]; dst[1] = s[i][1]; dst[2] = s[i][2]; dst[3] = s[i][3];
        }
        __syncthreads();

        // O += P @ V
#pragma unroll 8
        for (int k = 0; k < 64; k++) {
            float pa[4], vb[4];
#pragma unroll
            for (int i = 0; i < 4; i++) pa[i] = sP[(ty * 4 + i) * AST + k];
#pragma unroll
            for (int j = 0; j < 4; j++) vb[j] = sV[k * AST + tx * 4 + j];
#pragma unroll
            for (int i = 0; i < 4; i++)
#pragma unroll
                for (int j = 0; j < 4; j++)
                    o[i][j] = fmaf(pa[i], vb[j], o[i][j]);
        }
    }

    // epilogue: normalize and store
    float* Ob = (float*)O + (size_t)(b * SEQ + q0) * D_MODEL + h * D_K;
#pragma unroll
    for (int i = 0; i < 4; i++) {
        float inv = 1.f / l_i[i];
        float4 v4;
        v4.x = o[i][0] * inv; v4.y = o[i][1] * inv;
        v4.z = o[i][2] * inv; v4.w = o[i][3] * inv;
        *(float4*)(Ob + (size_t)(ty * 4 + i) * D_MODEL + tx * 4) = v4;
    }
}

// =================================================================================
// launch
// =================================================================================
extern "C" void kernel_launch(void* const* d_in, const int* in_sizes, int n_in,
                              void* d_out, int out_size)
{
    const float* x_q = (const float*)d_in[0];
    const float* x_k = (const float*)d_in[1];
    const float* x_v = (const float*)d_in[2];
    const float* wq  = (const float*)d_in[3];
    const float* bq  = (const float*)d_in[4];
    const float* wk  = (const float*)d_in[5];
    const float* bk  = (const float*)d_in[6];
    const float* wv  = (const float*)d_in[7];
    const float* bv  = (const float*)d_in[8];
    const float* wo  = (const float*)d_in[9];
    const float* bo  = (const float*)d_in[10];
    float* out = (float*)d_out;

    float *gq, *gk, *gv, *gc;
    cudaGetSymbolAddress((void**)&gq, g_Q);
    cudaGetSymbolAddress((void**)&gk, g_K);
    cudaGetSymbolAddress((void**)&gv, g_V);
    cudaGetSymbolAddress((void**)&gc, g_C);

    static int smem_set = 0;
    const int att_smem = 4 * 64 * AST * (int)sizeof(float);   // 66560 B
    if (!smem_set) {
        cudaFuncSetAttribute(attention_kernel,
                             cudaFuncAttributeMaxDynamicSharedMemorySize, att_smem);
        smem_set = 1;
    }

    dim3 gblk(256);
    dim3 ggrid(D_MODEL / BN, M_TOT / BM);   // (8, 64)

    // projections
    sgemm_bias_kernel<<<ggrid, gblk>>>(x_q, wq, bq, gq, M_TOT, D_MODEL, D_MODEL);
    sgemm_bias_kernel<<<ggrid, gblk>>>(x_k, wk, bk, gk, M_TOT, D_MODEL, D_MODEL);
    sgemm_bias_kernel<<<ggrid, gblk>>>(x_v, wv, bv, gv, M_TOT, D_MODEL, D_MODEL);

    // attention
    dim3 agrid(SEQ / 64, BATCH * NHEAD);    // (32, 64)
    attention_kernel<<<agrid, 256, att_smem>>>(gq, gk, gv, gc);

    // output projection
    sgemm_bias_kernel<<<ggrid, gblk>>>(gc, wo, bo, out, M_TOT, D_MODEL, D_MODEL);
}

// round 3
// speedup vs baseline: 1.3005x; 1.3005x over previous
#include <cuda_runtime.h>
#include <cuda_bf16.h>
#include <math.h>
#include <cstdint>

#define D_MODEL 1024
#define NHEAD   16
#define D_K     64
#define BATCH   4
#define SEQ     2048
#define M_TOT   (BATCH * SEQ)   // 8192

// ---------------- scratch (device globals: allocation-free rule) ----------------
__device__ float g_Q[M_TOT * D_MODEL];
__device__ float g_K[M_TOT * D_MODEL];
__device__ float g_V[M_TOT * D_MODEL];
__device__ float g_C[M_TOT * D_MODEL];

// bf16 hi/lo split buffers
__device__ __nv_bfloat16 g_XH0[M_TOT * D_MODEL];
__device__ __nv_bfloat16 g_XL0[M_TOT * D_MODEL];
__device__ __nv_bfloat16 g_XH1[M_TOT * D_MODEL];
__device__ __nv_bfloat16 g_XL1[M_TOT * D_MODEL];
__device__ __nv_bfloat16 g_XH2[M_TOT * D_MODEL];
__device__ __nv_bfloat16 g_XL2[M_TOT * D_MODEL];
__device__ __nv_bfloat16 g_CH [M_TOT * D_MODEL];
__device__ __nv_bfloat16 g_CL [M_TOT * D_MODEL];
__device__ __nv_bfloat16 g_WH0[D_MODEL * D_MODEL];
__device__ __nv_bfloat16 g_WL0[D_MODEL * D_MODEL];
__device__ __nv_bfloat16 g_WH1[D_MODEL * D_MODEL];
__device__ __nv_bfloat16 g_WL1[D_MODEL * D_MODEL];
__device__ __nv_bfloat16 g_WH2[D_MODEL * D_MODEL];
__device__ __nv_bfloat16 g_WL2[D_MODEL * D_MODEL];
__device__ __nv_bfloat16 g_WH3[D_MODEL * D_MODEL];
__device__ __nv_bfloat16 g_WL3[D_MODEL * D_MODEL];

// ====================== helpers (baseline PTX only: sm_80-class) ======================
__device__ __forceinline__ uint32_t smem_u32(const void* p) {
    uint32_t a;
    asm("{ .reg .u64 t; cvta.to.shared.u64 t, %1; cvt.u32.u64 %0, t; }" : "=r"(a) : "l"(p));
    return a;
}
__device__ __forceinline__ void ldsm4(uint32_t* r, uint32_t addr) {
    asm volatile("ldmatrix.sync.aligned.m8n8.x4.shared.b16 {%0,%1,%2,%3}, [%4];"
        : "=r"(r[0]), "=r"(r[1]), "=r"(r[2]), "=r"(r[3]) : "r"(addr));
}
__device__ __forceinline__ void mma_bf16(float* c, const uint32_t* a, const uint32_t* b) {
    asm volatile("mma.sync.aligned.m16n8k16.row.col.f32.bf16.bf16.f32 "
        "{%0,%1,%2,%3}, {%4,%5,%6,%7}, {%8,%9}, {%0,%1,%2,%3};"
        : "+f"(c[0]), "+f"(c[1]), "+f"(c[2]), "+f"(c[3])
        : "r"(a[0]), "r"(a[1]), "r"(a[2]), "r"(a[3]), "r"(b[0]), "r"(b[1]));
}
#define CP_ASYNC16(s, g) asm volatile("cp.async.cg.shared.global [%0], [%1], 16;" :: "r"(s), "l"(g) : "memory")
#define CP_COMMIT()      asm volatile("cp.async.commit_group;" ::: "memory")
#define CP_WAIT1()       asm volatile("cp.async.wait_group 1;" ::: "memory")

// =================================================================================
// convert: fp32 -> bf16 hi + bf16 lo residual
// =================================================================================
__global__ void split_kernel(const float* __restrict__ x,
                             __nv_bfloat16* __restrict__ hi,
                             __nv_bfloat16* __restrict__ lo, int n)
{
    int idx = (blockIdx.x * blockDim.x + threadIdx.x) * 4;
    if (idx >= n) return;
    float4 v = *(const float4*)(x + idx);
    __nv_bfloat16 h0 = __float2bfloat16(v.x);
    __nv_bfloat16 h1 = __float2bfloat16(v.y);
    __nv_bfloat16 h2 = __float2bfloat16(v.z);
    __nv_bfloat16 h3 = __float2bfloat16(v.w);
    __nv_bfloat16 l0 = __float2bfloat16(v.x - __bfloat162float(h0));
    __nv_bfloat16 l1 = __float2bfloat16(v.y - __bfloat162float(h1));
    __nv_bfloat16 l2 = __float2bfloat16(v.z - __bfloat162float(h2));
    __nv_bfloat16 l3 = __float2bfloat16(v.w - __bfloat162float(h3));
    *(__nv_bfloat162*)(hi + idx)     = __nv_bfloat162(h0, h1);
    *(__nv_bfloat162*)(hi + idx + 2) = __nv_bfloat162(h2, h3);
    *(__nv_bfloat162*)(lo + idx)     = __nv_bfloat162(l0, l1);
    *(__nv_bfloat162*)(lo + idx + 2) = __nv_bfloat162(l2, l3);
}

// =================================================================================
// mma.sync GEMM: C[M,N] = (Ah+Al)[M,K] @ (Wh+Wl)[N,K]^T + bias  (3-term bf16 split)
// CTA 128x128, BK=32, 256 thr (8 warps, warp tile 64x32), cp.async 2-stage pipeline.
// smem tile rows padded to 40 bf16 (80B) -> conflict-free ldmatrix & stores.
// =================================================================================
#define G_ROWPAD   40                      // bf16 elems per smem row
#define G_TILE_B   (128 * G_ROWPAD * 2)    // 10240 bytes per [128x32] tile
#define G_STAGE_B  (4 * G_TILE_B)          // Ah, Al, Wh, Wl
#define G_SMEM_TOT (2 * G_STAGE_B)         // 81920

__global__ __launch_bounds__(256)
void gemm_mma_kernel(const __nv_bfloat16* __restrict__ Ah,
                     const __nv_bfloat16* __restrict__ Al,
                     const __nv_bfloat16* __restrict__ Wh,
                     const __nv_bfloat16* __restrict__ Wl,
                     const float* __restrict__ bias,
                     float* __restrict__ C)
{
    extern __shared__ __align__(128) char smem[];
    const uint32_t sb = smem_u32(smem);
    const int tid  = threadIdx.x;
    const int lane = tid & 31, wid = tid >> 5;
    const int warp_m = wid >> 2;           // 0..1  (64 rows each)
    const int warp_n = wid & 3;            // 0..3  (32 cols each)
    const int row0 = blockIdx.y * 128;
    const int col0 = blockIdx.x * 128;

    const __nv_bfloat16* srcs[4] = {
        Ah + (size_t)row0 * 1024, Al + (size_t)row0 * 1024,
        Wh + (size_t)col0 * 1024, Wl + (size_t)col0 * 1024 };

    // cp.async mapping: row per lane (conflict-free smem stores), 2x16B chunks/thread/tile
    const int ld_row = tid & 127;
    const int ld_c0  = (tid >> 7) * 2;

    float acc[4][4][4];
#pragma unroll
    for (int a = 0; a < 4; a++)
#pragma unroll
        for (int b = 0; b < 4; b++)
#pragma unroll
            for (int c = 0; c < 4; c++) acc[a][b][c] = 0.f;

    // ldmatrix lane address components
    const int la   = lane & 7;
    const int lb8  = (lane >> 3) & 1;
    const int lb16 = lane >> 4;
    const uint32_t a_off = (uint32_t)((la + lb8 * 8) * (G_ROWPAD * 2) + lb16 * 16);
    const uint32_t b_off = (uint32_t)((la + lb16 * 8) * (G_ROWPAD * 2) + lb8 * 16);

    auto load_stage = [&](int buf, int k0) {
        const uint32_t sbase = sb + buf * G_STAGE_B + (uint32_t)ld_row * (G_ROWPAD * 2);
#pragma unroll
        for (int t = 0; t < 4; t++) {
            const __nv_bfloat16* g = srcs[t] + (size_t)ld_row * 1024 + k0;
            const uint32_t s = sbase + t * G_TILE_B;
#pragma unroll
            for (int u = 0; u < 2; u++) {
                const int c = ld_c0 + u;
                CP_ASYNC16(s + c * 16, (const void*)(g + c * 8));
            }
        }
    };

    auto compute_stage = [&](int buf) {
        const uint32_t s  = sb + buf * G_STAGE_B;
        const uint32_t aH = s + 0 * G_TILE_B + (uint32_t)(warp_m * 64) * (G_ROWPAD * 2);
        const uint32_t aL = s + 1 * G_TILE_B + (uint32_t)(warp_m * 64) * (G_ROWPAD * 2);
        const uint32_t bH = s + 2 * G_TILE_B + (uint32_t)(warp_n * 32) * (G_ROWPAD * 2);
        const uint32_t bL = s + 3 * G_TILE_B + (uint32_t)(warp_n * 32) * (G_ROWPAD * 2);
#pragma unroll
        for (int ks = 0; ks < 2; ks++) {
            uint32_t ah[4][4], al[4][4], bh[2][4], bl[2][4];
#pragma unroll
            for (int mt = 0; mt < 4; mt++) {
                ldsm4(ah[mt], aH + (uint32_t)(mt * 16) * (G_ROWPAD * 2) + ks * 32 + a_off);
                ldsm4(al[mt], aL + (uint32_t)(mt * 16) * (G_ROWPAD * 2) + ks * 32 + a_off);
            }
#pragma unroll
            for (int p = 0; p < 2; p++) {
                ldsm4(bh[p], bH + (uint32_t)(p * 16) * (G_ROWPAD * 2) + ks * 32 + b_off);
                ldsm4(bl[p], bL + (uint32_t)(p * 16) * (G_ROWPAD * 2) + ks * 32 + b_off);
            }
#pragma unroll
            for (int mt = 0; mt < 4; mt++)
#pragma unroll
                for (int nt = 0; nt < 4; nt++) {
                    float* c = acc[mt][nt];
                    const uint32_t* bhp = &bh[nt >> 1][(nt & 1) * 2];
                    const uint32_t* blp = &bl[nt >> 1][(nt & 1) * 2];
                    mma_bf16(c, ah[mt], bhp);   // Ah * Bh
                    mma_bf16(c, ah[mt], blp);   // Ah * Bl
                    mma_bf16(c, al[mt], bhp);   // Al * Bh
                }
        }
    };

    // pipeline: 2 stages
    load_stage(0, 0);  CP_COMMIT();
    load_stage(1, 32); CP_COMMIT();

    for (int c = 0; c < 32; c++) {       // 32 chunks of BK=32 -> K=1024
        CP_WAIT1();
        __syncthreads();
        const int buf = c & 1;
        compute_stage(buf);
        __syncthreads();
        if (c + 2 < 32) load_stage(buf, (c + 2) * 32);
        CP_COMMIT();
    }

    // epilogue: fragments -> gmem with bias
    const int r_base = row0 + warp_m * 64;
    const int c_base = col0 + warp_n * 32;
#pragma unroll
    for (int mt = 0; mt < 4; mt++) {
        const int r = r_base + mt * 16 + (lane >> 2);
#pragma unroll
        for (int nt = 0; nt < 4; nt++) {
            const int cc = c_base + nt * 8 + (lane & 3) * 2;
            const float b0 = __ldg(bias + cc), b1 = __ldg(bias + cc + 1);
            float2 o0, o1;
            o0.x = acc[mt][nt][0] + b0; o0.y = acc[mt][nt][1] + b1;
            o1.x = acc[mt][nt][2] + b0; o1.y = acc[mt][nt][3] + b1;
            *(float2*)(C + (size_t)r * 1024 + cc)       = o0;
            *(float2*)(C + (size_t)(r + 8) * 1024 + cc) = o1;
        }
    }
}

// =================================================================================
// Flash attention (fp32) — unchanged from R1 (fp32 roofline; R4 target)
// =================================================================================
#define AST 65

__global__ __launch_bounds__(256, 2)
void attention_kernel(const float* __restrict__ Q, const float* __restrict__ K,
                      const float* __restrict__ V, float* __restrict__ O)
{
    extern __shared__ float sm[];
    float* sQ = sm;
    float* sK = sQ + 64 * AST;
    float* sV = sK + 64 * AST;
    float* sP = sV + 64 * AST;

    const int tid = threadIdx.x;
    const int tx = tid & 15, ty = tid >> 4;
    const int bh = blockIdx.y;
    const int b = bh >> 4, h = bh & 15;
    const int q0 = blockIdx.x * 64;
    const float scale = 0.125f;

    const float* Qb = Q + (size_t)(b * SEQ + q0) * D_MODEL + h * D_K;
    const float* Kb = K + (size_t)(b * SEQ) * D_MODEL + h * D_K;
    const float* Vb = V + (size_t)(b * SEQ) * D_MODEL + h * D_K;

    for (int i = tid; i < 64 * 16; i += 256) {
        int r = i >> 4, c4 = (i & 15) << 2;
        float4 v4 = *(const float4*)(Qb + (size_t)r * D_MODEL + c4);
        float* dst = sQ + r * AST + c4;
        dst[0] = v4.x * scale; dst[1] = v4.y * scale;
        dst[2] = v4.z * scale; dst[3] = v4.w * scale;
    }

    float m_i[4], l_i[4], o[4][4];
#pragma unroll
    for (int i = 0; i < 4; i++) {
        m_i[i] = -1e30f; l_i[i] = 0.f;
#pragma unroll
        for (int j = 0; j < 4; j++) o[i][j] = 0.f;
    }

    for (int kv0 = 0; kv0 < SEQ; kv0 += 64) {
        __syncthreads();
        for (int i = tid; i < 64 * 16; i += 256) {
            int r = i >> 4, c4 = (i & 15) << 2;
            float4 k4 = *(const float4*)(Kb + (size_t)(kv0 + r) * D_MODEL + c4);
            sK[(c4 + 0) * AST + r] = k4.x;
            sK[(c4 + 1) * AST + r] = k4.y;
            sK[(c4 + 2) * AST + r] = k4.z;
            sK[(c4 + 3) * AST + r] = k4.w;
            float4 v4 = *(const float4*)(Vb + (size_t)(kv0 + r) * D_MODEL + c4);
            float* dst = sV + r * AST + c4;
            dst[0] = v4.x; dst[1] = v4.y; dst[2] = v4.z; dst[3] = v4.w;
        }
        __syncthreads();

        float s[4][4];
#pragma unroll
        for (int i = 0; i < 4; i++)
#pragma unroll
            for (int j = 0; j < 4; j++) s[i][j] = 0.f;

#pragma unroll 8
        for (int k = 0; k < 64; k++) {
            float qa[4], kb[4];
#pragma unroll
            for (int i = 0; i < 4; i++) qa[i] = sQ[(ty * 4 + i) * AST + k];
#pragma unroll
            for (int j = 0; j < 4; j++) kb[j] = sK[k * AST + tx * 4 + j];
#pragma unroll
            for (int i = 0; i < 4; i++)
#pragma unroll
                for (int j = 0; j < 4; j++)
                    s[i][j] = fmaf(qa[i], kb[j], s[i][j]);
        }

#pragma unroll
        for (int i = 0; i < 4; i++) {
            float rm = s[i][0];
#pragma unroll
            for (int j = 1; j < 4; j++) rm = fmaxf(rm, s[i][j]);
#pragma unroll
            for (int off = 8; off > 0; off >>= 1)
                rm = fmaxf(rm, __shfl_xor_sync(0xffffffffu, rm, off));
            float mn = fmaxf(m_i[i], rm);
            float alpha = __expf(m_i[i] - mn);
            m_i[i] = mn;
            float rs = 0.f;
#pragma unroll
            for (int j = 0; j < 4; j++) {
                s[i][j] = __expf(s[i][j] - mn);
                rs += s[i][j];
            }
#pragma unroll
            for (int off = 8; off > 0; off >>= 1)
                rs += __shfl_xor_sync(0xffffffffu, rs, off);
            l_i[i] = l_i[i] * alpha + rs;
#pragma unroll
            for (int j = 0; j < 4; j++) o[i][j] *= alpha;
            float* dst = sP + (ty * 4 + i) * AST + tx * 4;
            dst[0] = s[i][0]; dst[1] = s[i][1]; dst[2] = s[i][2]; dst[3] = s[i][3];
        }
        __syncthreads();

#pragma unroll 8
        for (int k = 0; k < 64; k++) {
            float pa[4], vb[4];
#pragma unroll
            for (int i = 0; i < 4; i++) pa[i] = sP[(ty * 4 + i) * AST + k];
#pragma unroll
            for (int j = 0; j < 4; j++) vb[j] = sV[k * AST + tx * 4 + j];
#pragma unroll
            for (int i = 0; i < 4; i++)
#pragma unroll
                for (int j = 0; j < 4; j++)
                    o[i][j] = fmaf(pa[i], vb[j], o[i][j]);
        }
    }

    float* Ob = (float*)O + (size_t)(b * SEQ + q0) * D_MODEL + h * D_K;
#pragma unroll
    for (int i = 0; i < 4; i++) {
        float inv = 1.f / l_i[i];
        float4 v4;
        v4.x = o[i][0] * inv; v4.y = o[i][1] * inv;
        v4.z = o[i][2] * inv; v4.w = o[i][3] * inv;
        *(float4*)(Ob + (size_t)(ty * 4 + i) * D_MODEL + tx * 4) = v4;
    }
}

// =================================================================================
// launch
// =================================================================================
extern "C" void kernel_launch(void* const* d_in, const int* in_sizes, int n_in,
                              void* d_out, int out_size)
{
    const float* x_q = (const float*)d_in[0];
    const float* x_k = (const float*)d_in[1];
    const float* x_v = (const float*)d_in[2];
    const float* wq  = (const float*)d_in[3];
    const float* bq  = (const float*)d_in[4];
    const float* wk  = (const float*)d_in[5];
    const float* bk  = (const float*)d_in[6];
    const float* wv  = (const float*)d_in[7];
    const float* bv  = (const float*)d_in[8];
    const float* wo  = (const float*)d_in[9];
    const float* bo  = (const float*)d_in[10];
    float* out = (float*)d_out;

    float *gq, *gk, *gv, *gc;
    cudaGetSymbolAddress((void**)&gq, g_Q);
    cudaGetSymbolAddress((void**)&gk, g_K);
    cudaGetSymbolAddress((void**)&gv, g_V);
    cudaGetSymbolAddress((void**)&gc, g_C);

    __nv_bfloat16 *xh0, *xl0, *xh1, *xl1, *xh2, *xl2, *ch, *cl;
    __nv_bfloat16 *wh0, *wl0, *wh1, *wl1, *wh2, *wl2, *wh3, *wl3;
    cudaGetSymbolAddress((void**)&xh0, g_XH0); cudaGetSymbolAddress((void**)&xl0, g_XL0);
    cudaGetSymbolAddress((void**)&xh1, g_XH1); cudaGetSymbolAddress((void**)&xl1, g_XL1);
    cudaGetSymbolAddress((void**)&xh2, g_XH2); cudaGetSymbolAddress((void**)&xl2, g_XL2);
    cudaGetSymbolAddress((void**)&ch,  g_CH);  cudaGetSymbolAddress((void**)&cl,  g_CL);
    cudaGetSymbolAddress((void**)&wh0, g_WH0); cudaGetSymbolAddress((void**)&wl0, g_WL0);
    cudaGetSymbolAddress((void**)&wh1, g_WH1); cudaGetSymbolAddress((void**)&wl1, g_WL1);
    cudaGetSymbolAddress((void**)&wh2, g_WH2); cudaGetSymbolAddress((void**)&wl2, g_WL2);
    cudaGetSymbolAddress((void**)&wh3, g_WH3); cudaGetSymbolAddress((void**)&wl3, g_WL3);

    static int attr_set = 0;
    const int att_smem = 4 * 64 * AST * (int)sizeof(float);
    if (!attr_set) {
        cudaFuncSetAttribute(attention_kernel,
                             cudaFuncAttributeMaxDynamicSharedMemorySize, att_smem);
        cudaFuncSetAttribute(gemm_mma_kernel,
                             cudaFuncAttributeMaxDynamicSharedMemorySize, G_SMEM_TOT);
        attr_set = 1;
    }

    const int NX = M_TOT * D_MODEL;       // 8388608
    const int NW = D_MODEL * D_MODEL;     // 1048576
    dim3 cb(256);
    dim3 cgx((NX / 4 + 255) / 256);
    dim3 cgw((NW / 4 + 255) / 256);

    // fp32 -> bf16 hi/lo splits
    split_kernel<<<cgx, cb>>>(x_q, xh0, xl0, NX);
    split_kernel<<<cgx, cb>>>(x_k, xh1, xl1, NX);
    split_kernel<<<cgx, cb>>>(x_v, xh2, xl2, NX);
    split_kernel<<<cgw, cb>>>(wq, wh0, wl0, NW);
    split_kernel<<<cgw, cb>>>(wk, wh1, wl1, NW);
    split_kernel<<<cgw, cb>>>(wv, wh2, wl2, NW);
    split_kernel<<<cgw, cb>>>(wo, wh3, wl3, NW);

    // projections on tensor cores (mma.sync)
    dim3 ggrid(D_MODEL / 128, M_TOT / 128);   // (8, 64)
    gemm_mma_kernel<<<ggrid, 256, G_SMEM_TOT>>>(xh0, xl0, wh0, wl0, bq, gq);
    gemm_mma_kernel<<<ggrid, 256, G_SMEM_TOT>>>(xh1, xl1, wh1, wl1, bk, gk);
    gemm_mma_kernel<<<ggrid, 256, G_SMEM_TOT>>>(xh2, xl2, wh2, wl2, bv, gv);

    // attention (fp32)
    dim3 agrid(SEQ / 64, BATCH * NHEAD);
    attention_kernel<<<agrid, 256, att_smem>>>(gq, gk, gv, gc);

    // output projection
    split_kernel<<<cgx, cb>>>(gc, ch, cl, NX);
    gemm_mma_kernel<<<ggrid, 256, G_SMEM_TOT>>>(ch, cl, wh3, wl3, bo, out);
}

// round 4
// speedup vs baseline: 2.4566x; 1.8889x over previous
#include <cuda_runtime.h>
#include <cuda_bf16.h>
#include <math.h>
#include <cstdint>

#define D_MODEL 1024
#define NHEAD   16
#define D_K     64
#define BATCH   4
#define SEQ     2048
#define M_TOT   (BATCH * SEQ)   // 8192

// ---------------- scratch (device globals: allocation-free rule) ----------------
__device__ float g_Q[M_TOT * D_MODEL];
__device__ float g_K[M_TOT * D_MODEL];
__device__ float g_V[M_TOT * D_MODEL];
__device__ float g_C[M_TOT * D_MODEL];

// bf16 hi/lo split buffers (X splits are reused for Q/K/Vt splits after projections)
__device__ __nv_bfloat16 g_XH0[M_TOT * D_MODEL];
__device__ __nv_bfloat16 g_XL0[M_TOT * D_MODEL];
__device__ __nv_bfloat16 g_XH1[M_TOT * D_MODEL];
__device__ __nv_bfloat16 g_XL1[M_TOT * D_MODEL];
__device__ __nv_bfloat16 g_XH2[M_TOT * D_MODEL];
__device__ __nv_bfloat16 g_XL2[M_TOT * D_MODEL];
__device__ __nv_bfloat16 g_CH [M_TOT * D_MODEL];
__device__ __nv_bfloat16 g_CL [M_TOT * D_MODEL];
__device__ __nv_bfloat16 g_WH0[D_MODEL * D_MODEL];
__device__ __nv_bfloat16 g_WL0[D_MODEL * D_MODEL];
__device__ __nv_bfloat16 g_WH1[D_MODEL * D_MODEL];
__device__ __nv_bfloat16 g_WL1[D_MODEL * D_MODEL];
__device__ __nv_bfloat16 g_WH2[D_MODEL * D_MODEL];
__device__ __nv_bfloat16 g_WL2[D_MODEL * D_MODEL];
__device__ __nv_bfloat16 g_WH3[D_MODEL * D_MODEL];
__device__ __nv_bfloat16 g_WL3[D_MODEL * D_MODEL];

// ====================== helpers (baseline PTX only: sm_80-class) ======================
__device__ __forceinline__ uint32_t smem_u32(const void* p) {
    uint32_t a;
    asm("{ .reg .u64 t; cvta.to.shared.u64 t, %1; cvt.u32.u64 %0, t; }" : "=r"(a) : "l"(p));
    return a;
}
__device__ __forceinline__ void ldsm4(uint32_t* r, uint32_t addr) {
    asm volatile("ldmatrix.sync.aligned.m8n8.x4.shared.b16 {%0,%1,%2,%3}, [%4];"
        : "=r"(r[0]), "=r"(r[1]), "=r"(r[2]), "=r"(r[3]) : "r"(addr));
}
__device__ __forceinline__ void mma_bf16(float* c, const uint32_t* a, const uint32_t* b) {
    asm volatile("mma.sync.aligned.m16n8k16.row.col.f32.bf16.bf16.f32 "
        "{%0,%1,%2,%3}, {%4,%5,%6,%7}, {%8,%9}, {%0,%1,%2,%3};"
        : "+f"(c[0]), "+f"(c[1]), "+f"(c[2]), "+f"(c[3])
        : "r"(a[0]), "r"(a[1]), "r"(a[2]), "r"(a[3]), "r"(b[0]), "r"(b[1]));
}
__device__ __forceinline__ uint32_t pack_bf16(float x, float y) {
    __nv_bfloat162 h = __floats2bfloat162_rn(x, y);
    return *(uint32_t*)&h;
}
#define CP_ASYNC16(s, g) asm volatile("cp.async.cg.shared.global [%0], [%1], 16;" :: "r"(s), "l"(g) : "memory")
#define CP_COMMIT()      asm volatile("cp.async.commit_group;" ::: "memory")
#define CP_WAIT1()       asm volatile("cp.async.wait_group 1;" ::: "memory")
#define CP_WAIT0()       asm volatile("cp.async.wait_group 0;" ::: "memory")

// =================================================================================
// convert: fp32 -> bf16 hi + bf16 lo residual (optional scale folded in)
// =================================================================================
__global__ void split_kernel(const float* __restrict__ x,
                             __nv_bfloat16* __restrict__ hi,
                             __nv_bfloat16* __restrict__ lo, int n, float scale)
{
    int idx = (blockIdx.x * blockDim.x + threadIdx.x) * 4;
    if (idx >= n) return;
    float4 v = *(const float4*)(x + idx);
    v.x *= scale; v.y *= scale; v.z *= scale; v.w *= scale;
    __nv_bfloat16 h0 = __float2bfloat16(v.x);
    __nv_bfloat16 h1 = __float2bfloat16(v.y);
    __nv_bfloat16 h2 = __float2bfloat16(v.z);
    __nv_bfloat16 h3 = __float2bfloat16(v.w);
    __nv_bfloat16 l0 = __float2bfloat16(v.x - __bfloat162float(h0));
    __nv_bfloat16 l1 = __float2bfloat16(v.y - __bfloat162float(h1));
    __nv_bfloat16 l2 = __float2bfloat16(v.z - __bfloat162float(h2));
    __nv_bfloat16 l3 = __float2bfloat16(v.w - __bfloat162float(h3));
    *(__nv_bfloat162*)(hi + idx)     = __nv_bfloat162(h0, h1);
    *(__nv_bfloat162*)(hi + idx + 2) = __nv_bfloat162(h2, h3);
    *(__nv_bfloat162*)(lo + idx)     = __nv_bfloat162(l0, l1);
    *(__nv_bfloat162*)(lo + idx + 2) = __nv_bfloat162(l2, l3);
}

// =================================================================================
// V transpose+split: V[b*S+s][h*64+d] fp32 -> Vt hi/lo [(b*16+h)*64+d][S]
// grid (S/32, 2, B*H), block 256; 32x32 tiles via smem.
// =================================================================================
__global__ void vtrans_split_kernel(const float* __restrict__ V,
                                    __nv_bfloat16* __restrict__ VTH,
                                    __nv_bfloat16* __restrict__ VTL)
{
    __shared__ float t[32][33];
    const int s0 = blockIdx.x * 32;
    const int d0 = blockIdx.y * 32;
    const int bh = blockIdx.z;
    const int b = bh >> 4, h = bh & 15;
    const int tid = threadIdx.x;
    const int cx = tid & 31, cy = tid >> 5;   // cy 0..7

#pragma unroll
    for (int i = 0; i < 4; i++) {
        int s = s0 + cy + i * 8;
        t[cy + i * 8][cx] = V[(size_t)(b * SEQ + s) * D_MODEL + h * 64 + d0 + cx];
    }
    __syncthreads();
#pragma unroll
    for (int i = 0; i < 4; i++) {
        int d = d0 + cy + i * 8;
        float v = t[cx][cy + i * 8];
        __nv_bfloat16 hh = __float2bfloat16(v);
        __nv_bfloat16 ll = __float2bfloat16(v - __bfloat162float(hh));
        size_t o = (size_t)(bh * 64 + d) * SEQ + s0 + cx;
        VTH[o] = hh; VTL[o] = ll;
    }
}

// =================================================================================
// mma.sync GEMM (unchanged from R3): C = (Ah+Al)(Wh+Wl)^T + bias
// =================================================================================
#define G_ROWPAD   40
#define G_TILE_B   (128 * G_ROWPAD * 2)
#define G_STAGE_B  (4 * G_TILE_B)
#define G_SMEM_TOT (2 * G_STAGE_B)

__global__ __launch_bounds__(256)
void gemm_mma_kernel(const __nv_bfloat16* __restrict__ Ah,
                     const __nv_bfloat16* __restrict__ Al,
                     const __nv_bfloat16* __restrict__ Wh,
                     const __nv_bfloat16* __restrict__ Wl,
                     const float* __restrict__ bias,
                     float* __restrict__ C)
{
    extern __shared__ __align__(128) char smem[];
    const uint32_t sb = smem_u32(smem);
    const int tid  = threadIdx.x;
    const int lane = tid & 31, wid = tid >> 5;
    const int warp_m = wid >> 2;
    const int warp_n = wid & 3;
    const int row0 = blockIdx.y * 128;
    const int col0 = blockIdx.x * 128;

    const __nv_bfloat16* srcs[4] = {
        Ah + (size_t)row0 * 1024, Al + (size_t)row0 * 1024,
        Wh + (size_t)col0 * 1024, Wl + (size_t)col0 * 1024 };

    const int ld_row = tid & 127;
    const int ld_c0  = (tid >> 7) * 2;

    float acc[4][4][4];
#pragma unroll
    for (int a = 0; a < 4; a++)
#pragma unroll
        for (int b = 0; b < 4; b++)
#pragma unroll
            for (int c = 0; c < 4; c++) acc[a][b][c] = 0.f;

    const int la   = lane & 7;
    const int lb8  = (lane >> 3) & 1;
    const int lb16 = lane >> 4;
    const uint32_t a_off = (uint32_t)((la + lb8 * 8) * (G_ROWPAD * 2) + lb16 * 16);
    const uint32_t b_off = (uint32_t)((la + lb16 * 8) * (G_ROWPAD * 2) + lb8 * 16);

    auto load_stage = [&](int buf, int k0) {
        const uint32_t sbase = sb + buf * G_STAGE_B + (uint32_t)ld_row * (G_ROWPAD * 2);
#pragma unroll
        for (int t = 0; t < 4; t++) {
            const __nv_bfloat16* g = srcs[t] + (size_t)ld_row * 1024 + k0;
            const uint32_t s = sbase + t * G_TILE_B;
#pragma unroll
            for (int u = 0; u < 2; u++) {
                const int c = ld_c0 + u;
                CP_ASYNC16(s + c * 16, (const void*)(g + c * 8));
            }
        }
    };

    auto compute_stage = [&](int buf) {
        const uint32_t s  = sb + buf * G_STAGE_B;
        const uint32_t aH = s + 0 * G_TILE_B + (uint32_t)(warp_m * 64) * (G_ROWPAD * 2);
        const uint32_t aL = s + 1 * G_TILE_B + (uint32_t)(warp_m * 64) * (G_ROWPAD * 2);
        const uint32_t bH = s + 2 * G_TILE_B + (uint32_t)(warp_n * 32) * (G_ROWPAD * 2);
        const uint32_t bL = s + 3 * G_TILE_B + (uint32_t)(warp_n * 32) * (G_ROWPAD * 2);
#pragma unroll
        for (int ks = 0; ks < 2; ks++) {
            uint32_t ah[4][4], al[4][4], bh[2][4], bl[2][4];
#pragma unroll
            for (int mt = 0; mt < 4; mt++) {
                ldsm4(ah[mt], aH + (uint32_t)(mt * 16) * (G_ROWPAD * 2) + ks * 32 + a_off);
                ldsm4(al[mt], aL + (uint32_t)(mt * 16) * (G_ROWPAD * 2) + ks * 32 + a_off);
            }
#pragma unroll
            for (int p = 0; p < 2; p++) {
                ldsm4(bh[p], bH + (uint32_t)(p * 16) * (G_ROWPAD * 2) + ks * 32 + b_off);
                ldsm4(bl[p], bL + (uint32_t)(p * 16) * (G_ROWPAD * 2) + ks * 32 + b_off);
            }
#pragma unroll
            for (int mt = 0; mt < 4; mt++)
#pragma unroll
                for (int nt = 0; nt < 4; nt++) {
                    float* c = acc[mt][nt];
                    const uint32_t* bhp = &bh[nt >> 1][(nt & 1) * 2];
                    const uint32_t* blp = &bl[nt >> 1][(nt & 1) * 2];
                    mma_bf16(c, ah[mt], bhp);
                    mma_bf16(c, ah[mt], blp);
                    mma_bf16(c, al[mt], bhp);
                }
        }
    };

    load_stage(0, 0);  CP_COMMIT();
    load_stage(1, 32); CP_COMMIT();

    for (int c = 0; c < 32; c++) {
        CP_WAIT1();
        __syncthreads();
        const int buf = c & 1;
        compute_stage(buf);
        __syncthreads();
        if (c + 2 < 32) load_stage(buf, (c + 2) * 32);
        CP_COMMIT();
    }

    const int r_base = row0 + warp_m * 64;
    const int c_base = col0 + warp_n * 32;
#pragma unroll
    for (int mt = 0; mt < 4; mt++) {
        const int r = r_base + mt * 16 + (lane >> 2);
#pragma unroll
        for (int nt = 0; nt < 4; nt++) {
            const int cc = c_base + nt * 8 + (lane & 3) * 2;
            const float b0 = __ldg(bias + cc), b1 = __ldg(bias + cc + 1);
            float2 o0, o1;
            o0.x = acc[mt][nt][0] + b0; o0.y = acc[mt][nt][1] + b1;
            o1.x = acc[mt][nt][2] + b0; o1.y = acc[mt][nt][3] + b1;
            *(float2*)(C + (size_t)r * 1024 + cc)       = o0;
            *(float2*)(C + (size_t)(r + 8) * 1024 + cc) = o1;
        }
    }
}

// =================================================================================
// Flash attention on mma.sync (bf16 hi/lo, 3-term). CTA: 128 q rows, 8 warps.
// KV tiles of 64, cp.async double-buffered. Q fragments resident in registers.
// smem stage: [Kh | Kl | Vth | Vtl], each 64 rows x 144B (72 bf16, conflict-free).
// =================================================================================
#define A_STRIDE_B 144
#define A_TILE_B   (64 * A_STRIDE_B)    // 9216
#define A_STAGE_B  (4 * A_TILE_B)       // 36864
#define A_SMEM_TOT (2 * A_STAGE_B)      // 73728

__global__ __launch_bounds__(256)
void attention_mma_kernel(const __nv_bfloat16* __restrict__ QH,
                          const __nv_bfloat16* __restrict__ QL,
                          const __nv_bfloat16* __restrict__ KH,
                          const __nv_bfloat16* __restrict__ KL,
                          const __nv_bfloat16* __restrict__ VTH,
                          const __nv_bfloat16* __restrict__ VTL,
                          float* __restrict__ O)
{
    extern __shared__ __align__(128) char smem[];
    const uint32_t sb = smem_u32(smem);
    const int tid  = threadIdx.x;
    const int lane = tid & 31, wid = tid >> 5;
    const int bh = blockIdx.y;
    const int b = bh >> 4, h = bh & 15;
    const int q0 = blockIdx.x * 128;

    const int la   = lane & 7;
    const int lb8  = (lane >> 3) & 1;
    const int lb16 = lane >> 4;
    const uint32_t a_off = (uint32_t)((la + lb8 * 8) * A_STRIDE_B + lb16 * 16);
    const uint32_t b_off = (uint32_t)((la + lb16 * 8) * A_STRIDE_B + lb8 * 16);

    // ---- stage Q (hi at sb+0, lo at sb+2*A_TILE_B) and move to registers ----
    {
        // 128 rows x 8 chunks = 1024 chunks each; 4 per thread
#pragma unroll
        for (int i = 0; i < 4; i++) {
            int c = tid + i * 256;
            int r = c >> 3, ch = c & 7;
            const size_t g = (size_t)(b * SEQ + q0 + r) * D_MODEL + h * 64 + ch * 8;
            CP_ASYNC16(sb + r * A_STRIDE_B + ch * 16, (const void*)(QH + g));
            CP_ASYNC16(sb + 2 * A_TILE_B + r * A_STRIDE_B + ch * 16, (const void*)(QL + g));
        }
        CP_COMMIT();
        CP_WAIT0();
        __syncthreads();
    }
    uint32_t qh[4][4], ql[4][4];
#pragma unroll
    for (int ks = 0; ks < 4; ks++) {
        ldsm4(qh[ks], sb + (uint32_t)(wid * 16) * A_STRIDE_B + ks * 32 + a_off);
        ldsm4(ql[ks], sb + 2 * A_TILE_B + (uint32_t)(wid * 16) * A_STRIDE_B + ks * 32 + a_off);
    }
    __syncthreads();   // Q reads done before KV loads overwrite

    // ---- KV stage loader ----
    const int lt = tid >> 6;       // tile 0..3
    const int lr = tid & 63;       // row 0..63
    auto load_stage = [&](int buf, int kv0) {
        const uint32_t s = sb + buf * A_STAGE_B + lt * A_TILE_B + (uint32_t)lr * A_STRIDE_B;
        const __nv_bfloat16* g;
        if (lt == 0)      g = KH  + (size_t)(b * SEQ + kv0 + lr) * D_MODEL + h * 64;
        else if (lt == 1) g = KL  + (size_t)(b * SEQ + kv0 + lr) * D_MODEL + h * 64;
        else if (lt == 2) g = VTH + (size_t)(bh * 64 + lr) * SEQ + kv0;
        else              g = VTL + (size_t)(bh * 64 + lr) * SEQ + kv0;
#pragma unroll
        for (int ch = 0; ch < 8; ch++)
            CP_ASYNC16(s + ch * 16, (const void*)(g + ch * 8));
    };

    load_stage(0, 0);  CP_COMMIT();
    load_stage(1, 64); CP_COMMIT();

    float o[8][4];
#pragma unroll
    for (int t = 0; t < 8; t++)
#pragma unroll
        for (int j = 0; j < 4; j++) o[t][j] = 0.f;
    float m_r[2] = {-1e30f, -1e30f};
    float l_r[2] = {0.f, 0.f};

    for (int it = 0; it < 32; it++) {
        CP_WAIT1();
        __syncthreads();
        const uint32_t st = sb + (it & 1) * A_STAGE_B;

        // ---- S = Q K^T (3-term) ----
        float s[8][4];
#pragma unroll
        for (int t = 0; t < 8; t++)
#pragma unroll
            for (int j = 0; j < 4; j++) s[t][j] = 0.f;
#pragma unroll
        for (int ks = 0; ks < 4; ks++) {
#pragma unroll
            for (int np = 0; np < 4; np++) {
                uint32_t kh4[4], kl4[4];
                const uint32_t base = (uint32_t)(np * 16) * A_STRIDE_B + ks * 32 + b_off;
                ldsm4(kh4, st + 0 * A_TILE_B + base);
                ldsm4(kl4, st + 1 * A_TILE_B + base);
                mma_bf16(s[2 * np],     qh[ks], kh4);
                mma_bf16(s[2 * np],     qh[ks], kl4);
                mma_bf16(s[2 * np],     ql[ks], kh4);
                mma_bf16(s[2 * np + 1], qh[ks], kh4 + 2);
                mma_bf16(s[2 * np + 1], qh[ks], kl4 + 2);
                mma_bf16(s[2 * np + 1], ql[ks], kh4 + 2);
            }
        }

        // ---- online softmax on fragments ----
#pragma unroll
        for (int r = 0; r < 2; r++) {
            float mx = s[0][2 * r];
#pragma unroll
            for (int t = 0; t < 8; t++) {
                mx = fmaxf(mx, s[t][2 * r]);
                mx = fmaxf(mx, s[t][2 * r + 1]);
            }
            mx = fmaxf(mx, __shfl_xor_sync(0xffffffffu, mx, 1));
            mx = fmaxf(mx, __shfl_xor_sync(0xffffffffu, mx, 2));
            float mn = fmaxf(m_r[r], mx);
            float al = __expf(m_r[r] - mn);
            m_r[r] = mn;
            float sum = 0.f;
#pragma unroll
            for (int t = 0; t < 8; t++) {
                float p0 = __expf(s[t][2 * r]     - mn);
                float p1 = __expf(s[t][2 * r + 1] - mn);
                s[t][2 * r] = p0; s[t][2 * r + 1] = p1;
                sum += p0 + p1;
            }
            sum += __shfl_xor_sync(0xffffffffu, sum, 1);
            sum += __shfl_xor_sync(0xffffffffu, sum, 2);
            l_r[r] = l_r[r] * al + sum;
#pragma unroll
            for (int t = 0; t < 8; t++) {
                o[t][2 * r] *= al; o[t][2 * r + 1] *= al;
            }
        }

        // ---- O += P V (3-term, P hi/lo built in registers) ----
#pragma unroll
        for (int ks = 0; ks < 4; ks++) {
            const int t0 = 2 * ks, t1 = 2 * ks + 1;
            float ph[8], pl[8];
            const float pv[8] = { s[t0][0], s[t0][1], s[t0][2], s[t0][3],
                                  s[t1][0], s[t1][1], s[t1][2], s[t1][3] };
#pragma unroll
            for (int j = 0; j < 8; j++) {
                float hf = __bfloat162float(__float2bfloat16(pv[j]));
                ph[j] = hf; pl[j] = pv[j] - hf;
            }
            uint32_t pa_h[4], pa_l[4];
#pragma unroll
            for (int j = 0; j < 4; j++) {
                pa_h[j] = pack_bf16(ph[2 * j], ph[2 * j + 1]);
                pa_l[j] = pack_bf16(pl[2 * j], pl[2 * j + 1]);
            }
#pragma unroll
            for (int np = 0; np < 4; np++) {
                uint32_t vh4[4], vl4[4];
                const uint32_t base = (uint32_t)(np * 16) * A_STRIDE_B + ks * 32 + b_off;
                ldsm4(vh4, st + 2 * A_TILE_B + base);
                ldsm4(vl4, st + 3 * A_TILE_B + base);
                mma_bf16(o[2 * np],     pa_h, vh4);
                mma_bf16(o[2 * np],     pa_h, vl4);
                mma_bf16(o[2 * np],     pa_l, vh4);
                mma_bf16(o[2 * np + 1], pa_h, vh4 + 2);
                mma_bf16(o[2 * np + 1], pa_h, vl4 + 2);
                mma_bf16(o[2 * np + 1], pa_l, vh4 + 2);
            }
        }

        __syncthreads();
        if (it + 2 < 32) load_stage(it & 1, (it + 2) * 64);
        CP_COMMIT();
    }

    // ---- epilogue ----
    const float inv0 = 1.f / l_r[0];
    const float inv1 = 1.f / l_r[1];
    const int row0 = q0 + wid * 16 + (lane >> 2);
#pragma unroll
    for (int t = 0; t < 8; t++) {
        const int col = h * 64 + t * 8 + (lane & 3) * 2;
        float2 v0, v1;
        v0.x = o[t][0] * inv0; v0.y = o[t][1] * inv0;
        v1.x = o[t][2] * inv1; v1.y = o[t][3] * inv1;
        *(float2*)(O + (size_t)(b * SEQ + row0) * D_MODEL + col)     = v0;
        *(float2*)(O + (size_t)(b * SEQ + row0 + 8) * D_MODEL + col) = v1;
    }
}

// =================================================================================
// launch
// =================================================================================
extern "C" void kernel_launch(void* const* d_in, const int* in_sizes, int n_in,
                              void* d_out, int out_size)
{
    const float* x_q = (const float*)d_in[0];
    const float* x_k = (const float*)d_in[1];
    const float* x_v = (const float*)d_in[2];
    const float* wq  = (const float*)d_in[3];
    const float* bq  = (const float*)d_in[4];
    const float* wk  = (const float*)d_in[5];
    const float* bk  = (const float*)d_in[6];
    const float* wv  = (const float*)d_in[7];
    const float* bv  = (const float*)d_in[8];
    const float* wo  = (const float*)d_in[9];
    const float* bo  = (const float*)d_in[10];
    float* out = (float*)d_out;

    float *gq, *gk, *gv, *gc;
    cudaGetSymbolAddress((void**)&gq, g_Q);
    cudaGetSymbolAddress((void**)&gk, g_K);
    cudaGetSymbolAddress((void**)&gv, g_V);
    cudaGetSymbolAddress((void**)&gc, g_C);

    __nv_bfloat16 *xh0, *xl0, *xh1, *xl1, *xh2, *xl2, *ch, *cl;
    __nv_bfloat16 *wh0, *wl0, *wh1, *wl1, *wh2, *wl2, *wh3, *wl3;
    cudaGetSymbolAddress((void**)&xh0, g_XH0); cudaGetSymbolAddress((void**)&xl0, g_XL0);
    cudaGetSymbolAddress((void**)&xh1, g_XH1); cudaGetSymbolAddress((void**)&xl1, g_XL1);
    cudaGetSymbolAddress((void**)&xh2, g_XH2); cudaGetSymbolAddress((void**)&xl2, g_XL2);
    cudaGetSymbolAddress((void**)&ch,  g_CH);  cudaGetSymbolAddress((void**)&cl,  g_CL);
    cudaGetSymbolAddress((void**)&wh0, g_WH0); cudaGetSymbolAddress((void**)&wl0, g_WL0);
    cudaGetSymbolAddress((void**)&wh1, g_WH1); cudaGetSymbolAddress((void**)&wl1, g_WL1);
    cudaGetSymbolAddress((void**)&wh2, g_WH2); cudaGetSymbolAddress((void**)&wl2, g_WL2);
    cudaGetSymbolAddress((void**)&wh3, g_WH3); cudaGetSymbolAddress((void**)&wl3, g_WL3);

    static int attr_set = 0;
    if (!attr_set) {
        cudaFuncSetAttribute(gemm_mma_kernel,
                             cudaFuncAttributeMaxDynamicSharedMemorySize, G_SMEM_TOT);
        cudaFuncSetAttribute(attention_mma_kernel,
                             cudaFuncAttributeMaxDynamicSharedMemorySize, A_SMEM_TOT);
        attr_set = 1;
    }

    const int NX = M_TOT * D_MODEL;
    const int NW = D_MODEL * D_MODEL;
    dim3 cb(256);
    dim3 cgx((NX / 4 + 255) / 256);
    dim3 cgw((NW / 4 + 255) / 256);

    // input splits
    split_kernel<<<cgx, cb>>>(x_q, xh0, xl0, NX, 1.f);
    split_kernel<<<cgx, cb>>>(x_k, xh1, xl1, NX, 1.f);
    split_kernel<<<cgx, cb>>>(x_v, xh2, xl2, NX, 1.f);
    split_kernel<<<cgw, cb>>>(wq, wh0, wl0, NW, 1.f);
    split_kernel<<<cgw, cb>>>(wk, wh1, wl1, NW, 1.f);
    split_kernel<<<cgw, cb>>>(wv, wh2, wl2, NW, 1.f);
    split_kernel<<<cgw, cb>>>(wo, wh3, wl3, NW, 1.f);

    // projections (tensor cores)
    dim3 ggrid(D_MODEL / 128, M_TOT / 128);
    gemm_mma_kernel<<<ggrid, 256, G_SMEM_TOT>>>(xh0, xl0, wh0, wl0, bq, gq);
    gemm_mma_kernel<<<ggrid, 256, G_SMEM_TOT>>>(xh1, xl1, wh1, wl1, bk, gk);
    gemm_mma_kernel<<<ggrid, 256, G_SMEM_TOT>>>(xh2, xl2, wh2, wl2, bv, gv);

    // re-split projections for attention (reuse X split buffers)
    split_kernel<<<cgx, cb>>>(gq, xh0, xl0, NX, 0.125f);   // Q scaled by 1/sqrt(d_k)
    split_kernel<<<cgx, cb>>>(gk, xh1, xl1, NX, 1.f);      // K
    {
        dim3 vg(SEQ / 32, 2, BATCH * NHEAD);
        vtrans_split_kernel<<<vg, 256>>>(gv, xh2, xl2);    // V^T hi/lo
    }

    // attention (tensor cores)
    dim3 agrid(SEQ / 128, BATCH * NHEAD);
    attention_mma_kernel<<<agrid, 256, A_SMEM_TOT>>>(xh0, xl0, xh1, xl1, xh2, xl2, gc);

    // output projection
    split_kernel<<<cgx, cb>>>(gc, ch, cl, NX, 1.f);
    gemm_mma_kernel<<<ggrid, 256, G_SMEM_TOT>>>(ch, cl, wh3, wl3, bo, out);
}

// round 5
// speedup vs baseline: 2.6256x; 1.0688x over previous
#include <cuda_runtime.h>
#include <cuda_bf16.h>
#include <math.h>
#include <cstdint>

#define D_MODEL 1024
#define NHEAD   16
#define D_K     64
#define BATCH   4
#define SEQ     2048
#define M_TOT   (BATCH * SEQ)   // 8192

typedef __nv_bfloat16 bf16;

// ---------------- scratch (device globals: allocation-free rule) ----------------
__device__ bf16 g_XH0[M_TOT * D_MODEL];
__device__ bf16 g_XL0[M_TOT * D_MODEL];
__device__ bf16 g_XH1[M_TOT * D_MODEL];
__device__ bf16 g_XL1[M_TOT * D_MODEL];
__device__ bf16 g_XH2[M_TOT * D_MODEL];
__device__ bf16 g_XL2[M_TOT * D_MODEL];
__device__ bf16 g_QH [M_TOT * D_MODEL];
__device__ bf16 g_QL [M_TOT * D_MODEL];
__device__ bf16 g_KH [M_TOT * D_MODEL];
__device__ bf16 g_KL [M_TOT * D_MODEL];
__device__ bf16 g_VH [M_TOT * D_MODEL];
__device__ bf16 g_VL [M_TOT * D_MODEL];
__device__ bf16 g_VTH[M_TOT * D_MODEL];
__device__ bf16 g_VTL[M_TOT * D_MODEL];
__device__ bf16 g_CH [M_TOT * D_MODEL];
__device__ bf16 g_CL [M_TOT * D_MODEL];
__device__ bf16 g_WH0[D_MODEL * D_MODEL];
__device__ bf16 g_WL0[D_MODEL * D_MODEL];
__device__ bf16 g_WH1[D_MODEL * D_MODEL];
__device__ bf16 g_WL1[D_MODEL * D_MODEL];
__device__ bf16 g_WH2[D_MODEL * D_MODEL];
__device__ bf16 g_WL2[D_MODEL * D_MODEL];
__device__ bf16 g_WH3[D_MODEL * D_MODEL];
__device__ bf16 g_WL3[D_MODEL * D_MODEL];

// ====================== helpers (baseline PTX only: sm_80-class) ======================
__device__ __forceinline__ uint32_t smem_u32(const void* p) {
    uint32_t a;
    asm("{ .reg .u64 t; cvta.to.shared.u64 t, %1; cvt.u32.u64 %0, t; }" : "=r"(a) : "l"(p));
    return a;
}
__device__ __forceinline__ void ldsm4(uint32_t* r, uint32_t addr) {
    asm volatile("ldmatrix.sync.aligned.m8n8.x4.shared.b16 {%0,%1,%2,%3}, [%4];"
        : "=r"(r[0]), "=r"(r[1]), "=r"(r[2]), "=r"(r[3]) : "r"(addr));
}
__device__ __forceinline__ void mma_bf16(float* c, const uint32_t* a, const uint32_t* b) {
    asm volatile("mma.sync.aligned.m16n8k16.row.col.f32.bf16.bf16.f32 "
        "{%0,%1,%2,%3}, {%4,%5,%6,%7}, {%8,%9}, {%0,%1,%2,%3};"
        : "+f"(c[0]), "+f"(c[1]), "+f"(c[2]), "+f"(c[3])
        : "r"(a[0]), "r"(a[1]), "r"(a[2]), "r"(a[3]), "r"(b[0]), "r"(b[1]));
}
__device__ __forceinline__ uint32_t pack_bf16(float x, float y) {
    __nv_bfloat162 h = __floats2bfloat162_rn(x, y);
    return *(uint32_t*)&h;
}
__device__ __forceinline__ void store_hilo(bf16* H, bf16* L, size_t off, float x, float y) {
    bf16 hx = __float2bfloat16(x), hy = __float2bfloat16(y);
    bf16 lx = __float2bfloat16(x - __bfloat162float(hx));
    bf16 ly = __float2bfloat16(y - __bfloat162float(hy));
    *(__nv_bfloat162*)(H + off) = __nv_bfloat162(hx, hy);
    *(__nv_bfloat162*)(L + off) = __nv_bfloat162(lx, ly);
}
#define CP_ASYNC16(s, g) asm volatile("cp.async.cg.shared.global [%0], [%1], 16;" :: "r"(s), "l"(g) : "memory")
#define CP_COMMIT()      asm volatile("cp.async.commit_group;" ::: "memory")
#define CP_WAIT1()       asm volatile("cp.async.wait_group 1;" ::: "memory")
#define CP_WAIT0()       asm volatile("cp.async.wait_group 0;" ::: "memory")

// =================================================================================
// split: fp32 -> bf16 hi + lo residual
// =================================================================================
__global__ void split_kernel(const float* __restrict__ x,
                             bf16* __restrict__ hi, bf16* __restrict__ lo, int n)
{
    int idx = (blockIdx.x * blockDim.x + threadIdx.x) * 4;
    if (idx >= n) return;
    float4 v = *(const float4*)(x + idx);
    bf16 h0 = __float2bfloat16(v.x), h1 = __float2bfloat16(v.y);
    bf16 h2 = __float2bfloat16(v.z), h3 = __float2bfloat16(v.w);
    bf16 l0 = __float2bfloat16(v.x - __bfloat162float(h0));
    bf16 l1 = __float2bfloat16(v.y - __bfloat162float(h1));
    bf16 l2 = __float2bfloat16(v.z - __bfloat162float(h2));
    bf16 l3 = __float2bfloat16(v.w - __bfloat162float(h3));
    *(__nv_bfloat162*)(hi + idx)     = __nv_bfloat162(h0, h1);
    *(__nv_bfloat162*)(hi + idx + 2) = __nv_bfloat162(h2, h3);
    *(__nv_bfloat162*)(lo + idx)     = __nv_bfloat162(l0, l1);
    *(__nv_bfloat162*)(lo + idx + 2) = __nv_bfloat162(l2, l3);
}

// =================================================================================
// V transpose (bf16 pair): VH/VL [b*S+s][h*64+d] -> VTH/VTL [(b*16+h)*64+d][S]
// =================================================================================
__global__ void vtrans_kernel(const bf16* __restrict__ VH, const bf16* __restrict__ VL,
                              bf16* __restrict__ VTH, bf16* __restrict__ VTL)
{
    __shared__ bf16 th[32][33], tl[32][33];
    const int s0 = blockIdx.x * 32;
    const int d0 = blockIdx.y * 32;
    const int bh = blockIdx.z;
    const int b = bh >> 4, h = bh & 15;
    const int tid = threadIdx.x;
    const int cx = tid & 31, cy = tid >> 5;

#pragma unroll
    for (int i = 0; i < 4; i++) {
        int s = s0 + cy + i * 8;
        size_t g = (size_t)(b * SEQ + s) * D_MODEL + h * 64 + d0 + cx;
        th[cy + i * 8][cx] = VH[g];
        tl[cy + i * 8][cx] = VL[g];
    }
    __syncthreads();
#pragma unroll
    for (int i = 0; i < 4; i++) {
        int d = d0 + cy + i * 8;
        size_t o = (size_t)(bh * 64 + d) * SEQ + s0 + cx;
        VTH[o] = th[cx][cy + i * 8];
        VTL[o] = tl[cx][cy + i * 8];
    }
}

// =================================================================================
// 16-warp mma.sync GEMM core: 128x128 CTA tile, BK=32, 3-term hi/lo, 3-stage ring.
// =================================================================================
#define G_ROWB     80                    // bytes per smem row (32 bf16 + 8 pad)
#define G_TILE_B   (128 * G_ROWB)        // 10240
#define G_STAGE_B  (4 * G_TILE_B)        // 40960 (Ah|Al|Wh|Wl)
#define G_SMEM_TOT (3 * G_STAGE_B)       // 122880

__device__ __forceinline__ void gemm16_mainloop(
    uint32_t sb, int tid, int lane, int wid,
    const bf16* __restrict__ Ah, const bf16* __restrict__ Al,
    const bf16* __restrict__ Wh, const bf16* __restrict__ Wl,
    int row0, int col0, float acc[2][4][4])
{
    const int warp_m = wid >> 2, warp_n = wid & 3;
    const int la = lane & 7, lb8 = (lane >> 3) & 1, lb16 = lane >> 4;
    const uint32_t a_off = (uint32_t)((la + lb8 * 8) * G_ROWB + lb16 * 16);
    const uint32_t b_off = (uint32_t)((la + lb16 * 8) * G_ROWB + lb8 * 16);

    const bf16* srcs[4] = { Ah + (size_t)row0 * 1024, Al + (size_t)row0 * 1024,
                            Wh + (size_t)col0 * 1024, Wl + (size_t)col0 * 1024 };
    const int lt = tid >> 7;     // tile 0..3
    const int lr = tid & 127;    // row 0..127

    auto load_stage = [&](int st, int k0) {
        const uint32_t s = sb + st * G_STAGE_B + lt * G_TILE_B + (uint32_t)lr * G_ROWB;
        const bf16* g = srcs[lt] + (size_t)lr * 1024 + k0;
#pragma unroll
        for (int ch = 0; ch < 4; ch++)
            CP_ASYNC16(s + ch * 16, (const void*)(g + ch * 8));
    };

    auto compute_stage = [&](int st) {
        const uint32_t s  = sb + st * G_STAGE_B;
        const uint32_t aH = s + 0 * G_TILE_B + (uint32_t)(warp_m * 32) * G_ROWB;
        const uint32_t aL = s + 1 * G_TILE_B + (uint32_t)(warp_m * 32) * G_ROWB;
        const uint32_t bH = s + 2 * G_TILE_B + (uint32_t)(warp_n * 32) * G_ROWB;
        const uint32_t bL = s + 3 * G_TILE_B + (uint32_t)(warp_n * 32) * G_ROWB;
#pragma unroll
        for (int ks = 0; ks < 2; ks++) {
            uint32_t ah[2][4], al[2][4], bh[2][4], bl[2][4];
#pragma unroll
            for (int mt = 0; mt < 2; mt++) {
                ldsm4(ah[mt], aH + (uint32_t)(mt * 16) * G_ROWB + ks * 32 + a_off);
                ldsm4(al[mt], aL + (uint32_t)(mt * 16) * G_ROWB + ks * 32 + a_off);
            }
#pragma unroll
            for (int p = 0; p < 2; p++) {
                ldsm4(bh[p], bH + (uint32_t)(p * 16) * G_ROWB + ks * 32 + b_off);
                ldsm4(bl[p], bL + (uint32_t)(p * 16) * G_ROWB + ks * 32 + b_off);
            }
#pragma unroll
            for (int mt = 0; mt < 2; mt++)
#pragma unroll
                for (int nt = 0; nt < 4; nt++) {
                    float* c = acc[mt][nt];
                    const uint32_t* bhp = &bh[nt >> 1][(nt & 1) * 2];
                    const uint32_t* blp = &bl[nt >> 1][(nt & 1) * 2];
                    mma_bf16(c, ah[mt], bhp);
                    mma_bf16(c, ah[mt], blp);
                    mma_bf16(c, al[mt], bhp);
                }
        }
    };

    load_stage(0, 0);  CP_COMMIT();
    load_stage(1, 32); CP_COMMIT();
    for (int c = 0; c < 32; c++) {
        CP_WAIT1();
        __syncthreads();
        compute_stage(c % 3);
        if (c + 2 < 32) load_stage((c + 2) % 3, (c + 2) * 32);
        CP_COMMIT();
    }
}

// ---- fused 3-projection kernel: epilogue -> bf16 hi/lo (scale folded) ----
struct ProjOne {
    const bf16 *Ah, *Al, *Wh, *Wl;
    const float* bias;
    bf16 *Oh, *Ol;
    float scale;
};
struct Proj3Args { ProjOne p[3]; };

__global__ __launch_bounds__(512)
void proj3_kernel(Proj3Args args)
{
    extern __shared__ __align__(128) char smem[];
    const ProjOne P = args.p[blockIdx.z];
    const uint32_t sb = smem_u32(smem);
    const int tid = threadIdx.x, lane = tid & 31, wid = tid >> 5;
    const int row0 = blockIdx.y * 128, col0 = blockIdx.x * 128;

    float acc[2][4][4];
#pragma unroll
    for (int a = 0; a < 2; a++)
#pragma unroll
        for (int b = 0; b < 4; b++)
#pragma unroll
            for (int c = 0; c < 4; c++) acc[a][b][c] = 0.f;

    gemm16_mainloop(sb, tid, lane, wid, P.Ah, P.Al, P.Wh, P.Wl, row0, col0, acc);

    const int warp_m = wid >> 2, warp_n = wid & 3;
    const int r_base = row0 + warp_m * 32, c_base = col0 + warp_n * 32;
#pragma unroll
    for (int mt = 0; mt < 2; mt++) {
        const int r = r_base + mt * 16 + (lane >> 2);
#pragma unroll
        for (int nt = 0; nt < 4; nt++) {
            const int cc = c_base + nt * 8 + (lane & 3) * 2;
            const float b0 = __ldg(P.bias + cc), b1 = __ldg(P.bias + cc + 1);
            store_hilo(P.Oh, P.Ol, (size_t)r * 1024 + cc,
                       (acc[mt][nt][0] + b0) * P.scale, (acc[mt][nt][1] + b1) * P.scale);
            store_hilo(P.Oh, P.Ol, (size_t)(r + 8) * 1024 + cc,
                       (acc[mt][nt][2] + b0) * P.scale, (acc[mt][nt][3] + b1) * P.scale);
        }
    }
}

// ---- output-projection kernel: epilogue -> fp32 + bias ----
__global__ __launch_bounds__(512)
void gemmF_kernel(const bf16* __restrict__ Ah, const bf16* __restrict__ Al,
                  const bf16* __restrict__ Wh, const bf16* __restrict__ Wl,
                  const float* __restrict__ bias, float* __restrict__ C)
{
    extern __shared__ __align__(128) char smem[];
    const uint32_t sb = smem_u32(smem);
    const int tid = threadIdx.x, lane = tid & 31, wid = tid >> 5;
    const int row0 = blockIdx.y * 128, col0 = blockIdx.x * 128;

    float acc[2][4][4];
#pragma unroll
    for (int a = 0; a < 2; a++)
#pragma unroll
        for (int b = 0; b < 4; b++)
#pragma unroll
            for (int c = 0; c < 4; c++) acc[a][b][c] = 0.f;

    gemm16_mainloop(sb, tid, lane, wid, Ah, Al, Wh, Wl, row0, col0, acc);

    const int warp_m = wid >> 2, warp_n = wid & 3;
    const int r_base = row0 + warp_m * 32, c_base = col0 + warp_n * 32;
#pragma unroll
    for (int mt = 0; mt < 2; mt++) {
        const int r = r_base + mt * 16 + (lane >> 2);
#pragma unroll
        for (int nt = 0; nt < 4; nt++) {
            const int cc = c_base + nt * 8 + (lane & 3) * 2;
            const float b0 = __ldg(bias + cc), b1 = __ldg(bias + cc + 1);
            float2 o0, o1;
            o0.x = acc[mt][nt][0] + b0; o0.y = acc[mt][nt][1] + b1;
            o1.x = acc[mt][nt][2] + b0; o1.y = acc[mt][nt][3] + b1;
            *(float2*)(C + (size_t)r * 1024 + cc)       = o0;
            *(float2*)(C + (size_t)(r + 8) * 1024 + cc) = o1;
        }
    }
}

// =================================================================================
// Flash attention, 16 warps, 256 q-rows/CTA, 3-stage KV ring, hi/lo 3-term.
// Output: CH/CL bf16 hi/lo (context, pre-out-projection).
// =================================================================================
#define A_STRIDE_B 144
#define A_TILE_B   (64 * A_STRIDE_B)    // 9216
#define A_STAGE_B  (4 * A_TILE_B)       // 36864 (Kh|Kl|Vth|Vtl)
#define A_SMEM_TOT (3 * A_STAGE_B)      // 110592

__global__ __launch_bounds__(512)
void attention_mma_kernel(const bf16* __restrict__ QH, const bf16* __restrict__ QL,
                          const bf16* __restrict__ KH, const bf16* __restrict__ KL,
                          const bf16* __restrict__ VTH, const bf16* __restrict__ VTL,
                          bf16* __restrict__ CH, bf16* __restrict__ CL)
{
    extern __shared__ __align__(128) char smem[];
    const uint32_t sb = smem_u32(smem);
    const int tid  = threadIdx.x;
    const int lane = tid & 31, wid = tid >> 5;   // wid 0..15
    const int bh = blockIdx.y;
    const int b = bh >> 4, h = bh & 15;
    const int q0 = blockIdx.x * 256;

    const int la   = lane & 7;
    const int lb8  = (lane >> 3) & 1;
    const int lb16 = lane >> 4;
    const uint32_t a_off = (uint32_t)((la + lb8 * 8) * A_STRIDE_B + lb16 * 16);
    const uint32_t b_off = (uint32_t)((la + lb16 * 8) * A_STRIDE_B + lb8 * 16);

    // ---- stage Q (hi at sb, lo at sb+4*A_TILE_B) and move to registers ----
    {
#pragma unroll
        for (int i = 0; i < 4; i++) {
            int c = tid + i * 512;           // 0..2047
            int r = c >> 3, ch = c & 7;
            const size_t g = (size_t)(b * SEQ + q0 + r) * D_MODEL + h * 64 + ch * 8;
            CP_ASYNC16(sb + r * A_STRIDE_B + ch * 16, (const void*)(QH + g));
            CP_ASYNC16(sb + 4 * A_TILE_B + r * A_STRIDE_B + ch * 16, (const void*)(QL + g));
        }
        CP_COMMIT();
        CP_WAIT0();
        __syncthreads();
    }
    uint32_t qh[4][4], ql[4][4];
#pragma unroll
    for (int ks = 0; ks < 4; ks++) {
        ldsm4(qh[ks], sb + (uint32_t)(wid * 16) * A_STRIDE_B + ks * 32 + a_off);
        ldsm4(ql[ks], sb + 4 * A_TILE_B + (uint32_t)(wid * 16) * A_STRIDE_B + ks * 32 + a_off);
    }
    __syncthreads();   // all Q frags read before KV loads overwrite

    // ---- KV loader: tile = tid>>7, row = (tid&127)>>1, half row per thread ----
    const int lt  = tid >> 7;
    const int lr2 = (tid & 127) >> 1;
    const int hf  = tid & 1;
    auto load_stage = [&](int st, int kv0) {
        const uint32_t s = sb + st * A_STAGE_B + lt * A_TILE_B
                         + (uint32_t)lr2 * A_STRIDE_B + hf * 64;
        const bf16* g;
        if (lt == 0)      g = KH  + (size_t)(b * SEQ + kv0 + lr2) * D_MODEL + h * 64 + hf * 32;
        else if (lt == 1) g = KL  + (size_t)(b * SEQ + kv0 + lr2) * D_MODEL + h * 64 + hf * 32;
        else if (lt == 2) g = VTH + (size_t)(bh * 64 + lr2) * SEQ + kv0 + hf * 32;
        else              g = VTL + (size_t)(bh * 64 + lr2) * SEQ + kv0 + hf * 32;
#pragma unroll
        for (int ch = 0; ch < 4; ch++)
            CP_ASYNC16(s + ch * 16, (const void*)(g + ch * 8));
    };

    load_stage(0, 0);  CP_COMMIT();
    load_stage(1, 64); CP_COMMIT();

    float o[8][4];
#pragma unroll
    for (int t = 0; t < 8; t++)
#pragma unroll
        for (int j = 0; j < 4; j++) o[t][j] = 0.f;
    float m_r[2] = {-1e30f, -1e30f};
    float l_r[2] = {0.f, 0.f};

    for (int it = 0; it < 32; it++) {
        CP_WAIT1();
        __syncthreads();
        const uint32_t st = sb + (it % 3) * A_STAGE_B;

        // ---- S = Q K^T (3-term) ----
        float s[8][4];
#pragma unroll
        for (int t = 0; t < 8; t++)
#pragma unroll
            for (int j = 0; j < 4; j++) s[t][j] = 0.f;
#pragma unroll
        for (int ks = 0; ks < 4; ks++) {
#pragma unroll
            for (int np = 0; np < 4; np++) {
                uint32_t kh4[4], kl4[4];
                const uint32_t base = (uint32_t)(np * 16) * A_STRIDE_B + ks * 32 + b_off;
                ldsm4(kh4, st + 0 * A_TILE_B + base);
                ldsm4(kl4, st + 1 * A_TILE_B + base);
                mma_bf16(s[2 * np],     qh[ks], kh4);
                mma_bf16(s[2 * np],     qh[ks], kl4);
                mma_bf16(s[2 * np],     ql[ks], kh4);
                mma_bf16(s[2 * np + 1], qh[ks], kh4 + 2);
                mma_bf16(s[2 * np + 1], qh[ks], kl4 + 2);
                mma_bf16(s[2 * np + 1], ql[ks], kh4 + 2);
            }
        }

        // ---- online softmax ----
#pragma unroll
        for (int r = 0; r < 2; r++) {
            float mx = s[0][2 * r];
#pragma unroll
            for (int t = 0; t < 8; t++) {
                mx = fmaxf(mx, s[t][2 * r]);
                mx = fmaxf(mx, s[t][2 * r + 1]);
            }
            mx = fmaxf(mx, __shfl_xor_sync(0xffffffffu, mx, 1));
            mx = fmaxf(mx, __shfl_xor_sync(0xffffffffu, mx, 2));
            float mn = fmaxf(m_r[r], mx);
            float al = __expf(m_r[r] - mn);
            m_r[r] = mn;
            float sum = 0.f;
#pragma unroll
            for (int t = 0; t < 8; t++) {
                float p0 = __expf(s[t][2 * r]     - mn);
                float p1 = __expf(s[t][2 * r + 1] - mn);
                s[t][2 * r] = p0; s[t][2 * r + 1] = p1;
                sum += p0 + p1;
            }
            sum += __shfl_xor_sync(0xffffffffu, sum, 1);
            sum += __shfl_xor_sync(0xffffffffu, sum, 2);
            l_r[r] = l_r[r] * al + sum;
#pragma unroll
            for (int t = 0; t < 8; t++) {
                o[t][2 * r] *= al; o[t][2 * r + 1] *= al;
            }
        }

        // ---- O += P V (3-term, P hi/lo in registers) ----
#pragma unroll
        for (int ks = 0; ks < 4; ks++) {
            const int t0 = 2 * ks, t1 = 2 * ks + 1;
            float ph[8], pl[8];
            const float pv[8] = { s[t0][0], s[t0][1], s[t0][2], s[t0][3],
                                  s[t1][0], s[t1][1], s[t1][2], s[t1][3] };
#pragma unroll
            for (int j = 0; j < 8; j++) {
                float hf2 = __bfloat162float(__float2bfloat16(pv[j]));
                ph[j] = hf2; pl[j] = pv[j] - hf2;
            }
            uint32_t pa_h[4], pa_l[4];
#pragma unroll
            for (int j = 0; j < 4; j++) {
                pa_h[j] = pack_bf16(ph[2 * j], ph[2 * j + 1]);
                pa_l[j] = pack_bf16(pl[2 * j], pl[2 * j + 1]);
            }
#pragma unroll
            for (int np = 0; np < 4; np++) {
                uint32_t vh4[4], vl4[4];
                const uint32_t base = (uint32_t)(np * 16) * A_STRIDE_B + ks * 32 + b_off;
                ldsm4(vh4, st + 2 * A_TILE_B + base);
                ldsm4(vl4, st + 3 * A_TILE_B + base);
                mma_bf16(o[2 * np],     pa_h, vh4);
                mma_bf16(o[2 * np],     pa_h, vl4);
                mma_bf16(o[2 * np],     pa_l, vh4);
                mma_bf16(o[2 * np + 1], pa_h, vh4 + 2);
                mma_bf16(o[2 * np + 1], pa_h, vl4 + 2);
                mma_bf16(o[2 * np + 1], pa_l, vh4 + 2);
            }
        }

        if (it + 2 < 32) load_stage((it + 2) % 3, (it + 2) * 64);
        CP_COMMIT();
    }

    // ---- epilogue: write context hi/lo ----
    const float inv0 = 1.f / l_r[0];
    const float inv1 = 1.f / l_r[1];
    const int row0 = q0 + wid * 16 + (lane >> 2);
#pragma unroll
    for (int t = 0; t < 8; t++) {
        const int col = h * 64 + t * 8 + (lane & 3) * 2;
        store_hilo(CH, CL, (size_t)(b * SEQ + row0) * D_MODEL + col,
                   o[t][0] * inv0, o[t][1] * inv0);
        store_hilo(CH, CL, (size_t)(b * SEQ + row0 + 8) * D_MODEL + col,
                   o[t][2] * inv1, o[t][3] * inv1);
    }
}

// =================================================================================
// launch
// =================================================================================
extern "C" void kernel_launch(void* const* d_in, const int* in_sizes, int n_in,
                              void* d_out, int out_size)
{
    const float* x_q = (const float*)d_in[0];
    const float* x_k = (const float*)d_in[1];
    const float* x_v = (const float*)d_in[2];
    const float* wq  = (const float*)d_in[3];
    const float* bq  = (const float*)d_in[4];
    const float* wk  = (const float*)d_in[5];
    const float* bk  = (const float*)d_in[6];
    const float* wv  = (const float*)d_in[7];
    const float* bv  = (const float*)d_in[8];
    const float* wo  = (const float*)d_in[9];
    const float* bo  = (const float*)d_in[10];
    float* out = (float*)d_out;

    bf16 *xh0, *xl0, *xh1, *xl1, *xh2, *xl2;
    bf16 *qh, *ql, *kh, *kl, *vh, *vl, *vth, *vtl, *ch, *cl;
    bf16 *wh0, *wl0, *wh1, *wl1, *wh2, *wl2, *wh3, *wl3;
    cudaGetSymbolAddress((void**)&xh0, g_XH0); cudaGetSymbolAddress((void**)&xl0, g_XL0);
    cudaGetSymbolAddress((void**)&xh1, g_XH1); cudaGetSymbolAddress((void**)&xl1, g_XL1);
    cudaGetSymbolAddress((void**)&xh2, g_XH2); cudaGetSymbolAddress((void**)&xl2, g_XL2);
    cudaGetSymbolAddress((void**)&qh,  g_QH);  cudaGetSymbolAddress((void**)&ql,  g_QL);
    cudaGetSymbolAddress((void**)&kh,  g_KH);  cudaGetSymbolAddress((void**)&kl,  g_KL);
    cudaGetSymbolAddress((void**)&vh,  g_VH);  cudaGetSymbolAddress((void**)&vl,  g_VL);
    cudaGetSymbolAddress((void**)&vth, g_VTH); cudaGetSymbolAddress((void**)&vtl, g_VTL);
    cudaGetSymbolAddress((void**)&ch,  g_CH);  cudaGetSymbolAddress((void**)&cl,  g_CL);
    cudaGetSymbolAddress((void**)&wh0, g_WH0); cudaGetSymbolAddress((void**)&wl0, g_WL0);
    cudaGetSymbolAddress((void**)&wh1, g_WH1); cudaGetSymbolAddress((void**)&wl1, g_WL1);
    cudaGetSymbolAddress((void**)&wh2, g_WH2); cudaGetSymbolAddress((void**)&wl2, g_WL2);
    cudaGetSymbolAddress((void**)&wh3, g_WH3); cudaGetSymbolAddress((void**)&wl3, g_WL3);

    static int attr_set = 0;
    if (!attr_set) {
        cudaFuncSetAttribute(proj3_kernel,
                             cudaFuncAttributeMaxDynamicSharedMemorySize, G_SMEM_TOT);
        cudaFuncSetAttribute(gemmF_kernel,
                             cudaFuncAttributeMaxDynamicSharedMemorySize, G_SMEM_TOT);
        cudaFuncSetAttribute(attention_mma_kernel,
                             cudaFuncAttributeMaxDynamicSharedMemorySize, A_SMEM_TOT);
        attr_set = 1;
    }

    const int NX = M_TOT * D_MODEL;
    const int NW = D_MODEL * D_MODEL;
    dim3 cb(256);
    dim3 cgx((NX / 4 + 255) / 256);
    dim3 cgw((NW / 4 + 255) / 256);

    // input + weight splits
    split_kernel<<<cgx, cb>>>(x_q, xh0, xl0, NX);
    split_kernel<<<cgx, cb>>>(x_k, xh1, xl1, NX);
    split_kernel<<<cgx, cb>>>(x_v, xh2, xl2, NX);
    split_kernel<<<cgw, cb>>>(wq, wh0, wl0, NW);
    split_kernel<<<cgw, cb>>>(wk, wh1, wl1, NW);
    split_kernel<<<cgw, cb>>>(wv, wh2, wl2, NW);
    split_kernel<<<cgw, cb>>>(wo, wh3, wl3, NW);

    // fused QKV projections -> bf16 hi/lo (Q pre-scaled by 1/sqrt(d_k))
    Proj3Args pa;
    pa.p[0] = { xh0, xl0, wh0, wl0, bq, qh, ql, 0.125f };
    pa.p[1] = { xh1, xl1, wh1, wl1, bk, kh, kl, 1.0f };
    pa.p[2] = { xh2, xl2, wh2, wl2, bv, vh, vl, 1.0f };
    proj3_kernel<<<dim3(8, 64, 3), 512, G_SMEM_TOT>>>(pa);

    // V transpose (bf16 pair)
    vtrans_kernel<<<dim3(SEQ / 32, 2, BATCH * NHEAD), 256>>>(vh, vl, vth, vtl);

    // attention -> context hi/lo
    attention_mma_kernel<<<dim3(SEQ / 256, BATCH * NHEAD), 512, A_SMEM_TOT>>>(
        qh, ql, kh, kl, vth, vtl, ch, cl);

    // output projection -> fp32 out
    gemmF_kernel<<<dim3(8, 64), 512, G_SMEM_TOT>>>(ch, cl, wh3, wl3, bo, out);
}

// round 6
// speedup vs baseline: 3.6343x; 1.3842x over previous
#include <cuda_runtime.h>
#include <cuda_fp16.h>
#include <math.h>
#include <cstdint>

#define D_MODEL 1024
#define NHEAD   16
#define D_K     64
#define BATCH   4
#define SEQ     2048
#define M_TOT   (BATCH * SEQ)   // 8192

// ---------------- scratch (device globals: allocation-free rule) ----------------
__device__ __half g_XH0[M_TOT * D_MODEL];
__device__ __half g_XL0[M_TOT * D_MODEL];
__device__ __half g_XH1[M_TOT * D_MODEL];
__device__ __half g_XL1[M_TOT * D_MODEL];
__device__ __half g_XH2[M_TOT * D_MODEL];
__device__ __half g_XL2[M_TOT * D_MODEL];
__device__ __half g_QH [M_TOT * D_MODEL];
__device__ __half g_QL [M_TOT * D_MODEL];
__device__ __half g_K16[M_TOT * D_MODEL];
__device__ __half g_V16[M_TOT * D_MODEL];
__device__ __half g_VT [M_TOT * D_MODEL];
__device__ __half g_CH [M_TOT * D_MODEL];
__device__ __half g_CL [M_TOT * D_MODEL];
__device__ __half g_W0 [D_MODEL * D_MODEL];
__device__ __half g_W1 [D_MODEL * D_MODEL];
__device__ __half g_W2 [D_MODEL * D_MODEL];
__device__ __half g_WOH[D_MODEL * D_MODEL];
__device__ __half g_WOL[D_MODEL * D_MODEL];

// ====================== helpers ======================
__device__ __forceinline__ uint32_t smem_u32(const void* p) {
    uint32_t a;
    asm("{ .reg .u64 t; cvta.to.shared.u64 t, %1; cvt.u32.u64 %0, t; }" : "=r"(a) : "l"(p));
    return a;
}
__device__ __forceinline__ void ldsm4(uint32_t* r, uint32_t addr) {
    asm volatile("ldmatrix.sync.aligned.m8n8.x4.shared.b16 {%0,%1,%2,%3}, [%4];"
        : "=r"(r[0]), "=r"(r[1]), "=r"(r[2]), "=r"(r[3]) : "r"(addr));
}
__device__ __forceinline__ void mma_f16(float* c, const uint32_t* a, const uint32_t* b) {
    asm volatile("mma.sync.aligned.m16n8k16.row.col.f32.f16.f16.f32 "
        "{%0,%1,%2,%3}, {%4,%5,%6,%7}, {%8,%9}, {%0,%1,%2,%3};"
        : "+f"(c[0]), "+f"(c[1]), "+f"(c[2]), "+f"(c[3])
        : "r"(a[0]), "r"(a[1]), "r"(a[2]), "r"(a[3]), "r"(b[0]), "r"(b[1]));
}
__device__ __forceinline__ uint32_t pack_h(float x, float y) {
    __half2 h = __floats2half2_rn(x, y);
    return *(uint32_t*)&h;
}
__device__ __forceinline__ void store_hilo(__half* H, __half* L, size_t off, float x, float y) {
    __half hx = __float2half_rn(x), hy = __float2half_rn(y);
    __half lx = __float2half_rn(x - __half2float(hx));
    __half ly = __float2half_rn(y - __half2float(hy));
    *(__half2*)(H + off) = __halves2half2(hx, hy);
    *(__half2*)(L + off) = __halves2half2(lx, ly);
}
#define CP_ASYNC16(s, g) asm volatile("cp.async.cg.shared.global [%0], [%1], 16;" :: "r"(s), "l"(g) : "memory")
#define CP_COMMIT()      asm volatile("cp.async.commit_group;" ::: "memory")
#define CP_WAIT1()       asm volatile("cp.async.wait_group 1;" ::: "memory")
#define CP_WAIT0()       asm volatile("cp.async.wait_group 0;" ::: "memory")

// =================================================================================
// converts
// =================================================================================
__global__ void split2_kernel(const float* __restrict__ x,
                              __half* __restrict__ hi, __half* __restrict__ lo, int n)
{
    int idx = (blockIdx.x * blockDim.x + threadIdx.x) * 4;
    if (idx >= n) return;
    float4 v = *(const float4*)(x + idx);
    __half h0 = __float2half_rn(v.x), h1 = __float2half_rn(v.y);
    __half h2 = __float2half_rn(v.z), h3 = __float2half_rn(v.w);
    __half l0 = __float2half_rn(v.x - __half2float(h0));
    __half l1 = __float2half_rn(v.y - __half2float(h1));
    __half l2 = __float2half_rn(v.z - __half2float(h2));
    __half l3 = __float2half_rn(v.w - __half2float(h3));
    *(__half2*)(hi + idx)     = __halves2half2(h0, h1);
    *(__half2*)(hi + idx + 2) = __halves2half2(h2, h3);
    *(__half2*)(lo + idx)     = __halves2half2(l0, l1);
    *(__half2*)(lo + idx + 2) = __halves2half2(l2, l3);
}

__global__ void conv1_kernel(const float* __restrict__ x, __half* __restrict__ o, int n)
{
    int idx = (blockIdx.x * blockDim.x + threadIdx.x) * 4;
    if (idx >= n) return;
    float4 v = *(const float4*)(x + idx);
    *(__half2*)(o + idx)     = __floats2half2_rn(v.x, v.y);
    *(__half2*)(o + idx + 2) = __floats2half2_rn(v.z, v.w);
}

// V transpose: V16 [b*S+s][h*64+d] -> VT [(b*16+h)*64+d][S]
__global__ void vtrans_kernel(const __half* __restrict__ V, __half* __restrict__ VT)
{
    __shared__ __half t[32][33];
    const int s0 = blockIdx.x * 32;
    const int d0 = blockIdx.y * 32;
    const int bh = blockIdx.z;
    const int b = bh >> 4, h = bh & 15;
    const int tid = threadIdx.x;
    const int cx = tid & 31, cy = tid >> 5;

#pragma unroll
    for (int i = 0; i < 4; i++) {
        int s = s0 + cy + i * 8;
        t[cy + i * 8][cx] = V[(size_t)(b * SEQ + s) * D_MODEL + h * 64 + d0 + cx];
    }
    __syncthreads();
#pragma unroll
    for (int i = 0; i < 4; i++) {
        int d = d0 + cy + i * 8;
        VT[(size_t)(bh * 64 + d) * SEQ + s0 + cx] = t[cx][cy + i * 8];
    }
}

// =================================================================================
// 16-warp mma.sync GEMM core: 128x128 CTA, BK=32, A 2-term + B NB-term, 3-stage ring.
// =================================================================================
#define G_ROWB     80                    // bytes per smem row (32 fp16 + pad)
#define G_TILE_B   (128 * G_ROWB)        // 10240

template<int NB>   // B-operand terms: 1 or 2. Tiles per stage = 2+NB.
__device__ __forceinline__ void gemm16_mainloop(
    uint32_t sb, int tid, int lane, int wid,
    const __half* __restrict__ Ah, const __half* __restrict__ Al,
    const __half* __restrict__ B0, const __half* __restrict__ B1,
    int row0, int col0, float acc[2][4][4])
{
    constexpr int NT = 2 + NB;
    constexpr int STAGE_B = NT * G_TILE_B;
    const int warp_m = wid >> 2, warp_n = wid & 3;
    const int la = lane & 7, lb8 = (lane >> 3) & 1, lb16 = lane >> 4;
    const uint32_t a_off = (uint32_t)((la + lb8 * 8) * G_ROWB + lb16 * 16);
    const uint32_t b_off = (uint32_t)((la + lb16 * 8) * G_ROWB + lb8 * 16);

    const __half* srcs[4] = { Ah + (size_t)row0 * 1024, Al + (size_t)row0 * 1024,
                              B0 + (size_t)col0 * 1024, B1 ? B1 + (size_t)col0 * 1024 : B0 };
    const int lt = tid >> 7;     // tile
    const int lr = tid & 127;    // row

    auto load_stage = [&](int st, int k0) {
        if (lt < NT) {
            const uint32_t s = sb + st * STAGE_B + lt * G_TILE_B + (uint32_t)lr * G_ROWB;
            const __half* g = srcs[lt] + (size_t)lr * 1024 + k0;
#pragma unroll
            for (int ch = 0; ch < 4; ch++)
                CP_ASYNC16(s + ch * 16, (const void*)(g + ch * 8));
        }
    };

    auto compute_stage = [&](int st) {
        const uint32_t s  = sb + st * STAGE_B;
        const uint32_t aH = s + 0 * G_TILE_B + (uint32_t)(warp_m * 32) * G_ROWB;
        const uint32_t aL = s + 1 * G_TILE_B + (uint32_t)(warp_m * 32) * G_ROWB;
        const uint32_t b0 = s + 2 * G_TILE_B + (uint32_t)(warp_n * 32) * G_ROWB;
        const uint32_t b1 = s + 3 * G_TILE_B + (uint32_t)(warp_n * 32) * G_ROWB;
#pragma unroll
        for (int ks = 0; ks < 2; ks++) {
            uint32_t ah[2][4], al[2][4], bh0[2][4], bh1[2][4];
#pragma unroll
            for (int mt = 0; mt < 2; mt++) {
                ldsm4(ah[mt], aH + (uint32_t)(mt * 16) * G_ROWB + ks * 32 + a_off);
                ldsm4(al[mt], aL + (uint32_t)(mt * 16) * G_ROWB + ks * 32 + a_off);
            }
#pragma unroll
            for (int p = 0; p < 2; p++) {
                ldsm4(bh0[p], b0 + (uint32_t)(p * 16) * G_ROWB + ks * 32 + b_off);
                if (NB == 2) ldsm4(bh1[p], b1 + (uint32_t)(p * 16) * G_ROWB + ks * 32 + b_off);
            }
#pragma unroll
            for (int mt = 0; mt < 2; mt++)
#pragma unroll
                for (int nt = 0; nt < 4; nt++) {
                    float* c = acc[mt][nt];
                    const uint32_t* bp = &bh0[nt >> 1][(nt & 1) * 2];
                    mma_f16(c, ah[mt], bp);
                    mma_f16(c, al[mt], bp);
                    if (NB == 2) mma_f16(c, ah[mt], &bh1[nt >> 1][(nt & 1) * 2]);
                }
        }
    };

    load_stage(0, 0);  CP_COMMIT();
    load_stage(1, 32); CP_COMMIT();
    for (int c = 0; c < 32; c++) {
        CP_WAIT1();
        __syncthreads();
        compute_stage(c % 3);
        if (c + 2 < 32) load_stage((c + 2) % 3, (c + 2) * 32);
        CP_COMMIT();
    }
}

// ---- fused QKV projection: A 2-term, W 1-term; epilogue hi/lo or 1-term ----
struct ProjOne {
    const __half *Ah, *Al, *W;
    const float* bias;
    __half *Oh, *Ol;      // Ol == nullptr -> single fp16 output
    float scale;
};
struct Proj3Args { ProjOne p[3]; };

__global__ __launch_bounds__(512)
void proj3_kernel(Proj3Args args)
{
    extern __shared__ __align__(128) char smem[];
    const ProjOne P = args.p[blockIdx.z];
    const uint32_t sb = smem_u32(smem);
    const int tid = threadIdx.x, lane = tid & 31, wid = tid >> 5;
    const int row0 = blockIdx.y * 128, col0 = blockIdx.x * 128;

    float acc[2][4][4];
#pragma unroll
    for (int a = 0; a < 2; a++)
#pragma unroll
        for (int b = 0; b < 4; b++)
#pragma unroll
            for (int c = 0; c < 4; c++) acc[a][b][c] = 0.f;

    gemm16_mainloop<1>(sb, tid, lane, wid, P.Ah, P.Al, P.W, nullptr, row0, col0, acc);

    const int warp_m = wid >> 2, warp_n = wid & 3;
    const int r_base = row0 + warp_m * 32, c_base = col0 + warp_n * 32;
#pragma unroll
    for (int mt = 0; mt < 2; mt++) {
        const int r = r_base + mt * 16 + (lane >> 2);
#pragma unroll
        for (int nt = 0; nt < 4; nt++) {
            const int cc = c_base + nt * 8 + (lane & 3) * 2;
            const float b0 = __ldg(P.bias + cc), b1 = __ldg(P.bias + cc + 1);
            float v00 = (acc[mt][nt][0] + b0) * P.scale;
            float v01 = (acc[mt][nt][1] + b1) * P.scale;
            float v10 = (acc[mt][nt][2] + b0) * P.scale;
            float v11 = (acc[mt][nt][3] + b1) * P.scale;
            if (P.Ol) {
                store_hilo(P.Oh, P.Ol, (size_t)r * 1024 + cc, v00, v01);
                store_hilo(P.Oh, P.Ol, (size_t)(r + 8) * 1024 + cc, v10, v11);
            } else {
                *(__half2*)(P.Oh + (size_t)r * 1024 + cc)       = __floats2half2_rn(v00, v01);
                *(__half2*)(P.Oh + (size_t)(r + 8) * 1024 + cc) = __floats2half2_rn(v10, v11);
            }
        }
    }
}

// ---- output projection: A=C 2-term, W 2-term (3 products), fp32 out ----
__global__ __launch_bounds__(512)
void gemmF_kernel(const __half* __restrict__ Ah, const __half* __restrict__ Al,
                  const __half* __restrict__ Wh, const __half* __restrict__ Wl,
                  const float* __restrict__ bias, float* __restrict__ C)
{
    extern __shared__ __align__(128) char smem[];
    const uint32_t sb = smem_u32(smem);
    const int tid = threadIdx.x, lane = tid & 31, wid = tid >> 5;
    const int row0 = blockIdx.y * 128, col0 = blockIdx.x * 128;

    float acc[2][4][4];
#pragma unroll
    for (int a = 0; a < 2; a++)
#pragma unroll
        for (int b = 0; b < 4; b++)
#pragma unroll
            for (int c = 0; c < 4; c++) acc[a][b][c] = 0.f;

    gemm16_mainloop<2>(sb, tid, lane, wid, Ah, Al, Wh, Wl, row0, col0, acc);

    const int warp_m = wid >> 2, warp_n = wid & 3;
    const int r_base = row0 + warp_m * 32, c_base = col0 + warp_n * 32;
#pragma unroll
    for (int mt = 0; mt < 2; mt++) {
        const int r = r_base + mt * 16 + (lane >> 2);
#pragma unroll
        for (int nt = 0; nt < 4; nt++) {
            const int cc = c_base + nt * 8 + (lane & 3) * 2;
            const float b0 = __ldg(bias + cc), b1 = __ldg(bias + cc + 1);
            float2 o0, o1;
            o0.x = acc[mt][nt][0] + b0; o0.y = acc[mt][nt][1] + b1;
            o1.x = acc[mt][nt][2] + b0; o1.y = acc[mt][nt][3] + b1;
            *(float2*)(C + (size_t)r * 1024 + cc)       = o0;
            *(float2*)(C + (size_t)(r + 8) * 1024 + cc) = o1;
        }
    }
}

// =================================================================================
// Flash attention: 16 warps, 256 q-rows/CTA, fp16. Q 2-term (regs), K/V 1-term.
// KV stage = [K | Vt], 3-stage ring. P hi/lo in registers. Out: CH/CL hi/lo.
// =================================================================================
#define A_STRIDE_B 144
#define A_TILE_B   (64 * A_STRIDE_B)    // 9216
#define A_STAGE_B  (2 * A_TILE_B)       // 18432 (K|Vt)
#define A_SMEM_TOT (8 * A_TILE_B)       // 73728 (Q staging needs 8 tiles worth)

__global__ __launch_bounds__(512)
void attention_mma_kernel(const __half* __restrict__ QH, const __half* __restrict__ QL,
                          const __half* __restrict__ K16, const __half* __restrict__ VT,
                          __half* __restrict__ CH, __half* __restrict__ CL)
{
    extern __shared__ __align__(128) char smem[];
    const uint32_t sb = smem_u32(smem);
    const int tid  = threadIdx.x;
    const int lane = tid & 31, wid = tid >> 5;
    const int bh = blockIdx.y;
    const int b = bh >> 4, h = bh & 15;
    const int q0 = blockIdx.x * 256;

    const int la   = lane & 7;
    const int lb8  = (lane >> 3) & 1;
    const int lb16 = lane >> 4;
    const uint32_t a_off = (uint32_t)((la + lb8 * 8) * A_STRIDE_B + lb16 * 16);
    const uint32_t b_off = (uint32_t)((la + lb16 * 8) * A_STRIDE_B + lb8 * 16);

    // ---- stage Q (hi at sb, lo at sb + 4*A_TILE_B), consume to registers ----
    {
#pragma unroll
        for (int i = 0; i < 4; i++) {
            int c = tid + i * 512;
            int r = c >> 3, ch = c & 7;
            const size_t g = (size_t)(b * SEQ + q0 + r) * D_MODEL + h * 64 + ch * 8;
            CP_ASYNC16(sb + r * A_STRIDE_B + ch * 16, (const void*)(QH + g));
            CP_ASYNC16(sb + 4 * A_TILE_B + r * A_STRIDE_B + ch * 16, (const void*)(QL + g));
        }
        CP_COMMIT();
        CP_WAIT0();
        __syncthreads();
    }
    uint32_t qh[4][4], ql[4][4];
#pragma unroll
    for (int ks = 0; ks < 4; ks++) {
        ldsm4(qh[ks], sb + (uint32_t)(wid * 16) * A_STRIDE_B + ks * 32 + a_off);
        ldsm4(ql[ks], sb + 4 * A_TILE_B + (uint32_t)(wid * 16) * A_STRIDE_B + ks * 32 + a_off);
    }
    __syncthreads();

    // ---- KV loader: 2 tiles x 64 rows x 128B; 4 threads per row, 32B each ----
    const int lt = tid >> 8;           // 0..1
    const int lr = (tid & 255) >> 2;   // 0..63
    const int lq = tid & 3;            // 0..3
    auto load_stage = [&](int st, int kv0) {
        const uint32_t s = sb + st * A_STAGE_B + lt * A_TILE_B
                         + (uint32_t)lr * A_STRIDE_B + lq * 32;
        const __half* g = (lt == 0)
            ? K16 + (size_t)(b * SEQ + kv0 + lr) * D_MODEL + h * 64 + lq * 16
            : VT  + (size_t)(bh * 64 + lr) * SEQ + kv0 + lq * 16;
        CP_ASYNC16(s,      (const void*)g);
        CP_ASYNC16(s + 16, (const void*)(g + 8));
    };

    load_stage(0, 0);  CP_COMMIT();
    load_stage(1, 64); CP_COMMIT();

    float o[8][4];
#pragma unroll
    for (int t = 0; t < 8; t++)
#pragma unroll
        for (int j = 0; j < 4; j++) o[t][j] = 0.f;
    float m_r[2] = {-1e30f, -1e30f};
    float l_r[2] = {0.f, 0.f};

    for (int it = 0; it < 32; it++) {
        CP_WAIT1();
        __syncthreads();
        const uint32_t st = sb + (it % 3) * A_STAGE_B;

        // ---- S = Q K^T (2 products) ----
        float s[8][4];
#pragma unroll
        for (int t = 0; t < 8; t++)
#pragma unroll
            for (int j = 0; j < 4; j++) s[t][j] = 0.f;
#pragma unroll
        for (int ks = 0; ks < 4; ks++) {
#pragma unroll
            for (int np = 0; np < 4; np++) {
                uint32_t k4[4];
                const uint32_t base = (uint32_t)(np * 16) * A_STRIDE_B + ks * 32 + b_off;
                ldsm4(k4, st + base);
                mma_f16(s[2 * np],     qh[ks], k4);
                mma_f16(s[2 * np],     ql[ks], k4);
                mma_f16(s[2 * np + 1], qh[ks], k4 + 2);
                mma_f16(s[2 * np + 1], ql[ks], k4 + 2);
            }
        }

        // ---- online softmax ----
#pragma unroll
        for (int r = 0; r < 2; r++) {
            float mx = s[0][2 * r];
#pragma unroll
            for (int t = 0; t < 8; t++) {
                mx = fmaxf(mx, s[t][2 * r]);
                mx = fmaxf(mx, s[t][2 * r + 1]);
            }
            mx = fmaxf(mx, __shfl_xor_sync(0xffffffffu, mx, 1));
            mx = fmaxf(mx, __shfl_xor_sync(0xffffffffu, mx, 2));
            float mn = fmaxf(m_r[r], mx);
            float al = __expf(m_r[r] - mn);
            m_r[r] = mn;
            float sum = 0.f;
#pragma unroll
            for (int t = 0; t < 8; t++) {
                float p0 = __expf(s[t][2 * r]     - mn);
                float p1 = __expf(s[t][2 * r + 1] - mn);
                s[t][2 * r] = p0; s[t][2 * r + 1] = p1;
                sum += p0 + p1;
            }
            sum += __shfl_xor_sync(0xffffffffu, sum, 1);
            sum += __shfl_xor_sync(0xffffffffu, sum, 2);
            l_r[r] = l_r[r] * al + sum;
#pragma unroll
            for (int t = 0; t < 8; t++) {
                o[t][2 * r] *= al; o[t][2 * r + 1] *= al;
            }
        }

        // ---- O += P V (2 products, P hi/lo in registers) ----
#pragma unroll
        for (int ks = 0; ks < 4; ks++) {
            const int t0 = 2 * ks, t1 = 2 * ks + 1;
            const float pv[8] = { s[t0][0], s[t0][1], s[t0][2], s[t0][3],
                                  s[t1][0], s[t1][1], s[t1][2], s[t1][3] };
            float ph[8], pl[8];
#pragma unroll
            for (int j = 0; j < 8; j++) {
                float hf = __half2float(__float2half_rn(pv[j]));
                ph[j] = hf; pl[j] = pv[j] - hf;
            }
            uint32_t pa_h[4], pa_l[4];
#pragma unroll
            for (int j = 0; j < 4; j++) {
                pa_h[j] = pack_h(ph[2 * j], ph[2 * j + 1]);
                pa_l[j] = pack_h(pl[2 * j], pl[2 * j + 1]);
            }
#pragma unroll
            for (int np = 0; np < 4; np++) {
                uint32_t v4[4];
                const uint32_t base = (uint32_t)(np * 16) * A_STRIDE_B + ks * 32 + b_off;
                ldsm4(v4, st + A_TILE_B + base);
                mma_f16(o[2 * np],     pa_h, v4);
                mma_f16(o[2 * np],     pa_l, v4);
                mma_f16(o[2 * np + 1], pa_h, v4 + 2);
                mma_f16(o[2 * np + 1], pa_l, v4 + 2);
            }
        }

        if (it + 2 < 32) load_stage((it + 2) % 3, (it + 2) * 64);
        CP_COMMIT();
    }

    // ---- epilogue: context hi/lo ----
    const float inv0 = 1.f / l_r[0];
    const float inv1 = 1.f / l_r[1];
    const int row0 = q0 + wid * 16 + (lane >> 2);
#pragma unroll
    for (int t = 0; t < 8; t++) {
        const int col = h * 64 + t * 8 + (lane & 3) * 2;
        store_hilo(CH, CL, (size_t)(b * SEQ + row0) * D_MODEL + col,
                   o[t][0] * inv0, o[t][1] * inv0);
        store_hilo(CH, CL, (size_t)(b * SEQ + row0 + 8) * D_MODEL + col,
                   o[t][2] * inv1, o[t][3] * inv1);
    }
}

// =================================================================================
// launch
// =================================================================================
extern "C" void kernel_launch(void* const* d_in, const int* in_sizes, int n_in,
                              void* d_out, int out_size)
{
    const float* x_q = (const float*)d_in[0];
    const float* x_k = (const float*)d_in[1];
    const float* x_v = (const float*)d_in[2];
    const float* wq  = (const float*)d_in[3];
    const float* bq  = (const float*)d_in[4];
    const float* wk  = (const float*)d_in[5];
    const float* bk  = (const float*)d_in[6];
    const float* wv  = (const float*)d_in[7];
    const float* bv  = (const float*)d_in[8];
    const float* wo  = (const float*)d_in[9];
    const float* bo  = (const float*)d_in[10];
    float* out = (float*)d_out;

    __half *xh0, *xl0, *xh1, *xl1, *xh2, *xl2;
    __half *qh, *ql, *k16, *v16, *vt, *ch, *cl;
    __half *w0, *w1, *w2, *woh, *wol;
    cudaGetSymbolAddress((void**)&xh0, g_XH0); cudaGetSymbolAddress((void**)&xl0, g_XL0);
    cudaGetSymbolAddress((void**)&xh1, g_XH1); cudaGetSymbolAddress((void**)&xl1, g_XL1);
    cudaGetSymbolAddress((void**)&xh2, g_XH2); cudaGetSymbolAddress((void**)&xl2, g_XL2);
    cudaGetSymbolAddress((void**)&qh,  g_QH);  cudaGetSymbolAddress((void**)&ql,  g_QL);
    cudaGetSymbolAddress((void**)&k16, g_K16); cudaGetSymbolAddress((void**)&v16, g_V16);
    cudaGetSymbolAddress((void**)&vt,  g_VT);
    cudaGetSymbolAddress((void**)&ch,  g_CH);  cudaGetSymbolAddress((void**)&cl,  g_CL);
    cudaGetSymbolAddress((void**)&w0,  g_W0);  cudaGetSymbolAddress((void**)&w1,  g_W1);
    cudaGetSymbolAddress((void**)&w2,  g_W2);
    cudaGetSymbolAddress((void**)&woh, g_WOH); cudaGetSymbolAddress((void**)&wol, g_WOL);

    static int attr_set = 0;
    const int proj_smem = 3 * 3 * G_TILE_B;   // 3 stages x 3 tiles = 92160
    const int gemf_smem = 3 * 4 * G_TILE_B;   // 3 stages x 4 tiles = 122880
    if (!attr_set) {
        cudaFuncSetAttribute(proj3_kernel,
                             cudaFuncAttributeMaxDynamicSharedMemorySize, proj_smem);
        cudaFuncSetAttribute(gemmF_kernel,
                             cudaFuncAttributeMaxDynamicSharedMemorySize, gemf_smem);
        cudaFuncSetAttribute(attention_mma_kernel,
                             cudaFuncAttributeMaxDynamicSharedMemorySize, A_SMEM_TOT);
        attr_set = 1;
    }

    const int NX = M_TOT * D_MODEL;
    const int NW = D_MODEL * D_MODEL;
    dim3 cb(256);
    dim3 cgx((NX / 4 + 255) / 256);
    dim3 cgw((NW / 4 + 255) / 256);

    // converts
    split2_kernel<<<cgx, cb>>>(x_q, xh0, xl0, NX);
    split2_kernel<<<cgx, cb>>>(x_k, xh1, xl1, NX);
    split2_kernel<<<cgx, cb>>>(x_v, xh2, xl2, NX);
    conv1_kernel<<<cgw, cb>>>(wq, w0, NW);
    conv1_kernel<<<cgw, cb>>>(wk, w1, NW);
    conv1_kernel<<<cgw, cb>>>(wv, w2, NW);
    split2_kernel<<<cgw, cb>>>(wo, woh, wol, NW);

    // fused QKV projections
    Proj3Args pa;
    pa.p[0] = { xh0, xl0, w0, bq, qh, ql, 0.125f };       // Q: hi/lo, pre-scaled
    pa.p[1] = { xh1, xl1, w1, bk, k16, nullptr, 1.0f };   // K: 1-term
    pa.p[2] = { xh2, xl2, w2, bv, v16, nullptr, 1.0f };   // V: 1-term
    proj3_kernel<<<dim3(8, 64, 3), 512, proj_smem>>>(pa);

    // V transpose
    vtrans_kernel<<<dim3(SEQ / 32, 2, BATCH * NHEAD), 256>>>(v16, vt);

    // attention
    attention_mma_kernel<<<dim3(SEQ / 256, BATCH * NHEAD), 512, A_SMEM_TOT>>>(
        qh, ql, k16, vt, ch, cl);

    // output projection (3-product for precision)
    gemmF_kernel<<<dim3(8, 64), 512, gemf_smem>>>(ch, cl, woh, wol, bo, out);
}

// round 7
// speedup vs baseline: 4.2475x; 1.1687x over previous
#include <cuda_runtime.h>
#include <cuda_fp16.h>
#include <math.h>
#include <cstdint>

#define D_MODEL 1024
#define NHEAD   16
#define D_K     64
#define BATCH   4
#define SEQ     2048
#define M_TOT   (BATCH * SEQ)   // 8192

// ---------------- scratch (device globals: allocation-free rule) ----------------
__device__ __half g_XH0[M_TOT * D_MODEL];
__device__ __half g_XL0[M_TOT * D_MODEL];
__device__ __half g_XH1[M_TOT * D_MODEL];
__device__ __half g_XL1[M_TOT * D_MODEL];
__device__ __half g_XH2[M_TOT * D_MODEL];
__device__ __half g_XL2[M_TOT * D_MODEL];
__device__ __half g_Q16[M_TOT * D_MODEL];
__device__ __half g_K16[M_TOT * D_MODEL];
__device__ __half g_V16[M_TOT * D_MODEL];
__device__ __half g_VT [M_TOT * D_MODEL];
__device__ __half g_CH [M_TOT * D_MODEL];
__device__ __half g_CL [M_TOT * D_MODEL];
__device__ __half g_W0 [D_MODEL * D_MODEL];
__device__ __half g_W1 [D_MODEL * D_MODEL];
__device__ __half g_W2 [D_MODEL * D_MODEL];
__device__ __half g_WOH[D_MODEL * D_MODEL];
__device__ __half g_WOL[D_MODEL * D_MODEL];

// ====================== helpers ======================
__device__ __forceinline__ uint32_t smem_u32(const void* p) {
    uint32_t a;
    asm("{ .reg .u64 t; cvta.to.shared.u64 t, %1; cvt.u32.u64 %0, t; }" : "=r"(a) : "l"(p));
    return a;
}
__device__ __forceinline__ void ldsm4(uint32_t* r, uint32_t addr) {
    asm volatile("ldmatrix.sync.aligned.m8n8.x4.shared.b16 {%0,%1,%2,%3}, [%4];"
        : "=r"(r[0]), "=r"(r[1]), "=r"(r[2]), "=r"(r[3]) : "r"(addr));
}
__device__ __forceinline__ void mma_f16(float* c, const uint32_t* a, const uint32_t* b) {
    asm volatile("mma.sync.aligned.m16n8k16.row.col.f32.f16.f16.f32 "
        "{%0,%1,%2,%3}, {%4,%5,%6,%7}, {%8,%9}, {%0,%1,%2,%3};"
        : "+f"(c[0]), "+f"(c[1]), "+f"(c[2]), "+f"(c[3])
        : "r"(a[0]), "r"(a[1]), "r"(a[2]), "r"(a[3]), "r"(b[0]), "r"(b[1]));
}
__device__ __forceinline__ uint32_t pack_h(float x, float y) {
    __half2 h = __floats2half2_rn(x, y);
    return *(uint32_t*)&h;
}
__device__ __forceinline__ void store_hilo(__half* H, __half* L, size_t off, float x, float y) {
    __half hx = __float2half_rn(x), hy = __float2half_rn(y);
    __half lx = __float2half_rn(x - __half2float(hx));
    __half ly = __float2half_rn(y - __half2float(hy));
    *(__half2*)(H + off) = __halves2half2(hx, hy);
    *(__half2*)(L + off) = __halves2half2(lx, ly);
}
#define CP_ASYNC16(s, g) asm volatile("cp.async.cg.shared.global [%0], [%1], 16;" :: "r"(s), "l"(g) : "memory")
#define CP_COMMIT()      asm volatile("cp.async.commit_group;" ::: "memory")
#define CP_WAIT1()       asm volatile("cp.async.wait_group 1;" ::: "memory")
#define CP_WAIT0()       asm volatile("cp.async.wait_group 0;" ::: "memory")

// =================================================================================
// converts
// =================================================================================
__global__ void split2_kernel(const float* __restrict__ x,
                              __half* __restrict__ hi, __half* __restrict__ lo, int n)
{
    int idx = (blockIdx.x * blockDim.x + threadIdx.x) * 4;
    if (idx >= n) return;
    float4 v = *(const float4*)(x + idx);
    __half h0 = __float2half_rn(v.x), h1 = __float2half_rn(v.y);
    __half h2 = __float2half_rn(v.z), h3 = __float2half_rn(v.w);
    __half l0 = __float2half_rn(v.x - __half2float(h0));
    __half l1 = __float2half_rn(v.y - __half2float(h1));
    __half l2 = __float2half_rn(v.z - __half2float(h2));
    __half l3 = __float2half_rn(v.w - __half2float(h3));
    *(__half2*)(hi + idx)     = __halves2half2(h0, h1);
    *(__half2*)(hi + idx + 2) = __halves2half2(h2, h3);
    *(__half2*)(lo + idx)     = __halves2half2(l0, l1);
    *(__half2*)(lo + idx + 2) = __halves2half2(l2, l3);
}

__global__ void conv1_kernel(const float* __restrict__ x, __half* __restrict__ o, int n)
{
    int idx = (blockIdx.x * blockDim.x + threadIdx.x) * 4;
    if (idx >= n) return;
    float4 v = *(const float4*)(x + idx);
    *(__half2*)(o + idx)     = __floats2half2_rn(v.x, v.y);
    *(__half2*)(o + idx + 2) = __floats2half2_rn(v.z, v.w);
}

// V transpose: V16 [b*S+s][h*64+d] -> VT [(b*16+h)*64+d][S]
__global__ void vtrans_kernel(const __half* __restrict__ V, __half* __restrict__ VT)
{
    __shared__ __half t[32][33];
    const int s0 = blockIdx.x * 32;
    const int d0 = blockIdx.y * 32;
    const int bh = blockIdx.z;
    const int b = bh >> 4, h = bh & 15;
    const int tid = threadIdx.x;
    const int cx = tid & 31, cy = tid >> 5;

#pragma unroll
    for (int i = 0; i < 4; i++) {
        int s = s0 + cy + i * 8;
        t[cy + i * 8][cx] = V[(size_t)(b * SEQ + s) * D_MODEL + h * 64 + d0 + cx];
    }
    __syncthreads();
#pragma unroll
    for (int i = 0; i < 4; i++) {
        int d = d0 + cy + i * 8;
        VT[(size_t)(bh * 64 + d) * SEQ + s0 + cx] = t[cx][cy + i * 8];
    }
}

// =================================================================================
// 16-warp mma.sync GEMM core: 128x128 CTA, BK=32, A 2-term + B NB-term, 3-stage ring.
// =================================================================================
#define G_ROWB     80
#define G_TILE_B   (128 * G_ROWB)        // 10240

template<int NB>
__device__ __forceinline__ void gemm16_mainloop(
    uint32_t sb, int tid, int lane, int wid,
    const __half* __restrict__ Ah, const __half* __restrict__ Al,
    const __half* __restrict__ B0, const __half* __restrict__ B1,
    int row0, int col0, float acc[2][4][4])
{
    constexpr int NT = 2 + NB;
    constexpr int STAGE_B = NT * G_TILE_B;
    const int warp_m = wid >> 2, warp_n = wid & 3;
    const int la = lane & 7, lb8 = (lane >> 3) & 1, lb16 = lane >> 4;
    const uint32_t a_off = (uint32_t)((la + lb8 * 8) * G_ROWB + lb16 * 16);
    const uint32_t b_off = (uint32_t)((la + lb16 * 8) * G_ROWB + lb8 * 16);

    const __half* srcs[4] = { Ah + (size_t)row0 * 1024, Al + (size_t)row0 * 1024,
                              B0 + (size_t)col0 * 1024, B1 ? B1 + (size_t)col0 * 1024 : B0 };
    const int lt = tid >> 7;
    const int lr = tid & 127;

    auto load_stage = [&](int st, int k0) {
        if (lt < NT) {
            const uint32_t s = sb + st * STAGE_B + lt * G_TILE_B + (uint32_t)lr * G_ROWB;
            const __half* g = srcs[lt] + (size_t)lr * 1024 + k0;
#pragma unroll
            for (int ch = 0; ch < 4; ch++)
                CP_ASYNC16(s + ch * 16, (const void*)(g + ch * 8));
        }
    };

    auto compute_stage = [&](int st) {
        const uint32_t s  = sb + st * STAGE_B;
        const uint32_t aH = s + 0 * G_TILE_B + (uint32_t)(warp_m * 32) * G_ROWB;
        const uint32_t aL = s + 1 * G_TILE_B + (uint32_t)(warp_m * 32) * G_ROWB;
        const uint32_t b0 = s + 2 * G_TILE_B + (uint32_t)(warp_n * 32) * G_ROWB;
        const uint32_t b1 = s + 3 * G_TILE_B + (uint32_t)(warp_n * 32) * G_ROWB;
#pragma unroll
        for (int ks = 0; ks < 2; ks++) {
            uint32_t ah[2][4], al[2][4], bh0[2][4], bh1[2][4];
#pragma unroll
            for (int mt = 0; mt < 2; mt++) {
                ldsm4(ah[mt], aH + (uint32_t)(mt * 16) * G_ROWB + ks * 32 + a_off);
                ldsm4(al[mt], aL + (uint32_t)(mt * 16) * G_ROWB + ks * 32 + a_off);
            }
#pragma unroll
            for (int p = 0; p < 2; p++) {
                ldsm4(bh0[p], b0 + (uint32_t)(p * 16) * G_ROWB + ks * 32 + b_off);
                if (NB == 2) ldsm4(bh1[p], b1 + (uint32_t)(p * 16) * G_ROWB + ks * 32 + b_off);
            }
#pragma unroll
            for (int mt = 0; mt < 2; mt++)
#pragma unroll
                for (int nt = 0; nt < 4; nt++) {
                    float* c = acc[mt][nt];
                    const uint32_t* bp = &bh0[nt >> 1][(nt & 1) * 2];
                    mma_f16(c, ah[mt], bp);
                    mma_f16(c, al[mt], bp);
                    if (NB == 2) mma_f16(c, ah[mt], &bh1[nt >> 1][(nt & 1) * 2]);
                }
        }
    };

    load_stage(0, 0);  CP_COMMIT();
    load_stage(1, 32); CP_COMMIT();
    for (int c = 0; c < 32; c++) {
        CP_WAIT1();
        __syncthreads();
        compute_stage(c % 3);
        if (c + 2 < 32) load_stage((c + 2) % 3, (c + 2) * 32);
        CP_COMMIT();
    }
}

// ---- fused QKV projection: A 2-term, W 1-term; fp16 single output (scaled) ----
struct ProjOne {
    const __half *Ah, *Al, *W;
    const float* bias;
    __half *O;
    float scale;
};
struct Proj3Args { ProjOne p[3]; };

__global__ __launch_bounds__(512)
void proj3_kernel(Proj3Args args)
{
    extern __shared__ __align__(128) char smem[];
    const ProjOne P = args.p[blockIdx.z];
    const uint32_t sb = smem_u32(smem);
    const int tid = threadIdx.x, lane = tid & 31, wid = tid >> 5;
    const int row0 = blockIdx.y * 128, col0 = blockIdx.x * 128;

    float acc[2][4][4];
#pragma unroll
    for (int a = 0; a < 2; a++)
#pragma unroll
        for (int b = 0; b < 4; b++)
#pragma unroll
            for (int c = 0; c < 4; c++) acc[a][b][c] = 0.f;

    gemm16_mainloop<1>(sb, tid, lane, wid, P.Ah, P.Al, P.W, nullptr, row0, col0, acc);

    const int warp_m = wid >> 2, warp_n = wid & 3;
    const int r_base = row0 + warp_m * 32, c_base = col0 + warp_n * 32;
#pragma unroll
    for (int mt = 0; mt < 2; mt++) {
        const int r = r_base + mt * 16 + (lane >> 2);
#pragma unroll
        for (int nt = 0; nt < 4; nt++) {
            const int cc = c_base + nt * 8 + (lane & 3) * 2;
            const float b0 = __ldg(P.bias + cc), b1 = __ldg(P.bias + cc + 1);
            *(__half2*)(P.O + (size_t)r * 1024 + cc) =
                __floats2half2_rn((acc[mt][nt][0] + b0) * P.scale,
                                  (acc[mt][nt][1] + b1) * P.scale);
            *(__half2*)(P.O + (size_t)(r + 8) * 1024 + cc) =
                __floats2half2_rn((acc[mt][nt][2] + b0) * P.scale,
                                  (acc[mt][nt][3] + b1) * P.scale);
        }
    }
}

// ---- output projection: C 2-term, W 2-term (3 products), fp32 out ----
__global__ __launch_bounds__(512)
void gemmF_kernel(const __half* __restrict__ Ah, const __half* __restrict__ Al,
                  const __half* __restrict__ Wh, const __half* __restrict__ Wl,
                  const float* __restrict__ bias, float* __restrict__ C)
{
    extern __shared__ __align__(128) char smem[];
    const uint32_t sb = smem_u32(smem);
    const int tid = threadIdx.x, lane = tid & 31, wid = tid >> 5;
    const int row0 = blockIdx.y * 128, col0 = blockIdx.x * 128;

    float acc[2][4][4];
#pragma unroll
    for (int a = 0; a < 2; a++)
#pragma unroll
        for (int b = 0; b < 4; b++)
#pragma unroll
            for (int c = 0; c < 4; c++) acc[a][b][c] = 0.f;

    gemm16_mainloop<2>(sb, tid, lane, wid, Ah, Al, Wh, Wl, row0, col0, acc);

    const int warp_m = wid >> 2, warp_n = wid & 3;
    const int r_base = row0 + warp_m * 32, c_base = col0 + warp_n * 32;
#pragma unroll
    for (int mt = 0; mt < 2; mt++) {
        const int r = r_base + mt * 16 + (lane >> 2);
#pragma unroll
        for (int nt = 0; nt < 4; nt++) {
            const int cc = c_base + nt * 8 + (lane & 3) * 2;
            const float b0 = __ldg(bias + cc), b1 = __ldg(bias + cc + 1);
            float2 o0, o1;
            o0.x = acc[mt][nt][0] + b0; o0.y = acc[mt][nt][1] + b1;
            o1.x = acc[mt][nt][2] + b0; o1.y = acc[mt][nt][3] + b1;
            *(float2*)(C + (size_t)r * 1024 + cc)       = o0;
            *(float2*)(C + (size_t)(r + 8) * 1024 + cc) = o1;
        }
    }
}

// =================================================================================
// Flash attention: pure fp16 operands, fp32 accum. 16 warps, 256 q-rows/CTA.
// KV stage = [K | Vt], 3-stage ring. Out: CH/CL hi/lo (kept exact for out-proj).
// =================================================================================
#define A_STRIDE_B 144
#define A_TILE_B   (64 * A_STRIDE_B)    // 9216
#define A_STAGE_B  (2 * A_TILE_B)       // 18432 (K|Vt)
#define A_SMEM_TOT (6 * A_TILE_B)       // 55296 (3-stage ring; Q staging fits: 4 tiles)

__global__ __launch_bounds__(512)
void attention_mma_kernel(const __half* __restrict__ Q16,
                          const __half* __restrict__ K16, const __half* __restrict__ VT,
                          __half* __restrict__ CH, __half* __restrict__ CL)
{
    extern __shared__ __align__(128) char smem[];
    const uint32_t sb = smem_u32(smem);
    const int tid  = threadIdx.x;
    const int lane = tid & 31, wid = tid >> 5;
    const int bh = blockIdx.y;
    const int b = bh >> 4, h = bh & 15;
    const int q0 = blockIdx.x * 256;

    const int la   = lane & 7;
    const int lb8  = (lane >> 3) & 1;
    const int lb16 = lane >> 4;
    const uint32_t a_off = (uint32_t)((la + lb8 * 8) * A_STRIDE_B + lb16 * 16);
    const uint32_t b_off = (uint32_t)((la + lb16 * 8) * A_STRIDE_B + lb8 * 16);

    // ---- stage Q (single term) and move to registers ----
    {
#pragma unroll
        for (int i = 0; i < 2; i++) {
            int c = tid + i * 512;           // 0..1023 -> 256 rows x 4? No: 2048 chunks
            // 256 rows x 8 chunks = 2048 chunks; each thread does 4
        }
#pragma unroll
        for (int i = 0; i < 4; i++) {
            int c = tid + i * 512;
            int r = c >> 3, ch = c & 7;
            const size_t g = (size_t)(b * SEQ + q0 + r) * D_MODEL + h * 64 + ch * 8;
            CP_ASYNC16(sb + r * A_STRIDE_B + ch * 16, (const void*)(Q16 + g));
        }
        CP_COMMIT();
        CP_WAIT0();
        __syncthreads();
    }
    uint32_t qh[4][4];
#pragma unroll
    for (int ks = 0; ks < 4; ks++)
        ldsm4(qh[ks], sb + (uint32_t)(wid * 16) * A_STRIDE_B + ks * 32 + a_off);
    __syncthreads();

    // ---- KV loader ----
    const int lt = tid >> 8;
    const int lr = (tid & 255) >> 2;
    const int lq = tid & 3;
    auto load_stage = [&](int st, int kv0) {
        const uint32_t s = sb + st * A_STAGE_B + lt * A_TILE_B
                         + (uint32_t)lr * A_STRIDE_B + lq * 32;
        const __half* g = (lt == 0)
            ? K16 + (size_t)(b * SEQ + kv0 + lr) * D_MODEL + h * 64 + lq * 16
            : VT  + (size_t)(bh * 64 + lr) * SEQ + kv0 + lq * 16;
        CP_ASYNC16(s,      (const void*)g);
        CP_ASYNC16(s + 16, (const void*)(g + 8));
    };

    load_stage(0, 0);  CP_COMMIT();
    load_stage(1, 64); CP_COMMIT();

    float o[8][4];
#pragma unroll
    for (int t = 0; t < 8; t++)
#pragma unroll
        for (int j = 0; j < 4; j++) o[t][j] = 0.f;
    float m_r[2] = {-1e30f, -1e30f};
    float l_r[2] = {0.f, 0.f};

    for (int it = 0; it < 32; it++) {
        CP_WAIT1();
        __syncthreads();
        const uint32_t st = sb + (it % 3) * A_STAGE_B;

        // ---- S = Q K^T (single product) ----
        float s[8][4];
#pragma unroll
        for (int t = 0; t < 8; t++)
#pragma unroll
            for (int j = 0; j < 4; j++) s[t][j] = 0.f;
#pragma unroll
        for (int ks = 0; ks < 4; ks++) {
#pragma unroll
            for (int np = 0; np < 4; np++) {
                uint32_t k4[4];
                const uint32_t base = (uint32_t)(np * 16) * A_STRIDE_B + ks * 32 + b_off;
                ldsm4(k4, st + base);
                mma_f16(s[2 * np],     qh[ks], k4);
                mma_f16(s[2 * np + 1], qh[ks], k4 + 2);
            }
        }

        // ---- online softmax ----
#pragma unroll
        for (int r = 0; r < 2; r++) {
            float mx = s[0][2 * r];
#pragma unroll
            for (int t = 0; t < 8; t++) {
                mx = fmaxf(mx, s[t][2 * r]);
                mx = fmaxf(mx, s[t][2 * r + 1]);
            }
            mx = fmaxf(mx, __shfl_xor_sync(0xffffffffu, mx, 1));
            mx = fmaxf(mx, __shfl_xor_sync(0xffffffffu, mx, 2));
            float mn = fmaxf(m_r[r], mx);
            float al = __expf(m_r[r] - mn);
            m_r[r] = mn;
            float sum = 0.f;
#pragma unroll
            for (int t = 0; t < 8; t++) {
                float p0 = __expf(s[t][2 * r]     - mn);
                float p1 = __expf(s[t][2 * r + 1] - mn);
                s[t][2 * r] = p0; s[t][2 * r + 1] = p1;
                sum += p0 + p1;
            }
            sum += __shfl_xor_sync(0xffffffffu, sum, 1);
            sum += __shfl_xor_sync(0xffffffffu, sum, 2);
            l_r[r] = l_r[r] * al + sum;
#pragma unroll
            for (int t = 0; t < 8; t++) {
                o[t][2 * r] *= al; o[t][2 * r + 1] *= al;
            }
        }

        // ---- O += P V (single product; P packed fp16 in registers) ----
#pragma unroll
        for (int ks = 0; ks < 4; ks++) {
            const int t0 = 2 * ks, t1 = 2 * ks + 1;
            uint32_t pa[4];
            pa[0] = pack_h(s[t0][0], s[t0][1]);
            pa[1] = pack_h(s[t0][2], s[t0][3]);
            pa[2] = pack_h(s[t1][0], s[t1][1]);
            pa[3] = pack_h(s[t1][2], s[t1][3]);
#pragma unroll
            for (int np = 0; np < 4; np++) {
                uint32_t v4[4];
                const uint32_t base = (uint32_t)(np * 16) * A_STRIDE_B + ks * 32 + b_off;
                ldsm4(v4, st + A_TILE_B + base);
                mma_f16(o[2 * np],     pa, v4);
                mma_f16(o[2 * np + 1], pa, v4 + 2);
            }
        }

        if (it + 2 < 32) load_stage((it + 2) % 3, (it + 2) * 64);
        CP_COMMIT();
    }

    // ---- epilogue: context hi/lo ----
    const float inv0 = 1.f / l_r[0];
    const float inv1 = 1.f / l_r[1];
    const int row0 = q0 + wid * 16 + (lane >> 2);
#pragma unroll
    for (int t = 0; t < 8; t++) {
        const int col = h * 64 + t * 8 + (lane & 3) * 2;
        store_hilo(CH, CL, (size_t)(b * SEQ + row0) * D_MODEL + col,
                   o[t][0] * inv0, o[t][1] * inv0);
        store_hilo(CH, CL, (size_t)(b * SEQ + row0 + 8) * D_MODEL + col,
                   o[t][2] * inv1, o[t][3] * inv1);
    }
}

// =================================================================================
// launch
// =================================================================================
extern "C" void kernel_launch(void* const* d_in, const int* in_sizes, int n_in,
                              void* d_out, int out_size)
{
    const float* x_q = (const float*)d_in[0];
    const float* x_k = (const float*)d_in[1];
    const float* x_v = (const float*)d_in[2];
    const float* wq  = (const float*)d_in[3];
    const float* bq  = (const float*)d_in[4];
    const float* wk  = (const float*)d_in[5];
    const float* bk  = (const float*)d_in[6];
    const float* wv  = (const float*)d_in[7];
    const float* bv  = (const float*)d_in[8];
    const float* wo  = (const float*)d_in[9];
    const float* bo  = (const float*)d_in[10];
    float* out = (float*)d_out;

    __half *xh0, *xl0, *xh1, *xl1, *xh2, *xl2;
    __half *q16, *k16, *v16, *vt, *ch, *cl;
    __half *w0, *w1, *w2, *woh, *wol;
    cudaGetSymbolAddress((void**)&xh0, g_XH0); cudaGetSymbolAddress((void**)&xl0, g_XL0);
    cudaGetSymbolAddress((void**)&xh1, g_XH1); cudaGetSymbolAddress((void**)&xl1, g_XL1);
    cudaGetSymbolAddress((void**)&xh2, g_XH2); cudaGetSymbolAddress((void**)&xl2, g_XL2);
    cudaGetSymbolAddress((void**)&q16, g_Q16);
    cudaGetSymbolAddress((void**)&k16, g_K16); cudaGetSymbolAddress((void**)&v16, g_V16);
    cudaGetSymbolAddress((void**)&vt,  g_VT);
    cudaGetSymbolAddress((void**)&ch,  g_CH);  cudaGetSymbolAddress((void**)&cl,  g_CL);
    cudaGetSymbolAddress((void**)&w0,  g_W0);  cudaGetSymbolAddress((void**)&w1,  g_W1);
    cudaGetSymbolAddress((void**)&w2,  g_W2);
    cudaGetSymbolAddress((void**)&woh, g_WOH); cudaGetSymbolAddress((void**)&wol, g_WOL);

    static int attr_set = 0;
    const int proj_smem = 3 * 3 * G_TILE_B;   // 92160
    const int gemf_smem = 3 * 4 * G_TILE_B;   // 122880
    if (!attr_set) {
        cudaFuncSetAttribute(proj3_kernel,
                             cudaFuncAttributeMaxDynamicSharedMemorySize, proj_smem);
        cudaFuncSetAttribute(gemmF_kernel,
                             cudaFuncAttributeMaxDynamicSharedMemorySize, gemf_smem);
        cudaFuncSetAttribute(attention_mma_kernel,
                             cudaFuncAttributeMaxDynamicSharedMemorySize, A_SMEM_TOT);
        attr_set = 1;
    }

    const int NX = M_TOT * D_MODEL;
    const int NW = D_MODEL * D_MODEL;
    dim3 cb(256);
    dim3 cgx((NX / 4 + 255) / 256);
    dim3 cgw((NW / 4 + 255) / 256);

    // converts
    split2_kernel<<<cgx, cb>>>(x_q, xh0, xl0, NX);
    split2_kernel<<<cgx, cb>>>(x_k, xh1, xl1, NX);
    split2_kernel<<<cgx, cb>>>(x_v, xh2, xl2, NX);
    conv1_kernel<<<cgw, cb>>>(wq, w0, NW);
    conv1_kernel<<<cgw, cb>>>(wk, w1, NW);
    conv1_kernel<<<cgw, cb>>>(wv, w2, NW);
    split2_kernel<<<cgw, cb>>>(wo, woh, wol, NW);

    // fused QKV projections (all fp16 single outputs; Q pre-scaled)
    Proj3Args pa;
    pa.p[0] = { xh0, xl0, w0, bq, q16, 0.125f };
    pa.p[1] = { xh1, xl1, w1, bk, k16, 1.0f };
    pa.p[2] = { xh2, xl2, w2, bv, v16, 1.0f };
    proj3_kernel<<<dim3(8, 64, 3), 512, proj_smem>>>(pa);

    // V transpose
    vtrans_kernel<<<dim3(SEQ / 32, 2, BATCH * NHEAD), 256>>>(v16, vt);

    // attention (pure fp16)
    attention_mma_kernel<<<dim3(SEQ / 256, BATCH * NHEAD), 512, A_SMEM_TOT>>>(
        q16, k16, vt, ch, cl);

    // output projection (3-product, exactness anchor)
    gemmF_kernel<<<dim3(8, 64), 512, gemf_smem>>>(ch, cl, woh, wol, bo, out);
}

// round 8
// speedup vs baseline: 5.3599x; 1.2619x over previous
#include <cuda_runtime.h>
#include <cuda_fp16.h>
#include <math.h>
#include <cstdint>

#define D_MODEL 1024
#define NHEAD   16
#define D_K     64
#define BATCH   4
#define SEQ     2048
#define M_TOT   (BATCH * SEQ)   // 8192

// ---------------- scratch (device globals: allocation-free rule) ----------------
__device__ __half g_X0 [M_TOT * D_MODEL];
__device__ __half g_X1 [M_TOT * D_MODEL];
__device__ __half g_X2 [M_TOT * D_MODEL];
__device__ __half g_Q16[M_TOT * D_MODEL];
__device__ __half g_K16[M_TOT * D_MODEL];
__device__ __half g_V16[M_TOT * D_MODEL];
__device__ __half g_VT [M_TOT * D_MODEL];
__device__ __half g_CH [M_TOT * D_MODEL];
__device__ __half g_CL [M_TOT * D_MODEL];
__device__ __half g_W0 [D_MODEL * D_MODEL];
__device__ __half g_W1 [D_MODEL * D_MODEL];
__device__ __half g_W2 [D_MODEL * D_MODEL];
__device__ __half g_W3 [D_MODEL * D_MODEL];

// ====================== helpers ======================
__device__ __forceinline__ uint32_t smem_u32(const void* p) {
    uint32_t a;
    asm("{ .reg .u64 t; cvta.to.shared.u64 t, %1; cvt.u32.u64 %0, t; }" : "=r"(a) : "l"(p));
    return a;
}
__device__ __forceinline__ void ldsm4(uint32_t* r, uint32_t addr) {
    asm volatile("ldmatrix.sync.aligned.m8n8.x4.shared.b16 {%0,%1,%2,%3}, [%4];"
        : "=r"(r[0]), "=r"(r[1]), "=r"(r[2]), "=r"(r[3]) : "r"(addr));
}
__device__ __forceinline__ void mma_f16(float* c, const uint32_t* a, const uint32_t* b) {
    asm volatile("mma.sync.aligned.m16n8k16.row.col.f32.f16.f16.f32 "
        "{%0,%1,%2,%3}, {%4,%5,%6,%7}, {%8,%9}, {%0,%1,%2,%3};"
        : "+f"(c[0]), "+f"(c[1]), "+f"(c[2]), "+f"(c[3])
        : "r"(a[0]), "r"(a[1]), "r"(a[2]), "r"(a[3]), "r"(b[0]), "r"(b[1]));
}
__device__ __forceinline__ uint32_t pack_h(float x, float y) {
    __half2 h = __floats2half2_rn(x, y);
    return *(uint32_t*)&h;
}
__device__ __forceinline__ void store_hilo(__half* H, __half* L, size_t off, float x, float y) {
    __half hx = __float2half_rn(x), hy = __float2half_rn(y);
    __half lx = __float2half_rn(x - __half2float(hx));
    __half ly = __float2half_rn(y - __half2float(hy));
    *(__half2*)(H + off) = __halves2half2(hx, hy);
    *(__half2*)(L + off) = __halves2half2(lx, ly);
}
#define CP_ASYNC16(s, g) asm volatile("cp.async.cg.shared.global [%0], [%1], 16;" :: "r"(s), "l"(g) : "memory")
#define CP_COMMIT()      asm volatile("cp.async.commit_group;" ::: "memory")
#define CP_WAIT1()       asm volatile("cp.async.wait_group 1;" ::: "memory")
#define CP_WAIT0()       asm volatile("cp.async.wait_group 0;" ::: "memory")

// =================================================================================
// converts
// =================================================================================
struct Conv3Args { const float* src[3]; __half* dst[3]; };

__global__ void conv3_kernel(Conv3Args a, int n)
{
    const float* x = a.src[blockIdx.z];
    __half* o = a.dst[blockIdx.z];
    int idx = (blockIdx.x * blockDim.x + threadIdx.x) * 4;
    if (idx >= n) return;
    float4 v = *(const float4*)(x + idx);
    *(__half2*)(o + idx)     = __floats2half2_rn(v.x, v.y);
    *(__half2*)(o + idx + 2) = __floats2half2_rn(v.z, v.w);
}

__global__ void conv1_kernel(const float* __restrict__ x, __half* __restrict__ o, int n)
{
    int idx = (blockIdx.x * blockDim.x + threadIdx.x) * 4;
    if (idx >= n) return;
    float4 v = *(const float4*)(x + idx);
    *(__half2*)(o + idx)     = __floats2half2_rn(v.x, v.y);
    *(__half2*)(o + idx + 2) = __floats2half2_rn(v.z, v.w);
}

// V transpose: V16 [b*S+s][h*64+d] -> VT [(b*16+h)*64+d][S]
__global__ void vtrans_kernel(const __half* __restrict__ V, __half* __restrict__ VT)
{
    __shared__ __half t[32][33];
    const int s0 = blockIdx.x * 32;
    const int d0 = blockIdx.y * 32;
    const int bh = blockIdx.z;
    const int b = bh >> 4, h = bh & 15;
    const int tid = threadIdx.x;
    const int cx = tid & 31, cy = tid >> 5;

#pragma unroll
    for (int i = 0; i < 4; i++) {
        int s = s0 + cy + i * 8;
        t[cy + i * 8][cx] = V[(size_t)(b * SEQ + s) * D_MODEL + h * 64 + d0 + cx];
    }
    __syncthreads();
#pragma unroll
    for (int i = 0; i < 4; i++) {
        int d = d0 + cy + i * 8;
        VT[(size_t)(bh * 64 + d) * SEQ + s0 + cx] = t[cx][cy + i * 8];
    }
}

// =================================================================================
// 16-warp mma.sync GEMM core: 128x128 CTA, BK=32, NA A-terms x 1 B-term, 3-stage ring.
// =================================================================================
#define G_ROWB     80
#define G_TILE_B   (128 * G_ROWB)        // 10240

template<int NA>   // A-operand terms: 1 or 2. Tiles per stage = NA+1.
__device__ __forceinline__ void gemm16_mainloop(
    uint32_t sb, int tid, int lane, int wid,
    const __half* __restrict__ A0, const __half* __restrict__ A1,
    const __half* __restrict__ B0,
    int row0, int col0, float acc[2][4][4])
{
    constexpr int NT = NA + 1;
    constexpr int STAGE_B = NT * G_TILE_B;
    const int warp_m = wid >> 2, warp_n = wid & 3;
    const int la = lane & 7, lb8 = (lane >> 3) & 1, lb16 = lane >> 4;
    const uint32_t a_off = (uint32_t)((la + lb8 * 8) * G_ROWB + lb16 * 16);
    const uint32_t b_off = (uint32_t)((la + lb16 * 8) * G_ROWB + lb8 * 16);

    const __half* srcs[3];
    srcs[0] = A0 + (size_t)row0 * 1024;
    srcs[1] = (NA == 2) ? A1 + (size_t)row0 * 1024 : B0 + (size_t)col0 * 1024;
    srcs[2] = B0 + (size_t)col0 * 1024;

    const int lt = tid >> 7;
    const int lr = tid & 127;

    auto load_stage = [&](int st, int k0) {
        if (lt < NT) {
            const uint32_t s = sb + st * STAGE_B + lt * G_TILE_B + (uint32_t)lr * G_ROWB;
            const __half* g = srcs[lt] + (size_t)lr * 1024 + k0;
#pragma unroll
            for (int ch = 0; ch < 4; ch++)
                CP_ASYNC16(s + ch * 16, (const void*)(g + ch * 8));
        }
    };

    auto compute_stage = [&](int st) {
        const uint32_t s   = sb + st * STAGE_B;
        const uint32_t aH  = s + 0 * G_TILE_B + (uint32_t)(warp_m * 32) * G_ROWB;
        const uint32_t aL  = s + 1 * G_TILE_B + (uint32_t)(warp_m * 32) * G_ROWB;
        const uint32_t bT  = s + NA * G_TILE_B + (uint32_t)(warp_n * 32) * G_ROWB;
#pragma unroll
        for (int ks = 0; ks < 2; ks++) {
            uint32_t ah[2][4], al[2][4], bb[2][4];
#pragma unroll
            for (int mt = 0; mt < 2; mt++) {
                ldsm4(ah[mt], aH + (uint32_t)(mt * 16) * G_ROWB + ks * 32 + a_off);
                if (NA == 2) ldsm4(al[mt], aL + (uint32_t)(mt * 16) * G_ROWB + ks * 32 + a_off);
            }
#pragma unroll
            for (int p = 0; p < 2; p++)
                ldsm4(bb[p], bT + (uint32_t)(p * 16) * G_ROWB + ks * 32 + b_off);
#pragma unroll
            for (int mt = 0; mt < 2; mt++)
#pragma unroll
                for (int nt = 0; nt < 4; nt++) {
                    float* c = acc[mt][nt];
                    const uint32_t* bp = &bb[nt >> 1][(nt & 1) * 2];
                    mma_f16(c, ah[mt], bp);
                    if (NA == 2) mma_f16(c, al[mt], bp);
                }
        }
    };

    load_stage(0, 0);  CP_COMMIT();
    load_stage(1, 32); CP_COMMIT();
    for (int c = 0; c < 32; c++) {
        CP_WAIT1();
        __syncthreads();
        compute_stage(c % 3);
        if (c + 2 < 32) load_stage((c + 2) % 3, (c + 2) * 32);
        CP_COMMIT();
    }
}

// ---- fused QKV projection: X fp16 x W fp16 (1 product); fp16 output (scaled) ----
struct ProjOne {
    const __half *A, *W;
    const float* bias;
    __half *O;
    float scale;
};
struct Proj3Args { ProjOne p[3]; };

__global__ __launch_bounds__(512)
void proj3_kernel(Proj3Args args)
{
    extern __shared__ __align__(128) char smem[];
    const ProjOne P = args.p[blockIdx.z];
    const uint32_t sb = smem_u32(smem);
    const int tid = threadIdx.x, lane = tid & 31, wid = tid >> 5;
    const int row0 = blockIdx.y * 128, col0 = blockIdx.x * 128;

    float acc[2][4][4];
#pragma unroll
    for (int a = 0; a < 2; a++)
#pragma unroll
        for (int b = 0; b < 4; b++)
#pragma unroll
            for (int c = 0; c < 4; c++) acc[a][b][c] = 0.f;

    gemm16_mainloop<1>(sb, tid, lane, wid, P.A, nullptr, P.W, row0, col0, acc);

    const int warp_m = wid >> 2, warp_n = wid & 3;
    const int r_base = row0 + warp_m * 32, c_base = col0 + warp_n * 32;
#pragma unroll
    for (int mt = 0; mt < 2; mt++) {
        const int r = r_base + mt * 16 + (lane >> 2);
#pragma unroll
        for (int nt = 0; nt < 4; nt++) {
            const int cc = c_base + nt * 8 + (lane & 3) * 2;
            const float b0 = __ldg(P.bias + cc), b1 = __ldg(P.bias + cc + 1);
            *(__half2*)(P.O + (size_t)r * 1024 + cc) =
                __floats2half2_rn((acc[mt][nt][0] + b0) * P.scale,
                                  (acc[mt][nt][1] + b1) * P.scale);
            *(__half2*)(P.O + (size_t)(r + 8) * 1024 + cc) =
                __floats2half2_rn((acc[mt][nt][2] + b0) * P.scale,
                                  (acc[mt][nt][3] + b1) * P.scale);
        }
    }
}

// ---- output projection: C 2-term x W 1-term (2 products), fp32 out ----
__global__ __launch_bounds__(512)
void gemmF_kernel(const __half* __restrict__ Ch, const __half* __restrict__ Cl,
                  const __half* __restrict__ W,
                  const float* __restrict__ bias, float* __restrict__ C)
{
    extern __shared__ __align__(128) char smem[];
    const uint32_t sb = smem_u32(smem);
    const int tid = threadIdx.x, lane = tid & 31, wid = tid >> 5;
    const int row0 = blockIdx.y * 128, col0 = blockIdx.x * 128;

    float acc[2][4][4];
#pragma unroll
    for (int a = 0; a < 2; a++)
#pragma unroll
        for (int b = 0; b < 4; b++)
#pragma unroll
            for (int c = 0; c < 4; c++) acc[a][b][c] = 0.f;

    gemm16_mainloop<2>(sb, tid, lane, wid, Ch, Cl, W, row0, col0, acc);

    const int warp_m = wid >> 2, warp_n = wid & 3;
    const int r_base = row0 + warp_m * 32, c_base = col0 + warp_n * 32;
#pragma unroll
    for (int mt = 0; mt < 2; mt++) {
        const int r = r_base + mt * 16 + (lane >> 2);
#pragma unroll
        for (int nt = 0; nt < 4; nt++) {
            const int cc = c_base + nt * 8 + (lane & 3) * 2;
            const float b0 = __ldg(bias + cc), b1 = __ldg(bias + cc + 1);
            float2 o0, o1;
            o0.x = acc[mt][nt][0] + b0; o0.y = acc[mt][nt][1] + b1;
            o1.x = acc[mt][nt][2] + b0; o1.y = acc[mt][nt][3] + b1;
            *(float2*)(C + (size_t)r * 1024 + cc)       = o0;
            *(float2*)(C + (size_t)(r + 8) * 1024 + cc) = o1;
        }
    }
}

// =================================================================================
// Flash attention: pure fp16 operands, fp32 accum. 16 warps, 256 q-rows/CTA.
// KV stage = [K | Vt], 3-stage ring. Out: CH/CL hi/lo.
// =================================================================================
#define A_STRIDE_B 144
#define A_TILE_B   (64 * A_STRIDE_B)    // 9216
#define A_STAGE_B  (2 * A_TILE_B)       // 18432 (K|Vt)
#define A_SMEM_TOT (6 * A_TILE_B)       // 55296

__global__ __launch_bounds__(512)
void attention_mma_kernel(const __half* __restrict__ Q16,
                          const __half* __restrict__ K16, const __half* __restrict__ VT,
                          __half* __restrict__ CH, __half* __restrict__ CL)
{
    extern __shared__ __align__(128) char smem[];
    const uint32_t sb = smem_u32(smem);
    const int tid  = threadIdx.x;
    const int lane = tid & 31, wid = tid >> 5;
    const int bh = blockIdx.y;
    const int b = bh >> 4, h = bh & 15;
    const int q0 = blockIdx.x * 256;

    const int la   = lane & 7;
    const int lb8  = (lane >> 3) & 1;
    const int lb16 = lane >> 4;
    const uint32_t a_off = (uint32_t)((la + lb8 * 8) * A_STRIDE_B + lb16 * 16);
    const uint32_t b_off = (uint32_t)((la + lb16 * 8) * A_STRIDE_B + lb8 * 16);

    // ---- stage Q and move to registers ----
    {
#pragma unroll
        for (int i = 0; i < 4; i++) {
            int c = tid + i * 512;
            int r = c >> 3, ch = c & 7;
            const size_t g = (size_t)(b * SEQ + q0 + r) * D_MODEL + h * 64 + ch * 8;
            CP_ASYNC16(sb + r * A_STRIDE_B + ch * 16, (const void*)(Q16 + g));
        }
        CP_COMMIT();
        CP_WAIT0();
        __syncthreads();
    }
    uint32_t qh[4][4];
#pragma unroll
    for (int ks = 0; ks < 4; ks++)
        ldsm4(qh[ks], sb + (uint32_t)(wid * 16) * A_STRIDE_B + ks * 32 + a_off);
    __syncthreads();

    // ---- KV loader ----
    const int lt = tid >> 8;
    const int lr = (tid & 255) >> 2;
    const int lq = tid & 3;
    auto load_stage = [&](int st, int kv0) {
        const uint32_t s = sb + st * A_STAGE_B + lt * A_TILE_B
                         + (uint32_t)lr * A_STRIDE_B + lq * 32;
        const __half* g = (lt == 0)
            ? K16 + (size_t)(b * SEQ + kv0 + lr) * D_MODEL + h * 64 + lq * 16
            : VT  + (size_t)(bh * 64 + lr) * SEQ + kv0 + lq * 16;
        CP_ASYNC16(s,      (const void*)g);
        CP_ASYNC16(s + 16, (const void*)(g + 8));
    };

    load_stage(0, 0);  CP_COMMIT();
    load_stage(1, 64); CP_COMMIT();

    float o[8][4];
#pragma unroll
    for (int t = 0; t < 8; t++)
#pragma unroll
        for (int j = 0; j < 4; j++) o[t][j] = 0.f;
    float m_r[2] = {-1e30f, -1e30f};
    float l_r[2] = {0.f, 0.f};

    for (int it = 0; it < 32; it++) {
        CP_WAIT1();
        __syncthreads();
        const uint32_t st = sb + (it % 3) * A_STAGE_B;

        // ---- S = Q K^T ----
        float s[8][4];
#pragma unroll
        for (int t = 0; t < 8; t++)
#pragma unroll
            for (int j = 0; j < 4; j++) s[t][j] = 0.f;
#pragma unroll
        for (int ks = 0; ks < 4; ks++) {
#pragma unroll
            for (int np = 0; np < 4; np++) {
                uint32_t k4[4];
                const uint32_t base = (uint32_t)(np * 16) * A_STRIDE_B + ks * 32 + b_off;
                ldsm4(k4, st + base);
                mma_f16(s[2 * np],     qh[ks], k4);
                mma_f16(s[2 * np + 1], qh[ks], k4 + 2);
            }
        }

        // ---- online softmax ----
#pragma unroll
        for (int r = 0; r < 2; r++) {
            float mx = s[0][2 * r];
#pragma unroll
            for (int t = 0; t < 8; t++) {
                mx = fmaxf(mx, s[t][2 * r]);
                mx = fmaxf(mx, s[t][2 * r + 1]);
            }
            mx = fmaxf(mx, __shfl_xor_sync(0xffffffffu, mx, 1));
            mx = fmaxf(mx, __shfl_xor_sync(0xffffffffu, mx, 2));
            float mn = fmaxf(m_r[r], mx);
            float al = __expf(m_r[r] - mn);
            m_r[r] = mn;
            float sum = 0.f;
#pragma unroll
            for (int t = 0; t < 8; t++) {
                float p0 = __expf(s[t][2 * r]     - mn);
                float p1 = __expf(s[t][2 * r + 1] - mn);
                s[t][2 * r] = p0; s[t][2 * r + 1] = p1;
                sum += p0 + p1;
            }
            sum += __shfl_xor_sync(0xffffffffu, sum, 1);
            sum += __shfl_xor_sync(0xffffffffu, sum, 2);
            l_r[r] = l_r[r] * al + sum;
#pragma unroll
            for (int t = 0; t < 8; t++) {
                o[t][2 * r] *= al; o[t][2 * r + 1] *= al;
            }
        }

        // ---- O += P V ----
#pragma unroll
        for (int ks = 0; ks < 4; ks++) {
            const int t0 = 2 * ks, t1 = 2 * ks + 1;
            uint32_t pa[4];
            pa[0] = pack_h(s[t0][0], s[t0][1]);
            pa[1] = pack_h(s[t0][2], s[t0][3]);
            pa[2] = pack_h(s[t1][0], s[t1][1]);
            pa[3] = pack_h(s[t1][2], s[t1][3]);
#pragma unroll
            for (int np = 0; np < 4; np++) {
                uint32_t v4[4];
                const uint32_t base = (uint32_t)(np * 16) * A_STRIDE_B + ks * 32 + b_off;
                ldsm4(v4, st + A_TILE_B + base);
                mma_f16(o[2 * np],     pa, v4);
                mma_f16(o[2 * np + 1], pa, v4 + 2);
            }
        }

        if (it + 2 < 32) load_stage((it + 2) % 3, (it + 2) * 64);
        CP_COMMIT();
    }

    // ---- epilogue: context hi/lo ----
    const float inv0 = 1.f / l_r[0];
    const float inv1 = 1.f / l_r[1];
    const int row0 = q0 + wid * 16 + (lane >> 2);
#pragma unroll
    for (int t = 0; t < 8; t++) {
        const int col = h * 64 + t * 8 + (lane & 3) * 2;
        store_hilo(CH, CL, (size_t)(b * SEQ + row0) * D_MODEL + col,
                   o[t][0] * inv0, o[t][1] * inv0);
        store_hilo(CH, CL, (size_t)(b * SEQ + row0 + 8) * D_MODEL + col,
                   o[t][2] * inv1, o[t][3] * inv1);
    }
}

// =================================================================================
// launch
// =================================================================================
extern "C" void kernel_launch(void* const* d_in, const int* in_sizes, int n_in,
                              void* d_out, int out_size)
{
    const float* x_q = (const float*)d_in[0];
    const float* x_k = (const float*)d_in[1];
    const float* x_v = (const float*)d_in[2];
    const float* wq  = (const float*)d_in[3];
    const float* bq  = (const float*)d_in[4];
    const float* wk  = (const float*)d_in[5];
    const float* bk  = (const float*)d_in[6];
    const float* wv  = (const float*)d_in[7];
    const float* bv  = (const float*)d_in[8];
    const float* wo  = (const float*)d_in[9];
    const float* bo  = (const float*)d_in[10];
    float* out = (float*)d_out;

    __half *x0, *x1, *x2, *q16, *k16, *v16, *vt, *ch, *cl;
    __half *w0, *w1, *w2, *w3;
    cudaGetSymbolAddress((void**)&x0,  g_X0);
    cudaGetSymbolAddress((void**)&x1,  g_X1);
    cudaGetSymbolAddress((void**)&x2,  g_X2);
    cudaGetSymbolAddress((void**)&q16, g_Q16);
    cudaGetSymbolAddress((void**)&k16, g_K16);
    cudaGetSymbolAddress((void**)&v16, g_V16);
    cudaGetSymbolAddress((void**)&vt,  g_VT);
    cudaGetSymbolAddress((void**)&ch,  g_CH);
    cudaGetSymbolAddress((void**)&cl,  g_CL);
    cudaGetSymbolAddress((void**)&w0,  g_W0);
    cudaGetSymbolAddress((void**)&w1,  g_W1);
    cudaGetSymbolAddress((void**)&w2,  g_W2);
    cudaGetSymbolAddress((void**)&w3,  g_W3);

    static int attr_set = 0;
    const int proj_smem = 3 * 2 * G_TILE_B;   // 61440
    const int gemf_smem = 3 * 3 * G_TILE_B;   // 92160
    if (!attr_set) {
        cudaFuncSetAttribute(proj3_kernel,
                             cudaFuncAttributeMaxDynamicSharedMemorySize, proj_smem);
        cudaFuncSetAttribute(gemmF_kernel,
                             cudaFuncAttributeMaxDynamicSharedMemorySize, gemf_smem);
        cudaFuncSetAttribute(attention_mma_kernel,
                             cudaFuncAttributeMaxDynamicSharedMemorySize, A_SMEM_TOT);
        attr_set = 1;
    }

    const int NX = M_TOT * D_MODEL;
    const int NW = D_MODEL * D_MODEL;
    dim3 cb(256);

    // converts (fused 3-way)
    {
        Conv3Args cx; cx.src[0] = x_q; cx.src[1] = x_k; cx.src[2] = x_v;
        cx.dst[0] = x0; cx.dst[1] = x1; cx.dst[2] = x2;
        conv3_kernel<<<dim3((NX / 4 + 255) / 256, 1, 3), cb>>>(cx, NX);
        Conv3Args cw; cw.src[0] = wq; cw.src[1] = wk; cw.src[2] = wv;
        cw.dst[0] = w0; cw.dst[1] = w1; cw.dst[2] = w2;
        conv3_kernel<<<dim3((NW / 4 + 255) / 256, 1, 3), cb>>>(cw, NW);
        conv1_kernel<<<(NW / 4 + 255) / 256, cb>>>(wo, w3, NW);
    }

    // fused QKV projections (fp16 1-term; Q pre-scaled)
    Proj3Args pa;
    pa.p[0] = { x0, w0, bq, q16, 0.125f };
    pa.p[1] = { x1, w1, bk, k16, 1.0f };
    pa.p[2] = { x2, w2, bv, v16, 1.0f };
    proj3_kernel<<<dim3(8, 64, 3), 512, proj_smem>>>(pa);

    // V transpose
    vtrans_kernel<<<dim3(SEQ / 32, 2, BATCH * NHEAD), 256>>>(v16, vt);

    // attention (pure fp16, context hi/lo out)
    attention_mma_kernel<<<dim3(SEQ / 256, BATCH * NHEAD), 512, A_SMEM_TOT>>>(
        q16, k16, vt, ch, cl);

    // output projection (C hi/lo x W, 2 products)
    gemmF_kernel<<<dim3(8, 64), 512, gemf_smem>>>(ch, cl, w3, bo, out);
}

// round 9
// speedup vs baseline: 5.8436x; 1.0902x over previous
#include <cuda_runtime.h>
#include <cuda_fp16.h>
#include <math.h>
#include <cstdint>

#define D_MODEL 1024
#define NHEAD   16
#define D_K     64
#define BATCH   4
#define SEQ     2048
#define M_TOT   (BATCH * SEQ)   // 8192

// ---------------- scratch (device globals: allocation-free rule) ----------------
__device__ __half g_X0 [M_TOT * D_MODEL];
__device__ __half g_X1 [M_TOT * D_MODEL];
__device__ __half g_X2 [M_TOT * D_MODEL];
__device__ __half g_Q16[M_TOT * D_MODEL];
__device__ __half g_K16[M_TOT * D_MODEL];
__device__ __half g_V16[M_TOT * D_MODEL];
__device__ __half g_VT [M_TOT * D_MODEL];
__device__ __half g_CH [M_TOT * D_MODEL];
__device__ __half g_CL [M_TOT * D_MODEL];
__device__ __half g_W0 [D_MODEL * D_MODEL];
__device__ __half g_W1 [D_MODEL * D_MODEL];
__device__ __half g_W2 [D_MODEL * D_MODEL];
__device__ __half g_W3 [D_MODEL * D_MODEL];

// ====================== helpers ======================
__device__ __forceinline__ uint32_t smem_u32(const void* p) {
    uint32_t a;
    asm("{ .reg .u64 t; cvta.to.shared.u64 t, %1; cvt.u32.u64 %0, t; }" : "=r"(a) : "l"(p));
    return a;
}
__device__ __forceinline__ void ldsm4(uint32_t* r, uint32_t addr) {
    asm volatile("ldmatrix.sync.aligned.m8n8.x4.shared.b16 {%0,%1,%2,%3}, [%4];"
        : "=r"(r[0]), "=r"(r[1]), "=r"(r[2]), "=r"(r[3]) : "r"(addr));
}
__device__ __forceinline__ void mma_f16(float* c, const uint32_t* a, const uint32_t* b) {
    asm volatile("mma.sync.aligned.m16n8k16.row.col.f32.f16.f16.f32 "
        "{%0,%1,%2,%3}, {%4,%5,%6,%7}, {%8,%9}, {%0,%1,%2,%3};"
        : "+f"(c[0]), "+f"(c[1]), "+f"(c[2]), "+f"(c[3])
        : "r"(a[0]), "r"(a[1]), "r"(a[2]), "r"(a[3]), "r"(b[0]), "r"(b[1]));
}
__device__ __forceinline__ uint32_t pack_h(float x, float y) {
    __half2 h = __floats2half2_rn(x, y);
    return *(uint32_t*)&h;
}
__device__ __forceinline__ void store_hilo(__half* H, __half* L, size_t off, float x, float y) {
    __half hx = __float2half_rn(x), hy = __float2half_rn(y);
    __half lx = __float2half_rn(x - __half2float(hx));
    __half ly = __float2half_rn(y - __half2float(hy));
    *(__half2*)(H + off) = __halves2half2(hx, hy);
    *(__half2*)(L + off) = __halves2half2(lx, ly);
}
#define CP_ASYNC16(s, g) asm volatile("cp.async.cg.shared.global [%0], [%1], 16;" :: "r"(s), "l"(g) : "memory")
#define CP_COMMIT()      asm volatile("cp.async.commit_group;" ::: "memory")
#define CP_WAIT1()       asm volatile("cp.async.wait_group 1;" ::: "memory")
#define CP_WAIT0()       asm volatile("cp.async.wait_group 0;" ::: "memory")

// =================================================================================
// converts
// =================================================================================
struct Conv3Args { const float* src[3]; __half* dst[3]; };

__global__ void conv3_kernel(Conv3Args a, int n)
{
    const float* x = a.src[blockIdx.z];
    __half* o = a.dst[blockIdx.z];
    int idx = (blockIdx.x * blockDim.x + threadIdx.x) * 4;
    if (idx >= n) return;
    float4 v = *(const float4*)(x + idx);
    *(__half2*)(o + idx)     = __floats2half2_rn(v.x, v.y);
    *(__half2*)(o + idx + 2) = __floats2half2_rn(v.z, v.w);
}

__global__ void conv1_kernel(const float* __restrict__ x, __half* __restrict__ o, int n)
{
    int idx = (blockIdx.x * blockDim.x + threadIdx.x) * 4;
    if (idx >= n) return;
    float4 v = *(const float4*)(x + idx);
    *(__half2*)(o + idx)     = __floats2half2_rn(v.x, v.y);
    *(__half2*)(o + idx + 2) = __floats2half2_rn(v.z, v.w);
}

// V transpose: V16 [b*S+s][h*64+d] -> VT [(b*16+h)*64+d][S]
__global__ void vtrans_kernel(const __half* __restrict__ V, __half* __restrict__ VT)
{
    __shared__ __half t[32][33];
    const int s0 = blockIdx.x * 32;
    const int d0 = blockIdx.y * 32;
    const int bh = blockIdx.z;
    const int b = bh >> 4, h = bh & 15;
    const int tid = threadIdx.x;
    const int cx = tid & 31, cy = tid >> 5;

#pragma unroll
    for (int i = 0; i < 4; i++) {
        int s = s0 + cy + i * 8;
        t[cy + i * 8][cx] = V[(size_t)(b * SEQ + s) * D_MODEL + h * 64 + d0 + cx];
    }
    __syncthreads();
#pragma unroll
    for (int i = 0; i < 4; i++) {
        int d = d0 + cy + i * 8;
        VT[(size_t)(bh * 64 + d) * SEQ + s0 + cx] = t[cx][cy + i * 8];
    }
}

// =================================================================================
// 8-warp mma.sync GEMM core: CTA 128x128, BK=64, warp tile 64x32 (warp grid 2x4).
// NA A-terms x 1 B-term; 3-stage cp.async ring, one __syncthreads per chunk.
// Ratio: 6 ldsm4 -> 16 HMMA per ks (vs 8->16 in the 32x32 design).
// =================================================================================
#define G_ROWB     144                   // bytes per smem row (64 fp16 + 8 pad)
#define G_TILE_B   (128 * G_ROWB)        // 18432

template<int NA>   // A-operand terms: 1 or 2. Tiles per stage = NA+1.
__device__ __forceinline__ void gemm8_mainloop(
    uint32_t sb, int tid, int lane, int wid,
    const __half* __restrict__ A0, const __half* __restrict__ A1,
    const __half* __restrict__ B0,
    int row0, int col0, float acc[4][4][4])
{
    constexpr int NT = NA + 1;
    constexpr int STAGE_B = NT * G_TILE_B;
    const int warp_m = wid >> 2;         // 0..1  (64 rows)
    const int warp_n = wid & 3;          // 0..3  (32 cols)
    const int la = lane & 7, lb8 = (lane >> 3) & 1, lb16 = lane >> 4;
    const uint32_t a_off = (uint32_t)((la + lb8 * 8) * G_ROWB + lb16 * 16);
    const uint32_t b_off = (uint32_t)((la + lb16 * 8) * G_ROWB + lb8 * 16);

    const __half* srcs[3];
    srcs[0] = A0 + (size_t)row0 * 1024;
    srcs[1] = (NA == 2) ? A1 + (size_t)row0 * 1024 : B0 + (size_t)col0 * 1024;
    srcs[2] = B0 + (size_t)col0 * 1024;

    const int lr = tid >> 1;     // row 0..127
    const int hf = tid & 1;      // half-row 0..1 (64B each)

    auto load_stage = [&](int st, int k0) {
#pragma unroll
        for (int t = 0; t < NT; t++) {
            const uint32_t s = sb + st * STAGE_B + t * G_TILE_B
                             + (uint32_t)lr * G_ROWB + hf * 64;
            const __half* g = srcs[t] + (size_t)lr * 1024 + k0 + hf * 32;
#pragma unroll
            for (int ch = 0; ch < 4; ch++)
                CP_ASYNC16(s + ch * 16, (const void*)(g + ch * 8));
        }
    };

    auto compute_stage = [&](int st) {
        const uint32_t s   = sb + st * STAGE_B;
        const uint32_t aB0 = s + (uint32_t)(warp_m * 64) * G_ROWB;
        const uint32_t aB1 = s + G_TILE_B + (uint32_t)(warp_m * 64) * G_ROWB;
        const uint32_t bB  = s + NA * G_TILE_B + (uint32_t)(warp_n * 32) * G_ROWB;
#pragma unroll
        for (int ks = 0; ks < 4; ks++) {
            uint32_t ah[4][4], al[4][4], bb[2][4];
#pragma unroll
            for (int mt = 0; mt < 4; mt++) {
                ldsm4(ah[mt], aB0 + (uint32_t)(mt * 16) * G_ROWB + ks * 32 + a_off);
                if (NA == 2)
                    ldsm4(al[mt], aB1 + (uint32_t)(mt * 16) * G_ROWB + ks * 32 + a_off);
            }
#pragma unroll
            for (int p = 0; p < 2; p++)
                ldsm4(bb[p], bB + (uint32_t)(p * 16) * G_ROWB + ks * 32 + b_off);
#pragma unroll
            for (int mt = 0; mt < 4; mt++)
#pragma unroll
                for (int nt = 0; nt < 4; nt++) {
                    float* c = acc[mt][nt];
                    const uint32_t* bp = &bb[nt >> 1][(nt & 1) * 2];
                    mma_f16(c, ah[mt], bp);
                    if (NA == 2) mma_f16(c, al[mt], bp);
                }
        }
    };

    load_stage(0, 0);   CP_COMMIT();
    load_stage(1, 64);  CP_COMMIT();
    for (int c = 0; c < 16; c++) {       // 16 chunks of BK=64
        CP_WAIT1();
        __syncthreads();
        compute_stage(c % 3);
        if (c + 2 < 16) load_stage((c + 2) % 3, (c + 2) * 64);
        CP_COMMIT();
    }
}

// ---- fused QKV projection: X fp16 x W fp16 (1 product); fp16 output (scaled) ----
struct ProjOne {
    const __half *A, *W;
    const float* bias;
    __half *O;
    float scale;
};
struct Proj3Args { ProjOne p[3]; };

__global__ __launch_bounds__(256, 2)
void proj3_kernel(Proj3Args args)
{
    extern __shared__ __align__(128) char smem[];
    const ProjOne P = args.p[blockIdx.z];
    const uint32_t sb = smem_u32(smem);
    const int tid = threadIdx.x, lane = tid & 31, wid = tid >> 5;
    const int row0 = blockIdx.y * 128, col0 = blockIdx.x * 128;

    float acc[4][4][4];
#pragma unroll
    for (int a = 0; a < 4; a++)
#pragma unroll
        for (int b = 0; b < 4; b++)
#pragma unroll
            for (int c = 0; c < 4; c++) acc[a][b][c] = 0.f;

    gemm8_mainloop<1>(sb, tid, lane, wid, P.A, nullptr, P.W, row0, col0, acc);

    const int warp_m = wid >> 2, warp_n = wid & 3;
    const int r_base = row0 + warp_m * 64, c_base = col0 + warp_n * 32;
#pragma unroll
    for (int mt = 0; mt < 4; mt++) {
        const int r = r_base + mt * 16 + (lane >> 2);
#pragma unroll
        for (int nt = 0; nt < 4; nt++) {
            const int cc = c_base + nt * 8 + (lane & 3) * 2;
            const float b0 = __ldg(P.bias + cc), b1 = __ldg(P.bias + cc + 1);
            *(__half2*)(P.O + (size_t)r * 1024 + cc) =
                __floats2half2_rn((acc[mt][nt][0] + b0) * P.scale,
                                  (acc[mt][nt][1] + b1) * P.scale);
            *(__half2*)(P.O + (size_t)(r + 8) * 1024 + cc) =
                __floats2half2_rn((acc[mt][nt][2] + b0) * P.scale,
                                  (acc[mt][nt][3] + b1) * P.scale);
        }
    }
}

// ---- output projection: C 2-term x W 1-term (2 products), fp32 out ----
__global__ __launch_bounds__(256)
void gemmF_kernel(const __half* __restrict__ Ch, const __half* __restrict__ Cl,
                  const __half* __restrict__ W,
                  const float* __restrict__ bias, float* __restrict__ C)
{
    extern __shared__ __align__(128) char smem[];
    const uint32_t sb = smem_u32(smem);
    const int tid = threadIdx.x, lane = tid & 31, wid = tid >> 5;
    const int row0 = blockIdx.y * 128, col0 = blockIdx.x * 128;

    float acc[4][4][4];
#pragma unroll
    for (int a = 0; a < 4; a++)
#pragma unroll
        for (int b = 0; b < 4; b++)
#pragma unroll
            for (int c = 0; c < 4; c++) acc[a][b][c] = 0.f;

    gemm8_mainloop<2>(sb, tid, lane, wid, Ch, Cl, W, row0, col0, acc);

    const int warp_m = wid >> 2, warp_n = wid & 3;
    const int r_base = row0 + warp_m * 64, c_base = col0 + warp_n * 32;
#pragma unroll
    for (int mt = 0; mt < 4; mt++) {
        const int r = r_base + mt * 16 + (lane >> 2);
#pragma unroll
        for (int nt = 0; nt < 4; nt++) {
            const int cc = c_base + nt * 8 + (lane & 3) * 2;
            const float b0 = __ldg(bias + cc), b1 = __ldg(bias + cc + 1);
            float2 o0, o1;
            o0.x = acc[mt][nt][0] + b0; o0.y = acc[mt][nt][1] + b1;
            o1.x = acc[mt][nt][2] + b0; o1.y = acc[mt][nt][3] + b1;
            *(float2*)(C + (size_t)r * 1024 + cc)       = o0;
            *(float2*)(C + (size_t)(r + 8) * 1024 + cc) = o1;
        }
    }
}

// =================================================================================
// Flash attention: pure fp16 operands, fp32 accum. 16 warps, 256 q-rows/CTA.
// KV stage = [K | Vt], 3-stage ring. Out: CH/CL hi/lo. (unchanged from R8)
// =================================================================================
#define A_STRIDE_B 144
#define A_TILE_B   (64 * A_STRIDE_B)    // 9216
#define A_STAGE_B  (2 * A_TILE_B)       // 18432 (K|Vt)
#define A_SMEM_TOT (6 * A_TILE_B)       // 55296

__global__ __launch_bounds__(512)
void attention_mma_kernel(const __half* __restrict__ Q16,
                          const __half* __restrict__ K16, const __half* __restrict__ VT,
                          __half* __restrict__ CH, __half* __restrict__ CL)
{
    extern __shared__ __align__(128) char smem[];
    const uint32_t sb = smem_u32(smem);
    const int tid  = threadIdx.x;
    const int lane = tid & 31, wid = tid >> 5;
    const int bh = blockIdx.y;
    const int b = bh >> 4, h = bh & 15;
    const int q0 = blockIdx.x * 256;

    const int la   = lane & 7;
    const int lb8  = (lane >> 3) & 1;
    const int lb16 = lane >> 4;
    const uint32_t a_off = (uint32_t)((la + lb8 * 8) * A_STRIDE_B + lb16 * 16);
    const uint32_t b_off = (uint32_t)((la + lb16 * 8) * A_STRIDE_B + lb8 * 16);

    // ---- stage Q and move to registers ----
    {
#pragma unroll
        for (int i = 0; i < 4; i++) {
            int c = tid + i * 512;
            int r = c >> 3, ch = c & 7;
            const size_t g = (size_t)(b * SEQ + q0 + r) * D_MODEL + h * 64 + ch * 8;
            CP_ASYNC16(sb + r * A_STRIDE_B + ch * 16, (const void*)(Q16 + g));
        }
        CP_COMMIT();
        CP_WAIT0();
        __syncthreads();
    }
    uint32_t qh[4][4];
#pragma unroll
    for (int ks = 0; ks < 4; ks++)
        ldsm4(qh[ks], sb + (uint32_t)(wid * 16) * A_STRIDE_B + ks * 32 + a_off);
    __syncthreads();

    // ---- KV loader ----
    const int lt = tid >> 8;
    const int lr = (tid & 255) >> 2;
    const int lq = tid & 3;
    auto load_stage = [&](int st, int kv0) {
        const uint32_t s = sb + st * A_STAGE_B + lt * A_TILE_B
                         + (uint32_t)lr * A_STRIDE_B + lq * 32;
        const __half* g = (lt == 0)
            ? K16 + (size_t)(b * SEQ + kv0 + lr) * D_MODEL + h * 64 + lq * 16
            : VT  + (size_t)(bh * 64 + lr) * SEQ + kv0 + lq * 16;
        CP_ASYNC16(s,      (const void*)g);
        CP_ASYNC16(s + 16, (const void*)(g + 8));
    };

    load_stage(0, 0);  CP_COMMIT();
    load_stage(1, 64); CP_COMMIT();

    float o[8][4];
#pragma unroll
    for (int t = 0; t < 8; t++)
#pragma unroll
        for (int j = 0; j < 4; j++) o[t][j] = 0.f;
    float m_r[2] = {-1e30f, -1e30f};
    float l_r[2] = {0.f, 0.f};

    for (int it = 0; it < 32; it++) {
        CP_WAIT1();
        __syncthreads();
        const uint32_t st = sb + (it % 3) * A_STAGE_B;

        // ---- S = Q K^T ----
        float s[8][4];
#pragma unroll
        for (int t = 0; t < 8; t++)
#pragma unroll
            for (int j = 0; j < 4; j++) s[t][j] = 0.f;
#pragma unroll
        for (int ks = 0; ks < 4; ks++) {
#pragma unroll
            for (int np = 0; np < 4; np++) {
                uint32_t k4[4];
                const uint32_t base = (uint32_t)(np * 16) * A_STRIDE_B + ks * 32 + b_off;
                ldsm4(k4, st + base);
                mma_f16(s[2 * np],     qh[ks], k4);
                mma_f16(s[2 * np + 1], qh[ks], k4 + 2);
            }
        }

        // ---- online softmax ----
#pragma unroll
        for (int r = 0; r < 2; r++) {
            float mx = s[0][2 * r];
#pragma unroll
            for (int t = 0; t < 8; t++) {
                mx = fmaxf(mx, s[t][2 * r]);
                mx = fmaxf(mx, s[t][2 * r + 1]);
            }
            mx = fmaxf(mx, __shfl_xor_sync(0xffffffffu, mx, 1));
            mx = fmaxf(mx, __shfl_xor_sync(0xffffffffu, mx, 2));
            float mn = fmaxf(m_r[r], mx);
            float al = __expf(m_r[r] - mn);
            m_r[r] = mn;
            float sum = 0.f;
#pragma unroll
            for (int t = 0; t < 8; t++) {
                float p0 = __expf(s[t][2 * r]     - mn);
                float p1 = __expf(s[t][2 * r + 1] - mn);
                s[t][2 * r] = p0; s[t][2 * r + 1] = p1;
                sum += p0 + p1;
            }
            sum += __shfl_xor_sync(0xffffffffu, sum, 1);
            sum += __shfl_xor_sync(0xffffffffu, sum, 2);
            l_r[r] = l_r[r] * al + sum;
#pragma unroll
            for (int t = 0; t < 8; t++) {
                o[t][2 * r] *= al; o[t][2 * r + 1] *= al;
            }
        }

        // ---- O += P V ----
#pragma unroll
        for (int ks = 0; ks < 4; ks++) {
            const int t0 = 2 * ks, t1 = 2 * ks + 1;
            uint32_t pa[4];
            pa[0] = pack_h(s[t0][0], s[t0][1]);
            pa[1] = pack_h(s[t0][2], s[t0][3]);
            pa[2] = pack_h(s[t1][0], s[t1][1]);
            pa[3] = pack_h(s[t1][2], s[t1][3]);
#pragma unroll
            for (int np = 0; np < 4; np++) {
                uint32_t v4[4];
                const uint32_t base = (uint32_t)(np * 16) * A_STRIDE_B + ks * 32 + b_off;
                ldsm4(v4, st + A_TILE_B + base);
                mma_f16(o[2 * np],     pa, v4);
                mma_f16(o[2 * np + 1], pa, v4 + 2);
            }
        }

        if (it + 2 < 32) load_stage((it + 2) % 3, (it + 2) * 64);
        CP_COMMIT();
    }

    // ---- epilogue: context hi/lo ----
    const float inv0 = 1.f / l_r[0];
    const float inv1 = 1.f / l_r[1];
    const int row0 = q0 + wid * 16 + (lane >> 2);
#pragma unroll
    for (int t = 0; t < 8; t++) {
        const int col = h * 64 + t * 8 + (lane & 3) * 2;
        store_hilo(CH, CL, (size_t)(b * SEQ + row0) * D_MODEL + col,
                   o[t][0] * inv0, o[t][1] * inv0);
        store_hilo(CH, CL, (size_t)(b * SEQ + row0 + 8) * D_MODEL + col,
                   o[t][2] * inv1, o[t][3] * inv1);
    }
}

// =================================================================================
// launch
// =================================================================================
extern "C" void kernel_launch(void* const* d_in, const int* in_sizes, int n_in,
                              void* d_out, int out_size)
{
    const float* x_q = (const float*)d_in[0];
    const float* x_k = (const float*)d_in[1];
    const float* x_v = (const float*)d_in[2];
    const float* wq  = (const float*)d_in[3];
    const float* bq  = (const float*)d_in[4];
    const float* wk  = (const float*)d_in[5];
    const float* bk  = (const float*)d_in[6];
    const float* wv  = (const float*)d_in[7];
    const float* bv  = (const float*)d_in[8];
    const float* wo  = (const float*)d_in[9];
    const float* bo  = (const float*)d_in[10];
    float* out = (float*)d_out;

    __half *x0, *x1, *x2, *q16, *k16, *v16, *vt, *ch, *cl;
    __half *w0, *w1, *w2, *w3;
    cudaGetSymbolAddress((void**)&x0,  g_X0);
    cudaGetSymbolAddress((void**)&x1,  g_X1);
    cudaGetSymbolAddress((void**)&x2,  g_X2);
    cudaGetSymbolAddress((void**)&q16, g_Q16);
    cudaGetSymbolAddress((void**)&k16, g_K16);
    cudaGetSymbolAddress((void**)&v16, g_V16);
    cudaGetSymbolAddress((void**)&vt,  g_VT);
    cudaGetSymbolAddress((void**)&ch,  g_CH);
    cudaGetSymbolAddress((void**)&cl,  g_CL);
    cudaGetSymbolAddress((void**)&w0,  g_W0);
    cudaGetSymbolAddress((void**)&w1,  g_W1);
    cudaGetSymbolAddress((void**)&w2,  g_W2);
    cudaGetSymbolAddress((void**)&w3,  g_W3);

    static int attr_set = 0;
    const int proj_smem = 3 * 2 * G_TILE_B;   // 110592
    const int gemf_smem = 3 * 3 * G_TILE_B;   // 165888
    if (!attr_set) {
        cudaFuncSetAttribute(proj3_kernel,
                             cudaFuncAttributeMaxDynamicSharedMemorySize, proj_smem);
        cudaFuncSetAttribute(gemmF_kernel,
                             cudaFuncAttributeMaxDynamicSharedMemorySize, gemf_smem);
        cudaFuncSetAttribute(attention_mma_kernel,
                             cudaFuncAttributeMaxDynamicSharedMemorySize, A_SMEM_TOT);
        attr_set = 1;
    }

    const int NX = M_TOT * D_MODEL;
    const int NW = D_MODEL * D_MODEL;
    dim3 cb(256);

    // converts (fused 3-way)
    {
        Conv3Args cx; cx.src[0] = x_q; cx.src[1] = x_k; cx.src[2] = x_v;
        cx.dst[0] = x0; cx.dst[1] = x1; cx.dst[2] = x2;
        conv3_kernel<<<dim3((NX / 4 + 255) / 256, 1, 3), cb>>>(cx, NX);
        Conv3Args cw; cw.src[0] = wq; cw.src[1] = wk; cw.src[2] = wv;
        cw.dst[0] = w0; cw.dst[1] = w1; cw.dst[2] = w2;
        conv3_kernel<<<dim3((NW / 4 + 255) / 256, 1, 3), cb>>>(cw, NW);
        conv1_kernel<<<(NW / 4 + 255) / 256, cb>>>(wo, w3, NW);
    }

    // fused QKV projections (fp16 1-term; Q pre-scaled)
    Proj3Args pa;
    pa.p[0] = { x0, w0, bq, q16, 0.125f };
    pa.p[1] = { x1, w1, bk, k16, 1.0f };
    pa.p[2] = { x2, w2, bv, v16, 1.0f };
    proj3_kernel<<<dim3(8, 64, 3), 256, proj_smem>>>(pa);

    // V transpose
    vtrans_kernel<<<dim3(SEQ / 32, 2, BATCH * NHEAD), 256>>>(v16, vt);

    // attention (pure fp16, context hi/lo out)
    attention_mma_kernel<<<dim3(SEQ / 256, BATCH * NHEAD), 512, A_SMEM_TOT>>>(
        q16, k16, vt, ch, cl);

    // output projection (C hi/lo x W, 2 products)
    gemmF_kernel<<<dim3(8, 64), 256, gemf_smem>>>(ch, cl, w3, bo, out);
}

// round 10
// speedup vs baseline: 5.8657x; 1.0038x over previous
#include <cuda_runtime.h>
#include <cuda_fp16.h>
#include <math.h>
#include <cstdint>

#define D_MODEL 1024
#define NHEAD   16
#define D_K     64
#define BATCH   4
#define SEQ     2048
#define M_TOT   (BATCH * SEQ)   // 8192

// ---------------- scratch (device globals: allocation-free rule) ----------------
__device__ __half g_X0 [M_TOT * D_MODEL];
__device__ __half g_X1 [M_TOT * D_MODEL];
__device__ __half g_X2 [M_TOT * D_MODEL];
__device__ __half g_Q16[M_TOT * D_MODEL];
__device__ __half g_K16[M_TOT * D_MODEL];
__device__ __half g_V16[M_TOT * D_MODEL];
__device__ __half g_VT [M_TOT * D_MODEL];
__device__ __half g_CH [M_TOT * D_MODEL];
__device__ __half g_CL [M_TOT * D_MODEL];
__device__ __half g_W0 [D_MODEL * D_MODEL];
__device__ __half g_W1 [D_MODEL * D_MODEL];
__device__ __half g_W2 [D_MODEL * D_MODEL];
__device__ __half g_W3 [D_MODEL * D_MODEL];

// ====================== helpers ======================
__device__ __forceinline__ uint32_t smem_u32(const void* p) {
    uint32_t a;
    asm("{ .reg .u64 t; cvta.to.shared.u64 t, %1; cvt.u32.u64 %0, t; }" : "=r"(a) : "l"(p));
    return a;
}
__device__ __forceinline__ void ldsm4(uint32_t* r, uint32_t addr) {
    asm volatile("ldmatrix.sync.aligned.m8n8.x4.shared.b16 {%0,%1,%2,%3}, [%4];"
        : "=r"(r[0]), "=r"(r[1]), "=r"(r[2]), "=r"(r[3]) : "r"(addr));
}
__device__ __forceinline__ void mma_f16(float* c, const uint32_t* a, const uint32_t* b) {
    asm volatile("mma.sync.aligned.m16n8k16.row.col.f32.f16.f16.f32 "
        "{%0,%1,%2,%3}, {%4,%5,%6,%7}, {%8,%9}, {%0,%1,%2,%3};"
        : "+f"(c[0]), "+f"(c[1]), "+f"(c[2]), "+f"(c[3])
        : "r"(a[0]), "r"(a[1]), "r"(a[2]), "r"(a[3]), "r"(b[0]), "r"(b[1]));
}
__device__ __forceinline__ uint32_t pack_h(float x, float y) {
    __half2 h = __floats2half2_rn(x, y);
    return *(uint32_t*)&h;
}
__device__ __forceinline__ void store_hilo(__half* H, __half* L, size_t off, float x, float y) {
    __half hx = __float2half_rn(x), hy = __float2half_rn(y);
    __half lx = __float2half_rn(x - __half2float(hx));
    __half ly = __float2half_rn(y - __half2float(hy));
    *(__half2*)(H + off) = __halves2half2(hx, hy);
    *(__half2*)(L + off) = __halves2half2(lx, ly);
}
#define CP_ASYNC16(s, g) asm volatile("cp.async.cg.shared.global [%0], [%1], 16;" :: "r"(s), "l"(g) : "memory")
#define CP_COMMIT()      asm volatile("cp.async.commit_group;" ::: "memory")
#define CP_WAIT1()       asm volatile("cp.async.wait_group 1;" ::: "memory")
#define CP_WAIT0()       asm volatile("cp.async.wait_group 0;" ::: "memory")

// =================================================================================
// converts
// =================================================================================
struct Conv3Args { const float* src[3]; __half* dst[3]; };

__global__ void conv3_kernel(Conv3Args a, int n)
{
    const float* x = a.src[blockIdx.z];
    __half* o = a.dst[blockIdx.z];
    int idx = (blockIdx.x * blockDim.x + threadIdx.x) * 4;
    if (idx >= n) return;
    float4 v = *(const float4*)(x + idx);
    *(__half2*)(o + idx)     = __floats2half2_rn(v.x, v.y);
    *(__half2*)(o + idx + 2) = __floats2half2_rn(v.z, v.w);
}

__global__ void conv1_kernel(const float* __restrict__ x, __half* __restrict__ o, int n)
{
    int idx = (blockIdx.x * blockDim.x + threadIdx.x) * 4;
    if (idx >= n) return;
    float4 v = *(const float4*)(x + idx);
    *(__half2*)(o + idx)     = __floats2half2_rn(v.x, v.y);
    *(__half2*)(o + idx + 2) = __floats2half2_rn(v.z, v.w);
}

// V transpose: V16 [b*S+s][h*64+d] -> VT [(b*16+h)*64+d][S]
__global__ void vtrans_kernel(const __half* __restrict__ V, __half* __restrict__ VT)
{
    __shared__ __half t[32][33];
    const int s0 = blockIdx.x * 32;
    const int d0 = blockIdx.y * 32;
    const int bh = blockIdx.z;
    const int b = bh >> 4, h = bh & 15;
    const int tid = threadIdx.x;
    const int cx = tid & 31, cy = tid >> 5;

#pragma unroll
    for (int i = 0; i < 4; i++) {
        int s = s0 + cy + i * 8;
        t[cy + i * 8][cx] = V[(size_t)(b * SEQ + s) * D_MODEL + h * 64 + d0 + cx];
    }
    __syncthreads();
#pragma unroll
    for (int i = 0; i < 4; i++) {
        int d = d0 + cy + i * 8;
        VT[(size_t)(bh * 64 + d) * SEQ + s0 + cx] = t[cx][cy + i * 8];
    }
}

// =================================================================================
// 8-warp mma.sync GEMM core: CTA 128x128, BK=64, warp tile 64x32 (warp grid 2x4).
// ks-level register double-buffer: ldsm for ks+1 issued before HMMAs of ks.
// =================================================================================
#define G_ROWB     144                   // bytes per smem row (64 fp16 + 8 pad)
#define G_TILE_B   (128 * G_ROWB)        // 18432

template<int NA>   // A-operand terms: 1 or 2. Tiles per stage = NA+1.
__device__ __forceinline__ void gemm8_mainloop(
    uint32_t sb, int tid, int lane, int wid,
    const __half* __restrict__ A0, const __half* __restrict__ A1,
    const __half* __restrict__ B0,
    int row0, int col0, float acc[4][4][4])
{
    constexpr int NT = NA + 1;
    constexpr int STAGE_B = NT * G_TILE_B;
    const int warp_m = wid >> 2;         // 0..1  (64 rows)
    const int warp_n = wid & 3;          // 0..3  (32 cols)
    const int la = lane & 7, lb8 = (lane >> 3) & 1, lb16 = lane >> 4;
    const uint32_t a_off = (uint32_t)((la + lb8 * 8) * G_ROWB + lb16 * 16);
    const uint32_t b_off = (uint32_t)((la + lb16 * 8) * G_ROWB + lb8 * 16);

    const __half* srcs[3];
    srcs[0] = A0 + (size_t)row0 * 1024;
    srcs[1] = (NA == 2) ? A1 + (size_t)row0 * 1024 : B0 + (size_t)col0 * 1024;
    srcs[2] = B0 + (size_t)col0 * 1024;

    const int lr = tid >> 1;     // row 0..127
    const int hf = tid & 1;      // half-row 0..1 (64B each)

    auto load_stage = [&](int st, int k0) {
#pragma unroll
        for (int t = 0; t < NT; t++) {
            const uint32_t s = sb + st * STAGE_B + t * G_TILE_B
                             + (uint32_t)lr * G_ROWB + hf * 64;
            const __half* g = srcs[t] + (size_t)lr * 1024 + k0 + hf * 32;
#pragma unroll
            for (int ch = 0; ch < 4; ch++)
                CP_ASYNC16(s + ch * 16, (const void*)(g + ch * 8));
        }
    };

    auto compute_stage = [&](int st) {
        const uint32_t s   = sb + st * STAGE_B;
        const uint32_t aB0 = s + (uint32_t)(warp_m * 64) * G_ROWB;
        const uint32_t aB1 = s + G_TILE_B + (uint32_t)(warp_m * 64) * G_ROWB;
        const uint32_t bB  = s + NA * G_TILE_B + (uint32_t)(warp_n * 32) * G_ROWB;

        uint32_t ah[2][4][4], al[2][4][4], bb[2][2][4];

        // preload ks = 0 into buffer 0
#pragma unroll
        for (int mt = 0; mt < 4; mt++) {
            ldsm4(ah[0][mt], aB0 + (uint32_t)(mt * 16) * G_ROWB + a_off);
            if (NA == 2)
                ldsm4(al[0][mt], aB1 + (uint32_t)(mt * 16) * G_ROWB + a_off);
        }
#pragma unroll
        for (int p = 0; p < 2; p++)
            ldsm4(bb[0][p], bB + (uint32_t)(p * 16) * G_ROWB + b_off);

#pragma unroll
        for (int ks = 0; ks < 4; ks++) {
            const int cur = ks & 1, nxt = cur ^ 1;
            // prefetch ks+1 fragments (no dependence on current HMMAs)
            if (ks < 3) {
                const uint32_t ko = (uint32_t)((ks + 1) * 32);
#pragma unroll
                for (int mt = 0; mt < 4; mt++) {
                    ldsm4(ah[nxt][mt], aB0 + (uint32_t)(mt * 16) * G_ROWB + ko + a_off);
                    if (NA == 2)
                        ldsm4(al[nxt][mt], aB1 + (uint32_t)(mt * 16) * G_ROWB + ko + a_off);
                }
#pragma unroll
                for (int p = 0; p < 2; p++)
                    ldsm4(bb[nxt][p], bB + (uint32_t)(p * 16) * G_ROWB + ko + b_off);
            }
            // compute ks
#pragma unroll
            for (int mt = 0; mt < 4; mt++)
#pragma unroll
                for (int nt = 0; nt < 4; nt++) {
                    float* c = acc[mt][nt];
                    const uint32_t* bp = &bb[cur][nt >> 1][(nt & 1) * 2];
                    mma_f16(c, ah[cur][mt], bp);
                    if (NA == 2) mma_f16(c, al[cur][mt], bp);
                }
        }
    };

    load_stage(0, 0);   CP_COMMIT();
    load_stage(1, 64);  CP_COMMIT();
    for (int c = 0; c < 16; c++) {       // 16 chunks of BK=64
        CP_WAIT1();
        __syncthreads();
        compute_stage(c % 3);
        if (c + 2 < 16) load_stage((c + 2) % 3, (c + 2) * 64);
        CP_COMMIT();
    }
}

// ---- fused QKV projection: X fp16 x W fp16 (1 product); fp16 output (scaled) ----
struct ProjOne {
    const __half *A, *W;
    const float* bias;
    __half *O;
    float scale;
};
struct Proj3Args { ProjOne p[3]; };

__global__ __launch_bounds__(256)
void proj3_kernel(Proj3Args args)
{
    extern __shared__ __align__(128) char smem[];
    const ProjOne P = args.p[blockIdx.z];
    const uint32_t sb = smem_u32(smem);
    const int tid = threadIdx.x, lane = tid & 31, wid = tid >> 5;
    const int row0 = blockIdx.y * 128, col0 = blockIdx.x * 128;

    float acc[4][4][4];
#pragma unroll
    for (int a = 0; a < 4; a++)
#pragma unroll
        for (int b = 0; b < 4; b++)
#pragma unroll
            for (int c = 0; c < 4; c++) acc[a][b][c] = 0.f;

    gemm8_mainloop<1>(sb, tid, lane, wid, P.A, nullptr, P.W, row0, col0, acc);

    const int warp_m = wid >> 2, warp_n = wid & 3;
    const int r_base = row0 + warp_m * 64, c_base = col0 + warp_n * 32;
#pragma unroll
    for (int mt = 0; mt < 4; mt++) {
        const int r = r_base + mt * 16 + (lane >> 2);
#pragma unroll
        for (int nt = 0; nt < 4; nt++) {
            const int cc = c_base + nt * 8 + (lane & 3) * 2;
            const float b0 = __ldg(P.bias + cc), b1 = __ldg(P.bias + cc + 1);
            *(__half2*)(P.O + (size_t)r * 1024 + cc) =
                __floats2half2_rn((acc[mt][nt][0] + b0) * P.scale,
                                  (acc[mt][nt][1] + b1) * P.scale);
            *(__half2*)(P.O + (size_t)(r + 8) * 1024 + cc) =
                __floats2half2_rn((acc[mt][nt][2] + b0) * P.scale,
                                  (acc[mt][nt][3] + b1) * P.scale);
        }
    }
}

// ---- output projection: C 2-term x W 1-term (2 products), fp32 out ----
__global__ __launch_bounds__(256)
void gemmF_kernel(const __half* __restrict__ Ch, const __half* __restrict__ Cl,
                  const __half* __restrict__ W,
                  const float* __restrict__ bias, float* __restrict__ C)
{
    extern __shared__ __align__(128) char smem[];
    const uint32_t sb = smem_u32(smem);
    const int tid = threadIdx.x, lane = tid & 31, wid = tid >> 5;
    const int row0 = blockIdx.y * 128, col0 = blockIdx.x * 128;

    float acc[4][4][4];
#pragma unroll
    for (int a = 0; a < 4; a++)
#pragma unroll
        for (int b = 0; b < 4; b++)
#pragma unroll
            for (int c = 0; c < 4; c++) acc[a][b][c] = 0.f;

    gemm8_mainloop<2>(sb, tid, lane, wid, Ch, Cl, W, row0, col0, acc);

    const int warp_m = wid >> 2, warp_n = wid & 3;
    const int r_base = row0 + warp_m * 64, c_base = col0 + warp_n * 32;
#pragma unroll
    for (int mt = 0; mt < 4; mt++) {
        const int r = r_base + mt * 16 + (lane >> 2);
#pragma unroll
        for (int nt = 0; nt < 4; nt++) {
            const int cc = c_base + nt * 8 + (lane & 3) * 2;
            const float b0 = __ldg(bias + cc), b1 = __ldg(bias + cc + 1);
            float2 o0, o1;
            o0.x = acc[mt][nt][0] + b0; o0.y = acc[mt][nt][1] + b1;
            o1.x = acc[mt][nt][2] + b0; o1.y = acc[mt][nt][3] + b1;
            *(float2*)(C + (size_t)r * 1024 + cc)       = o0;
            *(float2*)(C + (size_t)(r + 8) * 1024 + cc) = o1;
        }
    }
}

// =================================================================================
// Flash attention: pure fp16 operands, fp32 accum. 16 warps, 256 q-rows/CTA.
// KV stage = [K | Vt], 3-stage ring. Out: CH/CL hi/lo. (unchanged from R9)
// =================================================================================
#define A_STRIDE_B 144
#define A_TILE_B   (64 * A_STRIDE_B)    // 9216
#define A_STAGE_B  (2 * A_TILE_B)       // 18432 (K|Vt)
#define A_SMEM_TOT (6 * A_TILE_B)       // 55296

__global__ __launch_bounds__(512)
void attention_mma_kernel(const __half* __restrict__ Q16,
                          const __half* __restrict__ K16, const __half* __restrict__ VT,
                          __half* __restrict__ CH, __half* __restrict__ CL)
{
    extern __shared__ __align__(128) char smem[];
    const uint32_t sb = smem_u32(smem);
    const int tid  = threadIdx.x;
    const int lane = tid & 31, wid = tid >> 5;
    const int bh = blockIdx.y;
    const int b = bh >> 4, h = bh & 15;
    const int q0 = blockIdx.x * 256;

    const int la   = lane & 7;
    const int lb8  = (lane >> 3) & 1;
    const int lb16 = lane >> 4;
    const uint32_t a_off = (uint32_t)((la + lb8 * 8) * A_STRIDE_B + lb16 * 16);
    const uint32_t b_off = (uint32_t)((la + lb16 * 8) * A_STRIDE_B + lb8 * 16);

    // ---- stage Q and move to registers ----
    {
#pragma unroll
        for (int i = 0; i < 4; i++) {
            int c = tid + i * 512;
            int r = c >> 3, ch = c & 7;
            const size_t g = (size_t)(b * SEQ + q0 + r) * D_MODEL + h * 64 + ch * 8;
            CP_ASYNC16(sb + r * A_STRIDE_B + ch * 16, (const void*)(Q16 + g));
        }
        CP_COMMIT();
        CP_WAIT0();
        __syncthreads();
    }
    uint32_t qh[4][4];
#pragma unroll
    for (int ks = 0; ks < 4; ks++)
        ldsm4(qh[ks], sb + (uint32_t)(wid * 16) * A_STRIDE_B + ks * 32 + a_off);
    __syncthreads();

    // ---- KV loader ----
    const int lt = tid >> 8;
    const int lr = (tid & 255) >> 2;
    const int lq = tid & 3;
    auto load_stage = [&](int st, int kv0) {
        const uint32_t s = sb + st * A_STAGE_B + lt * A_TILE_B
                         + (uint32_t)lr * A_STRIDE_B + lq * 32;
        const __half* g = (lt == 0)
            ? K16 + (size_t)(b * SEQ + kv0 + lr) * D_MODEL + h * 64 + lq * 16
            : VT  + (size_t)(bh * 64 + lr) * SEQ + kv0 + lq * 16;
        CP_ASYNC16(s,      (const void*)g);
        CP_ASYNC16(s + 16, (const void*)(g + 8));
    };

    load_stage(0, 0);  CP_COMMIT();
    load_stage(1, 64); CP_COMMIT();

    float o[8][4];
#pragma unroll
    for (int t = 0; t < 8; t++)
#pragma unroll
        for (int j = 0; j < 4; j++) o[t][j] = 0.f;
    float m_r[2] = {-1e30f, -1e30f};
    float l_r[2] = {0.f, 0.f};

    for (int it = 0; it < 32; it++) {
        CP_WAIT1();
        __syncthreads();
        const uint32_t st = sb + (it % 3) * A_STAGE_B;

        // ---- S = Q K^T ----
        float s[8][4];
#pragma unroll
        for (int t = 0; t < 8; t++)
#pragma unroll
            for (int j = 0; j < 4; j++) s[t][j] = 0.f;
#pragma unroll
        for (int ks = 0; ks < 4; ks++) {
#pragma unroll
            for (int np = 0; np < 4; np++) {
                uint32_t k4[4];
                const uint32_t base = (uint32_t)(np * 16) * A_STRIDE_B + ks * 32 + b_off;
                ldsm4(k4, st + base);
                mma_f16(s[2 * np],     qh[ks], k4);
                mma_f16(s[2 * np + 1], qh[ks], k4 + 2);
            }
        }

        // ---- online softmax ----
#pragma unroll
        for (int r = 0; r < 2; r++) {
            float mx = s[0][2 * r];
#pragma unroll
            for (int t = 0; t < 8; t++) {
                mx = fmaxf(mx, s[t][2 * r]);
                mx = fmaxf(mx, s[t][2 * r + 1]);
            }
            mx = fmaxf(mx, __shfl_xor_sync(0xffffffffu, mx, 1));
            mx = fmaxf(mx, __shfl_xor_sync(0xffffffffu, mx, 2));
            float mn = fmaxf(m_r[r], mx);
            float al = __expf(m_r[r] - mn);
            m_r[r] = mn;
            float sum = 0.f;
#pragma unroll
            for (int t = 0; t < 8; t++) {
                float p0 = __expf(s[t][2 * r]     - mn);
                float p1 = __expf(s[t][2 * r + 1] - mn);
                s[t][2 * r] = p0; s[t][2 * r + 1] = p1;
                sum += p0 + p1;
            }
            sum += __shfl_xor_sync(0xffffffffu, sum, 1);
            sum += __shfl_xor_sync(0xffffffffu, sum, 2);
            l_r[r] = l_r[r] * al + sum;
#pragma unroll
            for (int t = 0; t < 8; t++) {
                o[t][2 * r] *= al; o[t][2 * r + 1] *= al;
            }
        }

        // ---- O += P V ----
#pragma unroll
        for (int ks = 0; ks < 4; ks++) {
            const int t0 = 2 * ks, t1 = 2 * ks + 1;
            uint32_t pa[4];
            pa[0] = pack_h(s[t0][0], s[t0][1]);
            pa[1] = pack_h(s[t0][2], s[t0][3]);
            pa[2] = pack_h(s[t1][0], s[t1][1]);
            pa[3] = pack_h(s[t1][2], s[t1][3]);
#pragma unroll
            for (int np = 0; np < 4; np++) {
                uint32_t v4[4];
                const uint32_t base = (uint32_t)(np * 16) * A_STRIDE_B + ks * 32 + b_off;
                ldsm4(v4, st + A_TILE_B + base);
                mma_f16(o[2 * np],     pa, v4);
                mma_f16(o[2 * np + 1], pa, v4 + 2);
            }
        }

        if (it + 2 < 32) load_stage((it + 2) % 3, (it + 2) * 64);
        CP_COMMIT();
    }

    // ---- epilogue: context hi/lo ----
    const float inv0 = 1.f / l_r[0];
    const float inv1 = 1.f / l_r[1];
    const int row0 = q0 + wid * 16 + (lane >> 2);
#pragma unroll
    for (int t = 0; t < 8; t++) {
        const int col = h * 64 + t * 8 + (lane & 3) * 2;
        store_hilo(CH, CL, (size_t)(b * SEQ + row0) * D_MODEL + col,
                   o[t][0] * inv0, o[t][1] * inv0);
        store_hilo(CH, CL, (size_t)(b * SEQ + row0 + 8) * D_MODEL + col,
                   o[t][2] * inv1, o[t][3] * inv1);
    }
}

// =================================================================================
// launch
// =================================================================================
extern "C" void kernel_launch(void* const* d_in, const int* in_sizes, int n_in,
                              void* d_out, int out_size)
{
    const float* x_q = (const float*)d_in[0];
    const float* x_k = (const float*)d_in[1];
    const float* x_v = (const float*)d_in[2];
    const float* wq  = (const float*)d_in[3];
    const float* bq  = (const float*)d_in[4];
    const float* wk  = (const float*)d_in[5];
    const float* bk  = (const float*)d_in[6];
    const float* wv  = (const float*)d_in[7];
    const float* bv  = (const float*)d_in[8];
    const float* wo  = (const float*)d_in[9];
    const float* bo  = (const float*)d_in[10];
    float* out = (float*)d_out;

    __half *x0, *x1, *x2, *q16, *k16, *v16, *vt, *ch, *cl;
    __half *w0, *w1, *w2, *w3;
    cudaGetSymbolAddress((void**)&x0,  g_X0);
    cudaGetSymbolAddress((void**)&x1,  g_X1);
    cudaGetSymbolAddress((void**)&x2,  g_X2);
    cudaGetSymbolAddress((void**)&q16, g_Q16);
    cudaGetSymbolAddress((void**)&k16, g_K16);
    cudaGetSymbolAddress((void**)&v16, g_V16);
    cudaGetSymbolAddress((void**)&vt,  g_VT);
    cudaGetSymbolAddress((void**)&ch,  g_CH);
    cudaGetSymbolAddress((void**)&cl,  g_CL);
    cudaGetSymbolAddress((void**)&w0,  g_W0);
    cudaGetSymbolAddress((void**)&w1,  g_W1);
    cudaGetSymbolAddress((void**)&w2,  g_W2);
    cudaGetSymbolAddress((void**)&w3,  g_W3);

    static int attr_set = 0;
    const int proj_smem = 3 * 2 * G_TILE_B;   // 110592
    const int gemf_smem = 3 * 3 * G_TILE_B;   // 165888
    if (!attr_set) {
        cudaFuncSetAttribute(proj3_kernel,
                             cudaFuncAttributeMaxDynamicSharedMemorySize, proj_smem);
        cudaFuncSetAttribute(gemmF_kernel,
                             cudaFuncAttributeMaxDynamicSharedMemorySize, gemf_smem);
        cudaFuncSetAttribute(attention_mma_kernel,
                             cudaFuncAttributeMaxDynamicSharedMemorySize, A_SMEM_TOT);
        attr_set = 1;
    }

    const int NX = M_TOT * D_MODEL;
    const int NW = D_MODEL * D_MODEL;
    dim3 cb(256);

    // converts (fused 3-way)
    {
        Conv3Args cx; cx.src[0] = x_q; cx.src[1] = x_k; cx.src[2] = x_v;
        cx.dst[0] = x0; cx.dst[1] = x1; cx.dst[2] = x2;
        conv3_kernel<<<dim3((NX / 4 + 255) / 256, 1, 3), cb>>>(cx, NX);
        Conv3Args cw; cw.src[0] = wq; cw.src[1] = wk; cw.src[2] = wv;
        cw.dst[0] = w0; cw.dst[1] = w1; cw.dst[2] = w2;
        conv3_kernel<<<dim3((NW / 4 + 255) / 256, 1, 3), cb>>>(cw, NW);
        conv1_kernel<<<(NW / 4 + 255) / 256, cb>>>(wo, w3, NW);
    }

    // fused QKV projections (fp16 1-term; Q pre-scaled)
    Proj3Args pa;
    pa.p[0] = { x0, w0, bq, q16, 0.125f };
    pa.p[1] = { x1, w1, bk, k16, 1.0f };
    pa.p[2] = { x2, w2, bv, v16, 1.0f };
    proj3_kernel<<<dim3(8, 64, 3), 256, proj_smem>>>(pa);

    // V transpose
    vtrans_kernel<<<dim3(SEQ / 32, 2, BATCH * NHEAD), 256>>>(v16, vt);

    // attention (pure fp16, context hi/lo out)
    attention_mma_kernel<<<dim3(SEQ / 256, BATCH * NHEAD), 512, A_SMEM_TOT>>>(
        q16, k16, vt, ch, cl);

    // output projection (C hi/lo x W, 2 products)
    gemmF_kernel<<<dim3(8, 64), 256, gemf_smem>>>(ch, cl, w3, bo, out);
}

// round 11
// speedup vs baseline: 6.8300x; 1.1644x over previous
#include <cuda_runtime.h>
#include <cuda_fp16.h>
#include <math.h>
#include <cstdint>

#define D_MODEL 1024
#define NHEAD   16
#define D_K     64
#define BATCH   4
#define SEQ     2048
#define M_TOT   (BATCH * SEQ)   // 8192

// ---------------- scratch (device globals: allocation-free rule) ----------------
__device__ __half g_X0 [M_TOT * D_MODEL];
__device__ __half g_X1 [M_TOT * D_MODEL];
__device__ __half g_X2 [M_TOT * D_MODEL];
__device__ __half g_Q16[M_TOT * D_MODEL];
__device__ __half g_K16[M_TOT * D_MODEL];
__device__ __half g_V16[M_TOT * D_MODEL];
__device__ __half g_VT [M_TOT * D_MODEL];
__device__ __half g_CH [M_TOT * D_MODEL];
__device__ __half g_CL [M_TOT * D_MODEL];
__device__ __half g_W0 [D_MODEL * D_MODEL];
__device__ __half g_W1 [D_MODEL * D_MODEL];
__device__ __half g_W2 [D_MODEL * D_MODEL];
__device__ __half g_W3 [D_MODEL * D_MODEL];

// ====================== helpers ======================
__device__ __forceinline__ uint32_t smem_u32(const void* p) {
    uint32_t a;
    asm("{ .reg .u64 t; cvta.to.shared.u64 t, %1; cvt.u32.u64 %0, t; }" : "=r"(a) : "l"(p));
    return a;
}
__device__ __forceinline__ void ldsm4(uint32_t* r, uint32_t addr) {
    asm volatile("ldmatrix.sync.aligned.m8n8.x4.shared.b16 {%0,%1,%2,%3}, [%4];"
        : "=r"(r[0]), "=r"(r[1]), "=r"(r[2]), "=r"(r[3]) : "r"(addr));
}
__device__ __forceinline__ void mma_f16(float* c, const uint32_t* a, const uint32_t* b) {
    asm volatile("mma.sync.aligned.m16n8k16.row.col.f32.f16.f16.f32 "
        "{%0,%1,%2,%3}, {%4,%5,%6,%7}, {%8,%9}, {%0,%1,%2,%3};"
        : "+f"(c[0]), "+f"(c[1]), "+f"(c[2]), "+f"(c[3])
        : "r"(a[0]), "r"(a[1]), "r"(a[2]), "r"(a[3]), "r"(b[0]), "r"(b[1]));
}
__device__ __forceinline__ uint32_t pack_h(float x, float y) {
    __half2 h = __floats2half2_rn(x, y);
    return *(uint32_t*)&h;
}
__device__ __forceinline__ void store_hilo(__half* H, __half* L, size_t off, float x, float y) {
    __half hx = __float2half_rn(x), hy = __float2half_rn(y);
    __half lx = __float2half_rn(x - __half2float(hx));
    __half ly = __float2half_rn(y - __half2float(hy));
    *(__half2*)(H + off) = __halves2half2(hx, hy);
    *(__half2*)(L + off) = __halves2half2(lx, ly);
}
#define CP_ASYNC16(s, g) asm volatile("cp.async.cg.shared.global [%0], [%1], 16;" :: "r"(s), "l"(g) : "memory")
#define CP_COMMIT()      asm volatile("cp.async.commit_group;" ::: "memory")
#define CP_WAIT1()       asm volatile("cp.async.wait_group 1;" ::: "memory")
#define CP_WAIT0()       asm volatile("cp.async.wait_group 0;" ::: "memory")

// =================================================================================
// converts
// =================================================================================
struct Conv3Args { const float* src[3]; __half* dst[3]; };

__global__ void conv3_kernel(Conv3Args a, int n)
{
    const float* x = a.src[blockIdx.z];
    __half* o = a.dst[blockIdx.z];
    int idx = (blockIdx.x * blockDim.x + threadIdx.x) * 4;
    if (idx >= n) return;
    float4 v = *(const float4*)(x + idx);
    *(__half2*)(o + idx)     = __floats2half2_rn(v.x, v.y);
    *(__half2*)(o + idx + 2) = __floats2half2_rn(v.z, v.w);
}

__global__ void conv1_kernel(const float* __restrict__ x, __half* __restrict__ o, int n)
{
    int idx = (blockIdx.x * blockDim.x + threadIdx.x) * 4;
    if (idx >= n) return;
    float4 v = *(const float4*)(x + idx);
    *(__half2*)(o + idx)     = __floats2half2_rn(v.x, v.y);
    *(__half2*)(o + idx + 2) = __floats2half2_rn(v.z, v.w);
}

// V transpose: V16 [b*S+s][h*64+d] -> VT [(b*16+h)*64+d][S]
__global__ void vtrans_kernel(const __half* __restrict__ V, __half* __restrict__ VT)
{
    __shared__ __half t[32][33];
    const int s0 = blockIdx.x * 32;
    const int d0 = blockIdx.y * 32;
    const int bh = blockIdx.z;
    const int b = bh >> 4, h = bh & 15;
    const int tid = threadIdx.x;
    const int cx = tid & 31, cy = tid >> 5;

#pragma unroll
    for (int i = 0; i < 4; i++) {
        int s = s0 + cy + i * 8;
        t[cy + i * 8][cx] = V[(size_t)(b * SEQ + s) * D_MODEL + h * 64 + d0 + cx];
    }
    __syncthreads();
#pragma unroll
    for (int i = 0; i < 4; i++) {
        int d = d0 + cy + i * 8;
        VT[(size_t)(bh * 64 + d) * SEQ + s0 + cx] = t[cx][cy + i * 8];
    }
}

// =================================================================================
// 8-warp GEMM core: CTA 256x128, BK=32, warp tile 64x64 (warp grid 4x2).
// NA A-terms x 1 B-term; 3-stage cp.async ring.
// Reads: 8 ldsm -> 32 HMMA per ks (128 B/HMMA); stores 48 B/HMMA.
// =================================================================================
#define G_ROWB   80                     // bytes per smem row (32 fp16 + 8 pad)
#define GA_TILE  (256 * G_ROWB)         // 20480
#define GB_TILE  (128 * G_ROWB)         // 10240

template<int NA>   // A-operand terms: 1 or 2
__device__ __forceinline__ void gemm_big_mainloop(
    uint32_t sb, int tid, int lane, int wid,
    const __half* __restrict__ A0, const __half* __restrict__ A1,
    const __half* __restrict__ B0,
    int row0, int col0, float acc[4][8][4])
{
    constexpr int STAGE_B = NA * GA_TILE + GB_TILE;
    constexpr int NCH = (NA * 256 + 128) * 4;     // cp.async 16B chunks per stage
    const int warp_m = wid >> 1;         // 0..3  (64 rows)
    const int warp_n = wid & 1;          // 0..1  (64 cols)
    const int la = lane & 7, lb8 = (lane >> 3) & 1, lb16 = lane >> 4;
    const uint32_t a_off = (uint32_t)((la + lb8 * 8) * G_ROWB + lb16 * 16);
    const uint32_t b_off = (uint32_t)((la + lb16 * 8) * G_ROWB + lb8 * 16);

    const __half* srcA0 = A0 + (size_t)row0 * 1024;
    const __half* srcA1 = (NA == 2) ? A1 + (size_t)row0 * 1024 : nullptr;
    const __half* srcB  = B0 + (size_t)col0 * 1024;

    auto load_stage = [&](int st, int k0) {
#pragma unroll
        for (int i = 0; i < NCH / 256; i++) {
            const int c = tid + i * 256;
            const int row = c >> 2, ch = c & 3;
            const __half* g;
            uint32_t soff;
            if (row < 256) {
                g = srcA0 + (size_t)row * 1024;
                soff = (uint32_t)row * G_ROWB;
            } else if (NA == 2 && row < 512) {
                g = srcA1 + (size_t)(row - 256) * 1024;
                soff = GA_TILE + (uint32_t)(row - 256) * G_ROWB;
            } else {
                const int br = row - NA * 256;
                g = srcB + (size_t)br * 1024;
                soff = NA * GA_TILE + (uint32_t)br * G_ROWB;
            }
            CP_ASYNC16(sb + st * STAGE_B + soff + ch * 16,
                       (const void*)(g + k0 + ch * 8));
        }
    };

    auto compute_stage = [&](int st) {
        const uint32_t s   = sb + st * STAGE_B;
        const uint32_t aB0 = s + (uint32_t)(warp_m * 64) * G_ROWB;
        const uint32_t aB1 = s + GA_TILE + (uint32_t)(warp_m * 64) * G_ROWB;
        const uint32_t bB  = s + NA * GA_TILE + (uint32_t)(warp_n * 64) * G_ROWB;
#pragma unroll
        for (int ks = 0; ks < 2; ks++) {
            uint32_t ah[4][4], al[4][4], bb[4][4];
#pragma unroll
            for (int mt = 0; mt < 4; mt++) {
                ldsm4(ah[mt], aB0 + (uint32_t)(mt * 16) * G_ROWB + ks * 32 + a_off);
                if (NA == 2)
                    ldsm4(al[mt], aB1 + (uint32_t)(mt * 16) * G_ROWB + ks * 32 + a_off);
            }
#pragma unroll
            for (int p = 0; p < 4; p++)
                ldsm4(bb[p], bB + (uint32_t)(p * 16) * G_ROWB + ks * 32 + b_off);
#pragma unroll
            for (int mt = 0; mt < 4; mt++)
#pragma unroll
                for (int nt = 0; nt < 8; nt++) {
                    float* c = acc[mt][nt];
                    const uint32_t* bp = &bb[nt >> 1][(nt & 1) * 2];
                    mma_f16(c, ah[mt], bp);
                    if (NA == 2) mma_f16(c, al[mt], bp);
                }
        }
    };

    load_stage(0, 0);   CP_COMMIT();
    load_stage(1, 32);  CP_COMMIT();
    for (int c = 0; c < 32; c++) {       // 32 chunks of BK=32
        CP_WAIT1();
        __syncthreads();
        compute_stage(c % 3);
        if (c + 2 < 32) load_stage((c + 2) % 3, (c + 2) * 32);
        CP_COMMIT();
    }
}

// ---- fused QKV projection: X fp16 x W fp16; fp16 output (scaled) ----
struct ProjOne {
    const __half *A, *W;
    const float* bias;
    __half *O;
    float scale;
};
struct Proj3Args { ProjOne p[3]; };

__global__ __launch_bounds__(256)
void proj3_kernel(Proj3Args args)
{
    extern __shared__ __align__(128) char smem[];
    const ProjOne P = args.p[blockIdx.z];
    const uint32_t sb = smem_u32(smem);
    const int tid = threadIdx.x, lane = tid & 31, wid = tid >> 5;
    const int row0 = blockIdx.y * 256, col0 = blockIdx.x * 128;

    float acc[4][8][4];
#pragma unroll
    for (int a = 0; a < 4; a++)
#pragma unroll
        for (int b = 0; b < 8; b++)
#pragma unroll
            for (int c = 0; c < 4; c++) acc[a][b][c] = 0.f;

    gemm_big_mainloop<1>(sb, tid, lane, wid, P.A, nullptr, P.W, row0, col0, acc);

    const int warp_m = wid >> 1, warp_n = wid & 1;
    const int r_base = row0 + warp_m * 64, c_base = col0 + warp_n * 64;
#pragma unroll
    for (int mt = 0; mt < 4; mt++) {
        const int r = r_base + mt * 16 + (lane >> 2);
#pragma unroll
        for (int nt = 0; nt < 8; nt++) {
            const int cc = c_base + nt * 8 + (lane & 3) * 2;
            const float b0 = __ldg(P.bias + cc), b1 = __ldg(P.bias + cc + 1);
            *(__half2*)(P.O + (size_t)r * 1024 + cc) =
                __floats2half2_rn((acc[mt][nt][0] + b0) * P.scale,
                                  (acc[mt][nt][1] + b1) * P.scale);
            *(__half2*)(P.O + (size_t)(r + 8) * 1024 + cc) =
                __floats2half2_rn((acc[mt][nt][2] + b0) * P.scale,
                                  (acc[mt][nt][3] + b1) * P.scale);
        }
    }
}

// ---- output projection: C 2-term x W 1-term (2 products), fp32 out ----
__global__ __launch_bounds__(256)
void gemmF_kernel(const __half* __restrict__ Ch, const __half* __restrict__ Cl,
                  const __half* __restrict__ W,
                  const float* __restrict__ bias, float* __restrict__ C)
{
    extern __shared__ __align__(128) char smem[];
    const uint32_t sb = smem_u32(smem);
    const int tid = threadIdx.x, lane = tid & 31, wid = tid >> 5;
    const int row0 = blockIdx.y * 256, col0 = blockIdx.x * 128;

    float acc[4][8][4];
#pragma unroll
    for (int a = 0; a < 4; a++)
#pragma unroll
        for (int b = 0; b < 8; b++)
#pragma unroll
            for (int c = 0; c < 4; c++) acc[a][b][c] = 0.f;

    gemm_big_mainloop<2>(sb, tid, lane, wid, Ch, Cl, W, row0, col0, acc);

    const int warp_m = wid >> 1, warp_n = wid & 1;
    const int r_base = row0 + warp_m * 64, c_base = col0 + warp_n * 64;
#pragma unroll
    for (int mt = 0; mt < 4; mt++) {
        const int r = r_base + mt * 16 + (lane >> 2);
#pragma unroll
        for (int nt = 0; nt < 8; nt++) {
            const int cc = c_base + nt * 8 + (lane & 3) * 2;
            const float b0 = __ldg(bias + cc), b1 = __ldg(bias + cc + 1);
            float2 o0, o1;
            o0.x = acc[mt][nt][0] + b0; o0.y = acc[mt][nt][1] + b1;
            o1.x = acc[mt][nt][2] + b0; o1.y = acc[mt][nt][3] + b1;
            *(float2*)(C + (size_t)r * 1024 + cc)       = o0;
            *(float2*)(C + (size_t)(r + 8) * 1024 + cc) = o1;
        }
    }
}

// =================================================================================
// Flash attention: 8 warps / 256 threads, warp M-tile 32, 256 q-rows/CTA.
// KV stage = [K | Vt] (64 kv rows), 3-stage ring. Out: CH/CL hi/lo.
// =================================================================================
#define A_STRIDE_B 144
#define A_TILE_B   (64 * A_STRIDE_B)    // 9216
#define A_STAGE_B  (2 * A_TILE_B)       // 18432 (K|Vt)
#define A_SMEM_TOT (6 * A_TILE_B)       // 55296 (Q staging 36864 fits)

__global__ __launch_bounds__(256)
void attention_mma_kernel(const __half* __restrict__ Q16,
                          const __half* __restrict__ K16, const __half* __restrict__ VT,
                          __half* __restrict__ CH, __half* __restrict__ CL)
{
    extern __shared__ __align__(128) char smem[];
    const uint32_t sb = smem_u32(smem);
    const int tid  = threadIdx.x;
    const int lane = tid & 31, wid = tid >> 5;   // wid 0..7
    const int bh = blockIdx.y;
    const int b = bh >> 4, h = bh & 15;
    const int q0 = blockIdx.x * 256;

    const int la   = lane & 7;
    const int lb8  = (lane >> 3) & 1;
    const int lb16 = lane >> 4;
    const uint32_t a_off = (uint32_t)((la + lb8 * 8) * A_STRIDE_B + lb16 * 16);
    const uint32_t b_off = (uint32_t)((la + lb16 * 8) * A_STRIDE_B + lb8 * 16);

    // ---- stage Q (256 rows) and move to registers (2 m-tiles per warp) ----
    {
#pragma unroll
        for (int i = 0; i < 8; i++) {
            int c = tid + i * 256;            // 0..2047
            int r = c >> 3, ch = c & 7;
            const size_t g = (size_t)(b * SEQ + q0 + r) * D_MODEL + h * 64 + ch * 8;
            CP_ASYNC16(sb + r * A_STRIDE_B + ch * 16, (const void*)(Q16 + g));
        }
        CP_COMMIT();
        CP_WAIT0();
        __syncthreads();
    }
    uint32_t qh[4][2][4];
#pragma unroll
    for (int ks = 0; ks < 4; ks++)
#pragma unroll
        for (int mt = 0; mt < 2; mt++)
            ldsm4(qh[ks][mt],
                  sb + (uint32_t)((wid * 32 + mt * 16)) * A_STRIDE_B + ks * 32 + a_off);
    __syncthreads();

    // ---- KV loader: 128 rows x 8 chunks = 1024 chunks; 4 per thread ----
    auto load_stage = [&](int st, int kv0) {
#pragma unroll
        for (int i = 0; i < 4; i++) {
            const int c = tid + i * 256;
            const int row = c >> 3, ch = c & 7;
            const __half* g;
            uint32_t soff;
            if (row < 64) {
                g = K16 + (size_t)(b * SEQ + kv0 + row) * D_MODEL + h * 64;
                soff = (uint32_t)row * A_STRIDE_B;
            } else {
                g = VT + (size_t)(bh * 64 + (row - 64)) * SEQ + kv0;
                soff = A_TILE_B + (uint32_t)(row - 64) * A_STRIDE_B;
            }
            CP_ASYNC16(sb + st * A_STAGE_B + soff + ch * 16, (const void*)(g + ch * 8));
        }
    };

    load_stage(0, 0);  CP_COMMIT();
    load_stage(1, 64); CP_COMMIT();

    float o[2][8][4];
#pragma unroll
    for (int mt = 0; mt < 2; mt++)
#pragma unroll
        for (int t = 0; t < 8; t++)
#pragma unroll
            for (int j = 0; j < 4; j++) o[mt][t][j] = 0.f;
    float m_r[4] = {-1e30f, -1e30f, -1e30f, -1e30f};
    float l_r[4] = {0.f, 0.f, 0.f, 0.f};

    for (int it = 0; it < 32; it++) {
        CP_WAIT1();
        __syncthreads();
        const uint32_t st = sb + (it % 3) * A_STAGE_B;

        // ---- S = Q K^T ----
        float s[2][8][4];
#pragma unroll
        for (int mt = 0; mt < 2; mt++)
#pragma unroll
            for (int t = 0; t < 8; t++)
#pragma unroll
                for (int j = 0; j < 4; j++) s[mt][t][j] = 0.f;
#pragma unroll
        for (int ks = 0; ks < 4; ks++) {
#pragma unroll
            for (int np = 0; np < 4; np++) {
                uint32_t k4[4];
                const uint32_t base = (uint32_t)(np * 16) * A_STRIDE_B + ks * 32 + b_off;
                ldsm4(k4, st + base);
#pragma unroll
                for (int mt = 0; mt < 2; mt++) {
                    mma_f16(s[mt][2 * np],     qh[ks][mt], k4);
                    mma_f16(s[mt][2 * np + 1], qh[ks][mt], k4 + 2);
                }
            }
        }

        // ---- online softmax (4 rows per thread: mt x r) ----
#pragma unroll
        for (int mt = 0; mt < 2; mt++)
#pragma unroll
            for (int r = 0; r < 2; r++) {
                const int ri = mt * 2 + r;
                float mx = s[mt][0][2 * r];
#pragma unroll
                for (int t = 0; t < 8; t++) {
                    mx = fmaxf(mx, s[mt][t][2 * r]);
                    mx = fmaxf(mx, s[mt][t][2 * r + 1]);
                }
                mx = fmaxf(mx, __shfl_xor_sync(0xffffffffu, mx, 1));
                mx = fmaxf(mx, __shfl_xor_sync(0xffffffffu, mx, 2));
                float mn = fmaxf(m_r[ri], mx);
                float al = __expf(m_r[ri] - mn);
                m_r[ri] = mn;
                float sum = 0.f;
#pragma unroll
                for (int t = 0; t < 8; t++) {
                    float p0 = __expf(s[mt][t][2 * r]     - mn);
                    float p1 = __expf(s[mt][t][2 * r + 1] - mn);
                    s[mt][t][2 * r] = p0; s[mt][t][2 * r + 1] = p1;
                    sum += p0 + p1;
                }
                sum += __shfl_xor_sync(0xffffffffu, sum, 1);
                sum += __shfl_xor_sync(0xffffffffu, sum, 2);
                l_r[ri] = l_r[ri] * al + sum;
#pragma unroll
                for (int t = 0; t < 8; t++) {
                    o[mt][t][2 * r] *= al; o[mt][t][2 * r + 1] *= al;
                }
            }

        // ---- O += P V ----
#pragma unroll
        for (int ks = 0; ks < 4; ks++) {
            const int t0 = 2 * ks, t1 = 2 * ks + 1;
            uint32_t pa[2][4];
#pragma unroll
            for (int mt = 0; mt < 2; mt++) {
                pa[mt][0] = pack_h(s[mt][t0][0], s[mt][t0][1]);
                pa[mt][1] = pack_h(s[mt][t0][2], s[mt][t0][3]);
                pa[mt][2] = pack_h(s[mt][t1][0], s[mt][t1][1]);
                pa[mt][3] = pack_h(s[mt][t1][2], s[mt][t1][3]);
            }
#pragma unroll
            for (int np = 0; np < 4; np++) {
                uint32_t v4[4];
                const uint32_t base = (uint32_t)(np * 16) * A_STRIDE_B + ks * 32 + b_off;
                ldsm4(v4, st + A_TILE_B + base);
#pragma unroll
                for (int mt = 0; mt < 2; mt++) {
                    mma_f16(o[mt][2 * np],     pa[mt], v4);
                    mma_f16(o[mt][2 * np + 1], pa[mt], v4 + 2);
                }
            }
        }

        if (it + 2 < 32) load_stage((it + 2) % 3, (it + 2) * 64);
        CP_COMMIT();
    }

    // ---- epilogue: context hi/lo ----
#pragma unroll
    for (int mt = 0; mt < 2; mt++) {
        const float inv0 = 1.f / l_r[mt * 2];
        const float inv1 = 1.f / l_r[mt * 2 + 1];
        const int row0 = q0 + wid * 32 + mt * 16 + (lane >> 2);
#pragma unroll
        for (int t = 0; t < 8; t++) {
            const int col = h * 64 + t * 8 + (lane & 3) * 2;
            store_hilo(CH, CL, (size_t)(b * SEQ + row0) * D_MODEL + col,
                       o[mt][t][0] * inv0, o[mt][t][1] * inv0);
            store_hilo(CH, CL, (size_t)(b * SEQ + row0 + 8) * D_MODEL + col,
                       o[mt][t][2] * inv1, o[mt][t][3] * inv1);
        }
    }
}

// =================================================================================
// launch
// =================================================================================
extern "C" void kernel_launch(void* const* d_in, const int* in_sizes, int n_in,
                              void* d_out, int out_size)
{
    const float* x_q = (const float*)d_in[0];
    const float* x_k = (const float*)d_in[1];
    const float* x_v = (const float*)d_in[2];
    const float* wq  = (const float*)d_in[3];
    const float* bq  = (const float*)d_in[4];
    const float* wk  = (const float*)d_in[5];
    const float* bk  = (const float*)d_in[6];
    const float* wv  = (const float*)d_in[7];
    const float* bv  = (const float*)d_in[8];
    const float* wo  = (const float*)d_in[9];
    const float* bo  = (const float*)d_in[10];
    float* out = (float*)d_out;

    __half *x0, *x1, *x2, *q16, *k16, *v16, *vt, *ch, *cl;
    __half *w0, *w1, *w2, *w3;
    cudaGetSymbolAddress((void**)&x0,  g_X0);
    cudaGetSymbolAddress((void**)&x1,  g_X1);
    cudaGetSymbolAddress((void**)&x2,  g_X2);
    cudaGetSymbolAddress((void**)&q16, g_Q16);
    cudaGetSymbolAddress((void**)&k16, g_K16);
    cudaGetSymbolAddress((void**)&v16, g_V16);
    cudaGetSymbolAddress((void**)&vt,  g_VT);
    cudaGetSymbolAddress((void**)&ch,  g_CH);
    cudaGetSymbolAddress((void**)&cl,  g_CL);
    cudaGetSymbolAddress((void**)&w0,  g_W0);
    cudaGetSymbolAddress((void**)&w1,  g_W1);
    cudaGetSymbolAddress((void**)&w2,  g_W2);
    cudaGetSymbolAddress((void**)&w3,  g_W3);

    static int attr_set = 0;
    const int proj_smem = 3 * (GA_TILE + GB_TILE);       // 92160
    const int gemf_smem = 3 * (2 * GA_TILE + GB_TILE);   // 153600
    if (!attr_set) {
        cudaFuncSetAttribute(proj3_kernel,
                             cudaFuncAttributeMaxDynamicSharedMemorySize, proj_smem);
        cudaFuncSetAttribute(gemmF_kernel,
                             cudaFuncAttributeMaxDynamicSharedMemorySize, gemf_smem);
        cudaFuncSetAttribute(attention_mma_kernel,
                             cudaFuncAttributeMaxDynamicSharedMemorySize, A_SMEM_TOT);
        attr_set = 1;
    }

    const int NX = M_TOT * D_MODEL;
    const int NW = D_MODEL * D_MODEL;
    dim3 cb(256);

    // converts (fused 3-way)
    {
        Conv3Args cx; cx.src[0] = x_q; cx.src[1] = x_k; cx.src[2] = x_v;
        cx.dst[0] = x0; cx.dst[1] = x1; cx.dst[2] = x2;
        conv3_kernel<<<dim3((NX / 4 + 255) / 256, 1, 3), cb>>>(cx, NX);
        Conv3Args cw; cw.src[0] = wq; cw.src[1] = wk; cw.src[2] = wv;
        cw.dst[0] = w0; cw.dst[1] = w1; cw.dst[2] = w2;
        conv3_kernel<<<dim3((NW / 4 + 255) / 256, 1, 3), cb>>>(cw, NW);
        conv1_kernel<<<(NW / 4 + 255) / 256, cb>>>(wo, w3, NW);
    }

    // fused QKV projections (fp16 1-term; Q pre-scaled). CTA 256x128.
    Proj3Args pa;
    pa.p[0] = { x0, w0, bq, q16, 0.125f };
    pa.p[1] = { x1, w1, bk, k16, 1.0f };
    pa.p[2] = { x2, w2, bv, v16, 1.0f };
    proj3_kernel<<<dim3(8, 32, 3), 256, proj_smem>>>(pa);

    // V transpose
    vtrans_kernel<<<dim3(SEQ / 32, 2, BATCH * NHEAD), 256>>>(v16, vt);

    // attention (pure fp16, 256 q-rows/CTA, context hi/lo out)
    attention_mma_kernel<<<dim3(SEQ / 256, BATCH * NHEAD), 256, A_SMEM_TOT>>>(
        q16, k16, vt, ch, cl);

    // output projection (C hi/lo x W, 2 products). CTA 256x128.
    gemmF_kernel<<<dim3(8, 32), 256, gemf_smem>>>(ch, cl, w3, bo, out);
}

// round 12
// speedup vs baseline: 6.9466x; 1.0171x over previous
#include <cuda_runtime.h>
#include <cuda_fp16.h>
#include <math.h>
#include <cstdint>

#define D_MODEL 1024
#define NHEAD   16
#define D_K     64
#define BATCH   4
#define SEQ     2048
#define M_TOT   (BATCH * SEQ)   // 8192

// ---------------- scratch (device globals: allocation-free rule) ----------------
__device__ __half g_X0 [M_TOT * D_MODEL];
__device__ __half g_X1 [M_TOT * D_MODEL];
__device__ __half g_X2 [M_TOT * D_MODEL];
__device__ __half g_Q16[M_TOT * D_MODEL];
__device__ __half g_K16[M_TOT * D_MODEL];
__device__ __half g_V16[M_TOT * D_MODEL];
__device__ __half g_VT [M_TOT * D_MODEL];
__device__ __half g_CH [M_TOT * D_MODEL];
__device__ __half g_CL [M_TOT * D_MODEL];
__device__ __half g_W0 [D_MODEL * D_MODEL];
__device__ __half g_W1 [D_MODEL * D_MODEL];
__device__ __half g_W2 [D_MODEL * D_MODEL];
__device__ __half g_W3 [D_MODEL * D_MODEL];

// ====================== helpers ======================
__device__ __forceinline__ uint32_t smem_u32(const void* p) {
    uint32_t a;
    asm("{ .reg .u64 t; cvta.to.shared.u64 t, %1; cvt.u32.u64 %0, t; }" : "=r"(a) : "l"(p));
    return a;
}
__device__ __forceinline__ void ldsm4(uint32_t* r, uint32_t addr) {
    asm volatile("ldmatrix.sync.aligned.m8n8.x4.shared.b16 {%0,%1,%2,%3}, [%4];"
        : "=r"(r[0]), "=r"(r[1]), "=r"(r[2]), "=r"(r[3]) : "r"(addr));
}
__device__ __forceinline__ void mma_f16(float* c, const uint32_t* a, const uint32_t* b) {
    asm volatile("mma.sync.aligned.m16n8k16.row.col.f32.f16.f16.f32 "
        "{%0,%1,%2,%3}, {%4,%5,%6,%7}, {%8,%9}, {%0,%1,%2,%3};"
        : "+f"(c[0]), "+f"(c[1]), "+f"(c[2]), "+f"(c[3])
        : "r"(a[0]), "r"(a[1]), "r"(a[2]), "r"(a[3]), "r"(b[0]), "r"(b[1]));
}
__device__ __forceinline__ uint32_t pack_h(float x, float y) {
    __half2 h = __floats2half2_rn(x, y);
    return *(uint32_t*)&h;
}
__device__ __forceinline__ void store_hilo(__half* H, __half* L, size_t off, float x, float y) {
    __half hx = __float2half_rn(x), hy = __float2half_rn(y);
    __half lx = __float2half_rn(x - __half2float(hx));
    __half ly = __float2half_rn(y - __half2float(hy));
    *(__half2*)(H + off) = __halves2half2(hx, hy);
    *(__half2*)(L + off) = __halves2half2(lx, ly);
}
#define CP_ASYNC16(s, g) asm volatile("cp.async.cg.shared.global [%0], [%1], 16;" :: "r"(s), "l"(g) : "memory")
#define CP_COMMIT()      asm volatile("cp.async.commit_group;" ::: "memory")
#define CP_WAIT1()       asm volatile("cp.async.wait_group 1;" ::: "memory")
#define CP_WAIT0()       asm volatile("cp.async.wait_group 0;" ::: "memory")

// =================================================================================
// converts
// =================================================================================
struct Conv3Args { const float* src[3]; __half* dst[3]; };

__global__ void conv3_kernel(Conv3Args a, int n)
{
    const float* x = a.src[blockIdx.z];
    __half* o = a.dst[blockIdx.z];
    int idx = (blockIdx.x * blockDim.x + threadIdx.x) * 4;
    if (idx >= n) return;
    float4 v = *(const float4*)(x + idx);
    *(__half2*)(o + idx)     = __floats2half2_rn(v.x, v.y);
    *(__half2*)(o + idx + 2) = __floats2half2_rn(v.z, v.w);
}

__global__ void conv1_kernel(const float* __restrict__ x, __half* __restrict__ o, int n)
{
    int idx = (blockIdx.x * blockDim.x + threadIdx.x) * 4;
    if (idx >= n) return;
    float4 v = *(const float4*)(x + idx);
    *(__half2*)(o + idx)     = __floats2half2_rn(v.x, v.y);
    *(__half2*)(o + idx + 2) = __floats2half2_rn(v.z, v.w);
}

// V transpose: V16 [b*S+s][h*64+d] -> VT [(b*16+h)*64+d][S]
__global__ void vtrans_kernel(const __half* __restrict__ V, __half* __restrict__ VT)
{
    __shared__ __half t[32][33];
    const int s0 = blockIdx.x * 32;
    const int d0 = blockIdx.y * 32;
    const int bh = blockIdx.z;
    const int b = bh >> 4, h = bh & 15;
    const int tid = threadIdx.x;
    const int cx = tid & 31, cy = tid >> 5;

#pragma unroll
    for (int i = 0; i < 4; i++) {
        int s = s0 + cy + i * 8;
        t[cy + i * 8][cx] = V[(size_t)(b * SEQ + s) * D_MODEL + h * 64 + d0 + cx];
    }
    __syncthreads();
#pragma unroll
    for (int i = 0; i < 4; i++) {
        int d = d0 + cy + i * 8;
        VT[(size_t)(bh * 64 + d) * SEQ + s0 + cx] = t[cx][cy + i * 8];
    }
}

// =================================================================================
// 8-warp GEMM core: CTA 256x128, BK=64, warp tile 64x64 (warp grid 4x2).
// 16 K-chunks; per chunk 4 ks-steps of (8|12) ldsm -> (32|64) HMMA.
// =================================================================================
#define G_ROWB   144                    // bytes per smem row (64 fp16 + 8 pad)
#define GA_TILE  (256 * G_ROWB)         // 36864
#define GB_TILE  (128 * G_ROWB)         // 18432

template<int NA>
__device__ __forceinline__ void gemm_load_stage(
    uint32_t sb, int tid,
    const __half* srcA0, const __half* srcA1, const __half* srcB,
    int st, int k0)
{
    constexpr int STAGE_B = NA * GA_TILE + GB_TILE;
    constexpr int NCH = (NA * 256 + 128) * 8;     // 16B chunks per stage
#pragma unroll
    for (int i = 0; i < NCH / 256; i++) {
        const int c = tid + i * 256;
        const int row = c >> 3, ch = c & 7;
        const __half* g;
        uint32_t soff;
        if (row < 256) {
            g = srcA0 + (size_t)row * 1024;
            soff = (uint32_t)row * G_ROWB;
        } else if (NA == 2 && row < 512) {
            g = srcA1 + (size_t)(row - 256) * 1024;
            soff = GA_TILE + (uint32_t)(row - 256) * G_ROWB;
        } else {
            const int br = row - NA * 256;
            g = srcB + (size_t)br * 1024;
            soff = NA * GA_TILE + (uint32_t)br * G_ROWB;
        }
        CP_ASYNC16(sb + st * STAGE_B + soff + ch * 16, (const void*)(g + k0 + ch * 8));
    }
}

template<int NA>
__device__ __forceinline__ void gemm_compute_stage(
    uint32_t sb, int warp_m, int warp_n, uint32_t a_off, uint32_t b_off,
    int st, float acc[4][8][4])
{
    constexpr int STAGE_B = NA * GA_TILE + GB_TILE;
    const uint32_t s   = sb + st * STAGE_B;
    const uint32_t aB0 = s + (uint32_t)(warp_m * 64) * G_ROWB;
    const uint32_t aB1 = s + GA_TILE + (uint32_t)(warp_m * 64) * G_ROWB;
    const uint32_t bB  = s + NA * GA_TILE + (uint32_t)(warp_n * 64) * G_ROWB;
#pragma unroll
    for (int ks = 0; ks < 4; ks++) {
        uint32_t ah[4][4], al[4][4], bb[4][4];
#pragma unroll
        for (int mt = 0; mt < 4; mt++) {
            ldsm4(ah[mt], aB0 + (uint32_t)(mt * 16) * G_ROWB + ks * 32 + a_off);
            if (NA == 2)
                ldsm4(al[mt], aB1 + (uint32_t)(mt * 16) * G_ROWB + ks * 32 + a_off);
        }
#pragma unroll
        for (int p = 0; p < 4; p++)
            ldsm4(bb[p], bB + (uint32_t)(p * 16) * G_ROWB + ks * 32 + b_off);
#pragma unroll
        for (int mt = 0; mt < 4; mt++)
#pragma unroll
            for (int nt = 0; nt < 8; nt++) {
                float* c = acc[mt][nt];
                const uint32_t* bp = &bb[nt >> 1][(nt & 1) * 2];
                mma_f16(c, ah[mt], bp);
                if (NA == 2) mma_f16(c, al[mt], bp);
            }
    }
}

// ---- fused QKV projection: X fp16 x W fp16; fp16 output (scaled). 3-stage ring. ----
struct ProjOne {
    const __half *A, *W;
    const float* bias;
    __half *O;
    float scale;
};
struct Proj3Args { ProjOne p[3]; };

__global__ __launch_bounds__(256)
void proj3_kernel(Proj3Args args)
{
    extern __shared__ __align__(128) char smem[];
    const ProjOne P = args.p[blockIdx.z];
    const uint32_t sb = smem_u32(smem);
    const int tid = threadIdx.x, lane = tid & 31, wid = tid >> 5;
    const int row0 = blockIdx.y * 256, col0 = blockIdx.x * 128;
    const int warp_m = wid >> 1, warp_n = wid & 1;
    const int la = lane & 7, lb8 = (lane >> 3) & 1, lb16 = lane >> 4;
    const uint32_t a_off = (uint32_t)((la + lb8 * 8) * G_ROWB + lb16 * 16);
    const uint32_t b_off = (uint32_t)((la + lb16 * 8) * G_ROWB + lb8 * 16);

    const __half* srcA = P.A + (size_t)row0 * 1024;
    const __half* srcB = P.W + (size_t)col0 * 1024;

    float acc[4][8][4];
#pragma unroll
    for (int a = 0; a < 4; a++)
#pragma unroll
        for (int b = 0; b < 8; b++)
#pragma unroll
            for (int c = 0; c < 4; c++) acc[a][b][c] = 0.f;

    gemm_load_stage<1>(sb, tid, srcA, nullptr, srcB, 0, 0);   CP_COMMIT();
    gemm_load_stage<1>(sb, tid, srcA, nullptr, srcB, 1, 64);  CP_COMMIT();
    for (int c = 0; c < 16; c++) {
        CP_WAIT1();
        __syncthreads();
        gemm_compute_stage<1>(sb, warp_m, warp_n, a_off, b_off, c % 3, acc);
        if (c + 2 < 16)
            gemm_load_stage<1>(sb, tid, srcA, nullptr, srcB, (c + 2) % 3, (c + 2) * 64);
        CP_COMMIT();
    }

    const int r_base = row0 + warp_m * 64, c_base = col0 + warp_n * 64;
#pragma unroll
    for (int mt = 0; mt < 4; mt++) {
        const int r = r_base + mt * 16 + (lane >> 2);
#pragma unroll
        for (int nt = 0; nt < 8; nt++) {
            const int cc = c_base + nt * 8 + (lane & 3) * 2;
            const float b0 = __ldg(P.bias + cc), b1 = __ldg(P.bias + cc + 1);
            *(__half2*)(P.O + (size_t)r * 1024 + cc) =
                __floats2half2_rn((acc[mt][nt][0] + b0) * P.scale,
                                  (acc[mt][nt][1] + b1) * P.scale);
            *(__half2*)(P.O + (size_t)(r + 8) * 1024 + cc) =
                __floats2half2_rn((acc[mt][nt][2] + b0) * P.scale,
                                  (acc[mt][nt][3] + b1) * P.scale);
        }
    }
}

// ---- output projection: C 2-term x W 1-term, fp32 out. 2-stage pipeline. ----
__global__ __launch_bounds__(256)
void gemmF_kernel(const __half* __restrict__ Ch, const __half* __restrict__ Cl,
                  const __half* __restrict__ W,
                  const float* __restrict__ bias, float* __restrict__ C)
{
    extern __shared__ __align__(128) char smem[];
    const uint32_t sb = smem_u32(smem);
    const int tid = threadIdx.x, lane = tid & 31, wid = tid >> 5;
    const int row0 = blockIdx.y * 256, col0 = blockIdx.x * 128;
    const int warp_m = wid >> 1, warp_n = wid & 1;
    const int la = lane & 7, lb8 = (lane >> 3) & 1, lb16 = lane >> 4;
    const uint32_t a_off = (uint32_t)((la + lb8 * 8) * G_ROWB + lb16 * 16);
    const uint32_t b_off = (uint32_t)((la + lb16 * 8) * G_ROWB + lb8 * 16);

    const __half* srcA0 = Ch + (size_t)row0 * 1024;
    const __half* srcA1 = Cl + (size_t)row0 * 1024;
    const __half* srcB  = W  + (size_t)col0 * 1024;

    float acc[4][8][4];
#pragma unroll
    for (int a = 0; a < 4; a++)
#pragma unroll
        for (int b = 0; b < 8; b++)
#pragma unroll
            for (int c = 0; c < 4; c++) acc[a][b][c] = 0.f;

    gemm_load_stage<2>(sb, tid, srcA0, srcA1, srcB, 0, 0);   CP_COMMIT();
    for (int c = 0; c < 16; c++) {
        CP_WAIT0();
        __syncthreads();
        if (c + 1 < 16) {
            gemm_load_stage<2>(sb, tid, srcA0, srcA1, srcB, (c + 1) & 1, (c + 1) * 64);
            CP_COMMIT();
        }
        gemm_compute_stage<2>(sb, warp_m, warp_n, a_off, b_off, c & 1, acc);
        __syncthreads();
    }

    const int r_base = row0 + warp_m * 64, c_base = col0 + warp_n * 64;
#pragma unroll
    for (int mt = 0; mt < 4; mt++) {
        const int r = r_base + mt * 16 + (lane >> 2);
#pragma unroll
        for (int nt = 0; nt < 8; nt++) {
            const int cc = c_base + nt * 8 + (lane & 3) * 2;
            const float b0 = __ldg(bias + cc), b1 = __ldg(bias + cc + 1);
            float2 o0, o1;
            o0.x = acc[mt][nt][0] + b0; o0.y = acc[mt][nt][1] + b1;
            o1.x = acc[mt][nt][2] + b0; o1.y = acc[mt][nt][3] + b1;
            *(float2*)(C + (size_t)r * 1024 + cc)       = o0;
            *(float2*)(C + (size_t)(r + 8) * 1024 + cc) = o1;
        }
    }
}

// =================================================================================
// Flash attention: 8 warps / 256 threads, warp M-tile 32, 256 q-rows/CTA.
// KV stage = [K | Vt] (64 kv rows), 3-stage ring. Out: CH/CL hi/lo. (unchanged)
// =================================================================================
#define A_STRIDE_B 144
#define A_TILE_B   (64 * A_STRIDE_B)    // 9216
#define A_STAGE_B  (2 * A_TILE_B)       // 18432 (K|Vt)
#define A_SMEM_TOT (6 * A_TILE_B)       // 55296

__global__ __launch_bounds__(256)
void attention_mma_kernel(const __half* __restrict__ Q16,
                          const __half* __restrict__ K16, const __half* __restrict__ VT,
                          __half* __restrict__ CH, __half* __restrict__ CL)
{
    extern __shared__ __align__(128) char smem[];
    const uint32_t sb = smem_u32(smem);
    const int tid  = threadIdx.x;
    const int lane = tid & 31, wid = tid >> 5;
    const int bh = blockIdx.y;
    const int b = bh >> 4, h = bh & 15;
    const int q0 = blockIdx.x * 256;

    const int la   = lane & 7;
    const int lb8  = (lane >> 3) & 1;
    const int lb16 = lane >> 4;
    const uint32_t a_off = (uint32_t)((la + lb8 * 8) * A_STRIDE_B + lb16 * 16);
    const uint32_t b_off = (uint32_t)((la + lb16 * 8) * A_STRIDE_B + lb8 * 16);

    // ---- stage Q (256 rows) and move to registers ----
    {
#pragma unroll
        for (int i = 0; i < 8; i++) {
            int c = tid + i * 256;
            int r = c >> 3, ch = c & 7;
            const size_t g = (size_t)(b * SEQ + q0 + r) * D_MODEL + h * 64 + ch * 8;
            CP_ASYNC16(sb + r * A_STRIDE_B + ch * 16, (const void*)(Q16 + g));
        }
        CP_COMMIT();
        CP_WAIT0();
        __syncthreads();
    }
    uint32_t qh[4][2][4];
#pragma unroll
    for (int ks = 0; ks < 4; ks++)
#pragma unroll
        for (int mt = 0; mt < 2; mt++)
            ldsm4(qh[ks][mt],
                  sb + (uint32_t)((wid * 32 + mt * 16)) * A_STRIDE_B + ks * 32 + a_off);
    __syncthreads();

    // ---- KV loader ----
    auto load_stage = [&](int st, int kv0) {
#pragma unroll
        for (int i = 0; i < 4; i++) {
            const int c = tid + i * 256;
            const int row = c >> 3, ch = c & 7;
            const __half* g;
            uint32_t soff;
            if (row < 64) {
                g = K16 + (size_t)(b * SEQ + kv0 + row) * D_MODEL + h * 64;
                soff = (uint32_t)row * A_STRIDE_B;
            } else {
                g = VT + (size_t)(bh * 64 + (row - 64)) * SEQ + kv0;
                soff = A_TILE_B + (uint32_t)(row - 64) * A_STRIDE_B;
            }
            CP_ASYNC16(sb + st * A_STAGE_B + soff + ch * 16, (const void*)(g + ch * 8));
        }
    };

    load_stage(0, 0);  CP_COMMIT();
    load_stage(1, 64); CP_COMMIT();

    float o[2][8][4];
#pragma unroll
    for (int mt = 0; mt < 2; mt++)
#pragma unroll
        for (int t = 0; t < 8; t++)
#pragma unroll
            for (int j = 0; j < 4; j++) o[mt][t][j] = 0.f;
    float m_r[4] = {-1e30f, -1e30f, -1e30f, -1e30f};
    float l_r[4] = {0.f, 0.f, 0.f, 0.f};

    for (int it = 0; it < 32; it++) {
        CP_WAIT1();
        __syncthreads();
        const uint32_t st = sb + (it % 3) * A_STAGE_B;

        // ---- S = Q K^T ----
        float s[2][8][4];
#pragma unroll
        for (int mt = 0; mt < 2; mt++)
#pragma unroll
            for (int t = 0; t < 8; t++)
#pragma unroll
                for (int j = 0; j < 4; j++) s[mt][t][j] = 0.f;
#pragma unroll
        for (int ks = 0; ks < 4; ks++) {
#pragma unroll
            for (int np = 0; np < 4; np++) {
                uint32_t k4[4];
                const uint32_t base = (uint32_t)(np * 16) * A_STRIDE_B + ks * 32 + b_off;
                ldsm4(k4, st + base);
#pragma unroll
                for (int mt = 0; mt < 2; mt++) {
                    mma_f16(s[mt][2 * np],     qh[ks][mt], k4);
                    mma_f16(s[mt][2 * np + 1], qh[ks][mt], k4 + 2);
                }
            }
        }

        // ---- online softmax ----
#pragma unroll
        for (int mt = 0; mt < 2; mt++)
#pragma unroll
            for (int r = 0; r < 2; r++) {
                const int ri = mt * 2 + r;
                float mx = s[mt][0][2 * r];
#pragma unroll
                for (int t = 0; t < 8; t++) {
                    mx = fmaxf(mx, s[mt][t][2 * r]);
                    mx = fmaxf(mx, s[mt][t][2 * r + 1]);
                }
                mx = fmaxf(mx, __shfl_xor_sync(0xffffffffu, mx, 1));
                mx = fmaxf(mx, __shfl_xor_sync(0xffffffffu, mx, 2));
                float mn = fmaxf(m_r[ri], mx);
                float al = __expf(m_r[ri] - mn);
                m_r[ri] = mn;
                float sum = 0.f;
#pragma unroll
                for (int t = 0; t < 8; t++) {
                    float p0 = __expf(s[mt][t][2 * r]     - mn);
                    float p1 = __expf(s[mt][t][2 * r + 1] - mn);
                    s[mt][t][2 * r] = p0; s[mt][t][2 * r + 1] = p1;
                    sum += p0 + p1;
                }
                sum += __shfl_xor_sync(0xffffffffu, sum, 1);
                sum += __shfl_xor_sync(0xffffffffu, sum, 2);
                l_r[ri] = l_r[ri] * al + sum;
#pragma unroll
                for (int t = 0; t < 8; t++) {
                    o[mt][t][2 * r] *= al; o[mt][t][2 * r + 1] *= al;
                }
            }

        // ---- O += P V ----
#pragma unroll
        for (int ks = 0; ks < 4; ks++) {
            const int t0 = 2 * ks, t1 = 2 * ks + 1;
            uint32_t pa[2][4];
#pragma unroll
            for (int mt = 0; mt < 2; mt++) {
                pa[mt][0] = pack_h(s[mt][t0][0], s[mt][t0][1]);
                pa[mt][1] = pack_h(s[mt][t0][2], s[mt][t0][3]);
                pa[mt][2] = pack_h(s[mt][t1][0], s[mt][t1][1]);
                pa[mt][3] = pack_h(s[mt][t1][2], s[mt][t1][3]);
            }
#pragma unroll
            for (int np = 0; np < 4; np++) {
                uint32_t v4[4];
                const uint32_t base = (uint32_t)(np * 16) * A_STRIDE_B + ks * 32 + b_off;
                ldsm4(v4, st + A_TILE_B + base);
#pragma unroll
                for (int mt = 0; mt < 2; mt++) {
                    mma_f16(o[mt][2 * np],     pa[mt], v4);
                    mma_f16(o[mt][2 * np + 1], pa[mt], v4 + 2);
                }
            }
        }

        if (it + 2 < 32) load_stage((it + 2) % 3, (it + 2) * 64);
        CP_COMMIT();
    }

    // ---- epilogue: context hi/lo ----
#pragma unroll
    for (int mt = 0; mt < 2; mt++) {
        const float inv0 = 1.f / l_r[mt * 2];
        const float inv1 = 1.f / l_r[mt * 2 + 1];
        const int row0 = q0 + wid * 32 + mt * 16 + (lane >> 2);
#pragma unroll
        for (int t = 0; t < 8; t++) {
            const int col = h * 64 + t * 8 + (lane & 3) * 2;
            store_hilo(CH, CL, (size_t)(b * SEQ + row0) * D_MODEL + col,
                       o[mt][t][0] * inv0, o[mt][t][1] * inv0);
            store_hilo(CH, CL, (size_t)(b * SEQ + row0 + 8) * D_MODEL + col,
                       o[mt][t][2] * inv1, o[mt][t][3] * inv1);
        }
    }
}

// =================================================================================
// launch
// =================================================================================
extern "C" void kernel_launch(void* const* d_in, const int* in_sizes, int n_in,
                              void* d_out, int out_size)
{
    const float* x_q = (const float*)d_in[0];
    const float* x_k = (const float*)d_in[1];
    const float* x_v = (const float*)d_in[2];
    const float* wq  = (const float*)d_in[3];
    const float* bq  = (const float*)d_in[4];
    const float* wk  = (const float*)d_in[5];
    const float* bk  = (const float*)d_in[6];
    const float* wv  = (const float*)d_in[7];
    const float* bv  = (const float*)d_in[8];
    const float* wo  = (const float*)d_in[9];
    const float* bo  = (const float*)d_in[10];
    float* out = (float*)d_out;

    __half *x0, *x1, *x2, *q16, *k16, *v16, *vt, *ch, *cl;
    __half *w0, *w1, *w2, *w3;
    cudaGetSymbolAddress((void**)&x0,  g_X0);
    cudaGetSymbolAddress((void**)&x1,  g_X1);
    cudaGetSymbolAddress((void**)&x2,  g_X2);
    cudaGetSymbolAddress((void**)&q16, g_Q16);
    cudaGetSymbolAddress((void**)&k16, g_K16);
    cudaGetSymbolAddress((void**)&v16, g_V16);
    cudaGetSymbolAddress((void**)&vt,  g_VT);
    cudaGetSymbolAddress((void**)&ch,  g_CH);
    cudaGetSymbolAddress((void**)&cl,  g_CL);
    cudaGetSymbolAddress((void**)&w0,  g_W0);
    cudaGetSymbolAddress((void**)&w1,  g_W1);
    cudaGetSymbolAddress((void**)&w2,  g_W2);
    cudaGetSymbolAddress((void**)&w3,  g_W3);

    static int attr_set = 0;
    const int proj_smem = 3 * (GA_TILE + GB_TILE);       // 165888
    const int gemf_smem = 2 * (2 * GA_TILE + GB_TILE);   // 184320
    if (!attr_set) {
        cudaFuncSetAttribute(proj3_kernel,
                             cudaFuncAttributeMaxDynamicSharedMemorySize, proj_smem);
        cudaFuncSetAttribute(gemmF_kernel,
                             cudaFuncAttributeMaxDynamicSharedMemorySize, gemf_smem);
        cudaFuncSetAttribute(attention_mma_kernel,
                             cudaFuncAttributeMaxDynamicSharedMemorySize, A_SMEM_TOT);
        attr_set = 1;
    }

    const int NX = M_TOT * D_MODEL;
    const int NW = D_MODEL * D_MODEL;
    dim3 cb(256);

    // converts (fused 3-way)
    {
        Conv3Args cx; cx.src[0] = x_q; cx.src[1] = x_k; cx.src[2] = x_v;
        cx.dst[0] = x0; cx.dst[1] = x1; cx.dst[2] = x2;
        conv3_kernel<<<dim3((NX / 4 + 255) / 256, 1, 3), cb>>>(cx, NX);
        Conv3Args cw; cw.src[0] = wq; cw.src[1] = wk; cw.src[2] = wv;
        cw.dst[0] = w0; cw.dst[1] = w1; cw.dst[2] = w2;
        conv3_kernel<<<dim3((NW / 4 + 255) / 256, 1, 3), cb>>>(cw, NW);
        conv1_kernel<<<(NW / 4 + 255) / 256, cb>>>(wo, w3, NW);
    }

    // fused QKV projections (fp16 1-term; Q pre-scaled). CTA 256x128, BK=64.
    Proj3Args pa;
    pa.p[0] = { x0, w0, bq, q16, 0.125f };
    pa.p[1] = { x1, w1, bk, k16, 1.0f };
    pa.p[2] = { x2, w2, bv, v16, 1.0f };
    proj3_kernel<<<dim3(8, 32, 3), 256, proj_smem>>>(pa);

    // V transpose
    vtrans_kernel<<<dim3(SEQ / 32, 2, BATCH * NHEAD), 256>>>(v16, vt);

    // attention (pure fp16, 256 q-rows/CTA, context hi/lo out)
    attention_mma_kernel<<<dim3(SEQ / 256, BATCH * NHEAD), 256, A_SMEM_TOT>>>(
        q16, k16, vt, ch, cl);

    // output projection (C hi/lo x W, 2 products). CTA 256x128, BK=64, 2-stage.
    gemmF_kernel<<<dim3(8, 32), 256, gemf_smem>>>(ch, cl, w3, bo, out);
}

// round 13
// speedup vs baseline: 7.7536x; 1.1162x over previous
#include <cuda_runtime.h>
#include <cuda_fp16.h>
#include <math.h>
#include <cstdint>

#define D_MODEL 1024
#define NHEAD   16
#define D_K     64
#define BATCH   4
#define SEQ     2048
#define M_TOT   (BATCH * SEQ)   // 8192

// ---------------- scratch (device globals: allocation-free rule) ----------------
__device__ __half g_X0 [M_TOT * D_MODEL];
__device__ __half g_X1 [M_TOT * D_MODEL];
__device__ __half g_X2 [M_TOT * D_MODEL];
__device__ __half g_Q16[M_TOT * D_MODEL];
__device__ __half g_K16[M_TOT * D_MODEL];
__device__ __half g_V16[M_TOT * D_MODEL];
__device__ __half g_VT [M_TOT * D_MODEL];
__device__ __half g_CH [M_TOT * D_MODEL];
__device__ __half g_CL [M_TOT * D_MODEL];
__device__ __half g_W0 [D_MODEL * D_MODEL];
__device__ __half g_W1 [D_MODEL * D_MODEL];
__device__ __half g_W2 [D_MODEL * D_MODEL];
__device__ __half g_W3 [D_MODEL * D_MODEL];

// ====================== helpers ======================
__device__ __forceinline__ uint32_t smem_u32(const void* p) {
    uint32_t a;
    asm("{ .reg .u64 t; cvta.to.shared.u64 t, %1; cvt.u32.u64 %0, t; }" : "=r"(a) : "l"(p));
    return a;
}
__device__ __forceinline__ void ldsm4(uint32_t* r, uint32_t addr) {
    asm volatile("ldmatrix.sync.aligned.m8n8.x4.shared.b16 {%0,%1,%2,%3}, [%4];"
        : "=r"(r[0]), "=r"(r[1]), "=r"(r[2]), "=r"(r[3]) : "r"(addr));
}
__device__ __forceinline__ void mma_f16(float* c, const uint32_t* a, const uint32_t* b) {
    asm volatile("mma.sync.aligned.m16n8k16.row.col.f32.f16.f16.f32 "
        "{%0,%1,%2,%3}, {%4,%5,%6,%7}, {%8,%9}, {%0,%1,%2,%3};"
        : "+f"(c[0]), "+f"(c[1]), "+f"(c[2]), "+f"(c[3])
        : "r"(a[0]), "r"(a[1]), "r"(a[2]), "r"(a[3]), "r"(b[0]), "r"(b[1]));
}
__device__ __forceinline__ uint32_t pack_h(float x, float y) {
    __half2 h = __floats2half2_rn(x, y);
    return *(uint32_t*)&h;
}
__device__ __forceinline__ void store_hilo(__half* H, __half* L, size_t off, float x, float y) {
    __half hx = __float2half_rn(x), hy = __float2half_rn(y);
    __half lx = __float2half_rn(x - __half2float(hx));
    __half ly = __float2half_rn(y - __half2float(hy));
    *(__half2*)(H + off) = __halves2half2(hx, hy);
    *(__half2*)(L + off) = __halves2half2(lx, ly);
}
#define CP_ASYNC16(s, g) asm volatile("cp.async.cg.shared.global [%0], [%1], 16;" :: "r"(s), "l"(g) : "memory")
#define CP_COMMIT()      asm volatile("cp.async.commit_group;" ::: "memory")
#define CP_WAIT1()       asm volatile("cp.async.wait_group 1;" ::: "memory")
#define CP_WAIT0()       asm volatile("cp.async.wait_group 0;" ::: "memory")

// =================================================================================
// converts
// =================================================================================
struct Conv3Args { const float* src[3]; __half* dst[3]; };

__global__ void conv3_kernel(Conv3Args a, int n)
{
    const float* x = a.src[blockIdx.z];
    __half* o = a.dst[blockIdx.z];
    int idx = (blockIdx.x * blockDim.x + threadIdx.x) * 4;
    if (idx >= n) return;
    float4 v = *(const float4*)(x + idx);
    *(__half2*)(o + idx)     = __floats2half2_rn(v.x, v.y);
    *(__half2*)(o + idx + 2) = __floats2half2_rn(v.z, v.w);
}

__global__ void conv1_kernel(const float* __restrict__ x, __half* __restrict__ o, int n)
{
    int idx = (blockIdx.x * blockDim.x + threadIdx.x) * 4;
    if (idx >= n) return;
    float4 v = *(const float4*)(x + idx);
    *(__half2*)(o + idx)     = __floats2half2_rn(v.x, v.y);
    *(__half2*)(o + idx + 2) = __floats2half2_rn(v.z, v.w);
}

// V transpose: V16 [b*S+s][h*64+d] -> VT [(b*16+h)*64+d][S]
__global__ void vtrans_kernel(const __half* __restrict__ V, __half* __restrict__ VT)
{
    __shared__ __half t[32][33];
    const int s0 = blockIdx.x * 32;
    const int d0 = blockIdx.y * 32;
    const int bh = blockIdx.z;
    const int b = bh >> 4, h = bh & 15;
    const int tid = threadIdx.x;
    const int cx = tid & 31, cy = tid >> 5;

#pragma unroll
    for (int i = 0; i < 4; i++) {
        int s = s0 + cy + i * 8;
        t[cy + i * 8][cx] = V[(size_t)(b * SEQ + s) * D_MODEL + h * 64 + d0 + cx];
    }
    __syncthreads();
#pragma unroll
    for (int i = 0; i < 4; i++) {
        int d = d0 + cy + i * 8;
        VT[(size_t)(bh * 64 + d) * SEQ + s0 + cx] = t[cx][cy + i * 8];
    }
}

// =================================================================================
// 4-warp GEMM core: CTA 128x128, BK=64, warp tile 64x64 (warp grid 2x2).
// 128 threads -> 2 CTAs/SM (de-phased overlap + finer wave granularity).
// =================================================================================
#define G_ROWB   144                    // bytes per smem row (64 fp16 + 8 pad)
#define G_T128   (128 * G_ROWB)         // 18432 per 128-row tile

template<int NA>   // A-operand terms: 1 or 2. Tiles per stage = NA+1.
__device__ __forceinline__ void gemm_load_stage(
    uint32_t sb, int tid,
    const __half* srcA0, const __half* srcA1, const __half* srcB,
    int st, int k0)
{
    constexpr int STAGE_B = (NA + 1) * G_T128;
    constexpr int NCH = (NA * 128 + 128) * 8;     // 16B chunks per stage
#pragma unroll
    for (int i = 0; i < NCH / 128; i++) {
        const int c = tid + i * 128;
        const int row = c >> 3, ch = c & 7;
        const __half* g;
        uint32_t soff;
        if (row < 128) {
            g = srcA0 + (size_t)row * 1024;
            soff = (uint32_t)row * G_ROWB;
        } else if (NA == 2 && row < 256) {
            g = srcA1 + (size_t)(row - 128) * 1024;
            soff = G_T128 + (uint32_t)(row - 128) * G_ROWB;
        } else {
            const int br = row - NA * 128;
            g = srcB + (size_t)br * 1024;
            soff = NA * G_T128 + (uint32_t)br * G_ROWB;
        }
        CP_ASYNC16(sb + st * STAGE_B + soff + ch * 16, (const void*)(g + k0 + ch * 8));
    }
}

template<int NA>
__device__ __forceinline__ void gemm_compute_stage(
    uint32_t sb, int warp_m, int warp_n, uint32_t a_off, uint32_t b_off,
    int st, float acc[4][8][4])
{
    constexpr int STAGE_B = (NA + 1) * G_T128;
    const uint32_t s   = sb + st * STAGE_B;
    const uint32_t aB0 = s + (uint32_t)(warp_m * 64) * G_ROWB;
    const uint32_t aB1 = s + G_T128 + (uint32_t)(warp_m * 64) * G_ROWB;
    const uint32_t bB  = s + NA * G_T128 + (uint32_t)(warp_n * 64) * G_ROWB;
#pragma unroll
    for (int ks = 0; ks < 4; ks++) {
        uint32_t ah[4][4], al[4][4], bb[4][4];
#pragma unroll
        for (int mt = 0; mt < 4; mt++) {
            ldsm4(ah[mt], aB0 + (uint32_t)(mt * 16) * G_ROWB + ks * 32 + a_off);
            if (NA == 2)
                ldsm4(al[mt], aB1 + (uint32_t)(mt * 16) * G_ROWB + ks * 32 + a_off);
        }
#pragma unroll
        for (int p = 0; p < 4; p++)
            ldsm4(bb[p], bB + (uint32_t)(p * 16) * G_ROWB + ks * 32 + b_off);
#pragma unroll
        for (int mt = 0; mt < 4; mt++)
#pragma unroll
            for (int nt = 0; nt < 8; nt++) {
                float* c = acc[mt][nt];
                const uint32_t* bp = &bb[nt >> 1][(nt & 1) * 2];
                mma_f16(c, ah[mt], bp);
                if (NA == 2) mma_f16(c, al[mt], bp);
            }
    }
}

// ---- fused QKV projection: X fp16 x W fp16; fp16 output (scaled). 3-stage ring. ----
struct ProjOne {
    const __half *A, *W;
    const float* bias;
    __half *O;
    float scale;
};
struct Proj3Args { ProjOne p[3]; };

__global__ __launch_bounds__(128, 2)
void proj3_kernel(Proj3Args args)
{
    extern __shared__ __align__(128) char smem[];
    const ProjOne P = args.p[blockIdx.z];
    const uint32_t sb = smem_u32(smem);
    const int tid = threadIdx.x, lane = tid & 31, wid = tid >> 5;
    const int row0 = blockIdx.y * 128, col0 = blockIdx.x * 128;
    const int warp_m = wid >> 1, warp_n = wid & 1;
    const int la = lane & 7, lb8 = (lane >> 3) & 1, lb16 = lane >> 4;
    const uint32_t a_off = (uint32_t)((la + lb8 * 8) * G_ROWB + lb16 * 16);
    const uint32_t b_off = (uint32_t)((la + lb16 * 8) * G_ROWB + lb8 * 16);

    const __half* srcA = P.A + (size_t)row0 * 1024;
    const __half* srcB = P.W + (size_t)col0 * 1024;

    float acc[4][8][4];
#pragma unroll
    for (int a = 0; a < 4; a++)
#pragma unroll
        for (int b = 0; b < 8; b++)
#pragma unroll
            for (int c = 0; c < 4; c++) acc[a][b][c] = 0.f;

    gemm_load_stage<1>(sb, tid, srcA, nullptr, srcB, 0, 0);   CP_COMMIT();
    gemm_load_stage<1>(sb, tid, srcA, nullptr, srcB, 1, 64);  CP_COMMIT();
    for (int c = 0; c < 16; c++) {
        CP_WAIT1();
        __syncthreads();
        gemm_compute_stage<1>(sb, warp_m, warp_n, a_off, b_off, c % 3, acc);
        if (c + 2 < 16)
            gemm_load_stage<1>(sb, tid, srcA, nullptr, srcB, (c + 2) % 3, (c + 2) * 64);
        CP_COMMIT();
    }

    const int r_base = row0 + warp_m * 64, c_base = col0 + warp_n * 64;
#pragma unroll
    for (int mt = 0; mt < 4; mt++) {
        const int r = r_base + mt * 16 + (lane >> 2);
#pragma unroll
        for (int nt = 0; nt < 8; nt++) {
            const int cc = c_base + nt * 8 + (lane & 3) * 2;
            const float b0 = __ldg(P.bias + cc), b1 = __ldg(P.bias + cc + 1);
            *(__half2*)(P.O + (size_t)r * 1024 + cc) =
                __floats2half2_rn((acc[mt][nt][0] + b0) * P.scale,
                                  (acc[mt][nt][1] + b1) * P.scale);
            *(__half2*)(P.O + (size_t)(r + 8) * 1024 + cc) =
                __floats2half2_rn((acc[mt][nt][2] + b0) * P.scale,
                                  (acc[mt][nt][3] + b1) * P.scale);
        }
    }
}

// ---- output projection: C 2-term x W 1-term, fp32 out. 2-stage pipeline. ----
__global__ __launch_bounds__(128, 2)
void gemmF_kernel(const __half* __restrict__ Ch, const __half* __restrict__ Cl,
                  const __half* __restrict__ W,
                  const float* __restrict__ bias, float* __restrict__ C)
{
    extern __shared__ __align__(128) char smem[];
    const uint32_t sb = smem_u32(smem);
    const int tid = threadIdx.x, lane = tid & 31, wid = tid >> 5;
    const int row0 = blockIdx.y * 128, col0 = blockIdx.x * 128;
    const int warp_m = wid >> 1, warp_n = wid & 1;
    const int la = lane & 7, lb8 = (lane >> 3) & 1, lb16 = lane >> 4;
    const uint32_t a_off = (uint32_t)((la + lb8 * 8) * G_ROWB + lb16 * 16);
    const uint32_t b_off = (uint32_t)((la + lb16 * 8) * G_ROWB + lb8 * 16);

    const __half* srcA0 = Ch + (size_t)row0 * 1024;
    const __half* srcA1 = Cl + (size_t)row0 * 1024;
    const __half* srcB  = W  + (size_t)col0 * 1024;

    float acc[4][8][4];
#pragma unroll
    for (int a = 0; a < 4; a++)
#pragma unroll
        for (int b = 0; b < 8; b++)
#pragma unroll
            for (int c = 0; c < 4; c++) acc[a][b][c] = 0.f;

    gemm_load_stage<2>(sb, tid, srcA0, srcA1, srcB, 0, 0);   CP_COMMIT();
    for (int c = 0; c < 16; c++) {
        CP_WAIT0();
        __syncthreads();
        if (c + 1 < 16) {
            gemm_load_stage<2>(sb, tid, srcA0, srcA1, srcB, (c + 1) & 1, (c + 1) * 64);
            CP_COMMIT();
        }
        gemm_compute_stage<2>(sb, warp_m, warp_n, a_off, b_off, c & 1, acc);
        __syncthreads();
    }

    const int r_base = row0 + warp_m * 64, c_base = col0 + warp_n * 64;
#pragma unroll
    for (int mt = 0; mt < 4; mt++) {
        const int r = r_base + mt * 16 + (lane >> 2);
#pragma unroll
        for (int nt = 0; nt < 8; nt++) {
            const int cc = c_base + nt * 8 + (lane & 3) * 2;
            const float b0 = __ldg(bias + cc), b1 = __ldg(bias + cc + 1);
            float2 o0, o1;
            o0.x = acc[mt][nt][0] + b0; o0.y = acc[mt][nt][1] + b1;
            o1.x = acc[mt][nt][2] + b0; o1.y = acc[mt][nt][3] + b1;
            *(float2*)(C + (size_t)r * 1024 + cc)       = o0;
            *(float2*)(C + (size_t)(r + 8) * 1024 + cc) = o1;
        }
    }
}

// =================================================================================
// Flash attention: 4 warps / 128 threads, warp M-tile 32, 128 q-rows/CTA.
// KV stage = [K | Vt] (64 kv rows), 3-stage ring. Out: CH/CL hi/lo.
// =================================================================================
#define A_STRIDE_B 144
#define A_TILE_B   (64 * A_STRIDE_B)    // 9216
#define A_STAGE_B  (2 * A_TILE_B)       // 18432 (K|Vt)
#define A_SMEM_TOT (6 * A_TILE_B)       // 55296 (Q staging 18432 fits)

__global__ __launch_bounds__(128, 2)
void attention_mma_kernel(const __half* __restrict__ Q16,
                          const __half* __restrict__ K16, const __half* __restrict__ VT,
                          __half* __restrict__ CH, __half* __restrict__ CL)
{
    extern __shared__ __align__(128) char smem[];
    const uint32_t sb = smem_u32(smem);
    const int tid  = threadIdx.x;
    const int lane = tid & 31, wid = tid >> 5;   // wid 0..3
    const int bh = blockIdx.y;
    const int b = bh >> 4, h = bh & 15;
    const int q0 = blockIdx.x * 128;

    const int la   = lane & 7;
    const int lb8  = (lane >> 3) & 1;
    const int lb16 = lane >> 4;
    const uint32_t a_off = (uint32_t)((la + lb8 * 8) * A_STRIDE_B + lb16 * 16);
    const uint32_t b_off = (uint32_t)((la + lb16 * 8) * A_STRIDE_B + lb8 * 16);

    // ---- stage Q (128 rows) and move to registers (2 m-tiles per warp) ----
    {
#pragma unroll
        for (int i = 0; i < 8; i++) {
            int c = tid + i * 128;            // 0..1023
            int r = c >> 3, ch = c & 7;
            const size_t g = (size_t)(b * SEQ + q0 + r) * D_MODEL + h * 64 + ch * 8;
            CP_ASYNC16(sb + r * A_STRIDE_B + ch * 16, (const void*)(Q16 + g));
        }
        CP_COMMIT();
        CP_WAIT0();
        __syncthreads();
    }
    uint32_t qh[4][2][4];
#pragma unroll
    for (int ks = 0; ks < 4; ks++)
#pragma unroll
        for (int mt = 0; mt < 2; mt++)
            ldsm4(qh[ks][mt],
                  sb + (uint32_t)((wid * 32 + mt * 16)) * A_STRIDE_B + ks * 32 + a_off);
    __syncthreads();

    // ---- KV loader: 128 rows x 8 chunks = 1024 chunks; 8 per thread ----
    auto load_stage = [&](int st, int kv0) {
#pragma unroll
        for (int i = 0; i < 8; i++) {
            const int c = tid + i * 128;
            const int row = c >> 3, ch = c & 7;
            const __half* g;
            uint32_t soff;
            if (row < 64) {
                g = K16 + (size_t)(b * SEQ + kv0 + row) * D_MODEL + h * 64;
                soff = (uint32_t)row * A_STRIDE_B;
            } else {
                g = VT + (size_t)(bh * 64 + (row - 64)) * SEQ + kv0;
                soff = A_TILE_B + (uint32_t)(row - 64) * A_STRIDE_B;
            }
            CP_ASYNC16(sb + st * A_STAGE_B + soff + ch * 16, (const void*)(g + ch * 8));
        }
    };

    load_stage(0, 0);  CP_COMMIT();
    load_stage(1, 64); CP_COMMIT();

    float o[2][8][4];
#pragma unroll
    for (int mt = 0; mt < 2; mt++)
#pragma unroll
        for (int t = 0; t < 8; t++)
#pragma unroll
            for (int j = 0; j < 4; j++) o[mt][t][j] = 0.f;
    float m_r[4] = {-1e30f, -1e30f, -1e30f, -1e30f};
    float l_r[4] = {0.f, 0.f, 0.f, 0.f};

    for (int it = 0; it < 32; it++) {
        CP_WAIT1();
        __syncthreads();
        const uint32_t st = sb + (it % 3) * A_STAGE_B;

        // ---- S = Q K^T ----
        float s[2][8][4];
#pragma unroll
        for (int mt = 0; mt < 2; mt++)
#pragma unroll
            for (int t = 0; t < 8; t++)
#pragma unroll
                for (int j = 0; j < 4; j++) s[mt][t][j] = 0.f;
#pragma unroll
        for (int ks = 0; ks < 4; ks++) {
#pragma unroll
            for (int np = 0; np < 4; np++) {
                uint32_t k4[4];
                const uint32_t base = (uint32_t)(np * 16) * A_STRIDE_B + ks * 32 + b_off;
                ldsm4(k4, st + base);
#pragma unroll
                for (int mt = 0; mt < 2; mt++) {
                    mma_f16(s[mt][2 * np],     qh[ks][mt], k4);
                    mma_f16(s[mt][2 * np + 1], qh[ks][mt], k4 + 2);
                }
            }
        }

        // ---- online softmax (4 rows per thread: mt x r) ----
#pragma unroll
        for (int mt = 0; mt < 2; mt++)
#pragma unroll
            for (int r = 0; r < 2; r++) {
                const int ri = mt * 2 + r;
                float mx = s[mt][0][2 * r];
#pragma unroll
                for (int t = 0; t < 8; t++) {
                    mx = fmaxf(mx, s[mt][t][2 * r]);
                    mx = fmaxf(mx, s[mt][t][2 * r + 1]);
                }
                mx = fmaxf(mx, __shfl_xor_sync(0xffffffffu, mx, 1));
                mx = fmaxf(mx, __shfl_xor_sync(0xffffffffu, mx, 2));
                float mn = fmaxf(m_r[ri], mx);
                float al = __expf(m_r[ri] - mn);
                m_r[ri] = mn;
                float sum = 0.f;
#pragma unroll
                for (int t = 0; t < 8; t++) {
                    float p0 = __expf(s[mt][t][2 * r]     - mn);
                    float p1 = __expf(s[mt][t][2 * r + 1] - mn);
                    s[mt][t][2 * r] = p0; s[mt][t][2 * r + 1] = p1;
                    sum += p0 + p1;
                }
                sum += __shfl_xor_sync(0xffffffffu, sum, 1);
                sum += __shfl_xor_sync(0xffffffffu, sum, 2);
                l_r[ri] = l_r[ri] * al + sum;
#pragma unroll
                for (int t = 0; t < 8; t++) {
                    o[mt][t][2 * r] *= al; o[mt][t][2 * r + 1] *= al;
                }
            }

        // ---- O += P V ----
#pragma unroll
        for (int ks = 0; ks < 4; ks++) {
            const int t0 = 2 * ks, t1 = 2 * ks + 1;
            uint32_t pa[2][4];
#pragma unroll
            for (int mt = 0; mt < 2; mt++) {
                pa[mt][0] = pack_h(s[mt][t0][0], s[mt][t0][1]);
                pa[mt][1] = pack_h(s[mt][t0][2], s[mt][t0][3]);
                pa[mt][2] = pack_h(s[mt][t1][0], s[mt][t1][1]);
                pa[mt][3] = pack_h(s[mt][t1][2], s[mt][t1][3]);
            }
#pragma unroll
            for (int np = 0; np < 4; np++) {
                uint32_t v4[4];
                const uint32_t base = (uint32_t)(np * 16) * A_STRIDE_B + ks * 32 + b_off;
                ldsm4(v4, st + A_TILE_B + base);
#pragma unroll
                for (int mt = 0; mt < 2; mt++) {
                    mma_f16(o[mt][2 * np],     pa[mt], v4);
                    mma_f16(o[mt][2 * np + 1], pa[mt], v4 + 2);
                }
            }
        }

        if (it + 2 < 32) load_stage((it + 2) % 3, (it + 2) * 64);
        CP_COMMIT();
    }

    // ---- epilogue: context hi/lo ----
#pragma unroll
    for (int mt = 0; mt < 2; mt++) {
        const float inv0 = 1.f / l_r[mt * 2];
        const float inv1 = 1.f / l_r[mt * 2 + 1];
        const int row0 = q0 + wid * 32 + mt * 16 + (lane >> 2);
#pragma unroll
        for (int t = 0; t < 8; t++) {
            const int col = h * 64 + t * 8 + (lane & 3) * 2;
            store_hilo(CH, CL, (size_t)(b * SEQ + row0) * D_MODEL + col,
                       o[mt][t][0] * inv0, o[mt][t][1] * inv0);
            store_hilo(CH, CL, (size_t)(b * SEQ + row0 + 8) * D_MODEL + col,
                       o[mt][t][2] * inv1, o[mt][t][3] * inv1);
        }
    }
}

// =================================================================================
// launch
// =================================================================================
extern "C" void kernel_launch(void* const* d_in, const int* in_sizes, int n_in,
                              void* d_out, int out_size)
{
    const float* x_q = (const float*)d_in[0];
    const float* x_k = (const float*)d_in[1];
    const float* x_v = (const float*)d_in[2];
    const float* wq  = (const float*)d_in[3];
    const float* bq  = (const float*)d_in[4];
    const float* wk  = (const float*)d_in[5];
    const float* bk  = (const float*)d_in[6];
    const float* wv  = (const float*)d_in[7];
    const float* bv  = (const float*)d_in[8];
    const float* wo  = (const float*)d_in[9];
    const float* bo  = (const float*)d_in[10];
    float* out = (float*)d_out;

    __half *x0, *x1, *x2, *q16, *k16, *v16, *vt, *ch, *cl;
    __half *w0, *w1, *w2, *w3;
    cudaGetSymbolAddress((void**)&x0,  g_X0);
    cudaGetSymbolAddress((void**)&x1,  g_X1);
    cudaGetSymbolAddress((void**)&x2,  g_X2);
    cudaGetSymbolAddress((void**)&q16, g_Q16);
    cudaGetSymbolAddress((void**)&k16, g_K16);
    cudaGetSymbolAddress((void**)&v16, g_V16);
    cudaGetSymbolAddress((void**)&vt,  g_VT);
    cudaGetSymbolAddress((void**)&ch,  g_CH);
    cudaGetSymbolAddress((void**)&cl,  g_CL);
    cudaGetSymbolAddress((void**)&w0,  g_W0);
    cudaGetSymbolAddress((void**)&w1,  g_W1);
    cudaGetSymbolAddress((void**)&w2,  g_W2);
    cudaGetSymbolAddress((void**)&w3,  g_W3);

    static int attr_set = 0;
    const int proj_smem = 3 * 2 * G_T128;   // 110592
    const int gemf_smem = 2 * 3 * G_T128;   // 110592
    if (!attr_set) {
        cudaFuncSetAttribute(proj3_kernel,
                             cudaFuncAttributeMaxDynamicSharedMemorySize, proj_smem);
        cudaFuncSetAttribute(gemmF_kernel,
                             cudaFuncAttributeMaxDynamicSharedMemorySize, gemf_smem);
        cudaFuncSetAttribute(attention_mma_kernel,
                             cudaFuncAttributeMaxDynamicSharedMemorySize, A_SMEM_TOT);
        attr_set = 1;
    }

    const int NX = M_TOT * D_MODEL;
    const int NW = D_MODEL * D_MODEL;
    dim3 cb(256);

    // converts (fused 3-way)
    {
        Conv3Args cx; cx.src[0] = x_q; cx.src[1] = x_k; cx.src[2] = x_v;
        cx.dst[0] = x0; cx.dst[1] = x1; cx.dst[2] = x2;
        conv3_kernel<<<dim3((NX / 4 + 255) / 256, 1, 3), cb>>>(cx, NX);
        Conv3Args cw; cw.src[0] = wq; cw.src[1] = wk; cw.src[2] = wv;
        cw.dst[0] = w0; cw.dst[1] = w1; cw.dst[2] = w2;
        conv3_kernel<<<dim3((NW / 4 + 255) / 256, 1, 3), cb>>>(cw, NW);
        conv1_kernel<<<(NW / 4 + 255) / 256, cb>>>(wo, w3, NW);
    }

    // fused QKV projections (fp16 1-term; Q pre-scaled). CTA 128x128, BK=64, 128 thr.
    Proj3Args pa;
    pa.p[0] = { x0, w0, bq, q16, 0.125f };
    pa.p[1] = { x1, w1, bk, k16, 1.0f };
    pa.p[2] = { x2, w2, bv, v16, 1.0f };
    proj3_kernel<<<dim3(8, 64, 3), 128, proj_smem>>>(pa);

    // V transpose
    vtrans_kernel<<<dim3(SEQ / 32, 2, BATCH * NHEAD), 256>>>(v16, vt);

    // attention (pure fp16, 128 q-rows/CTA, 128 thr, context hi/lo out)
    attention_mma_kernel<<<dim3(SEQ / 128, BATCH * NHEAD), 128, A_SMEM_TOT>>>(
        q16, k16, vt, ch, cl);

    // output projection (C hi/lo x W, 2 products). CTA 128x128, BK=64, 2-stage, 128 thr.
    gemmF_kernel<<<dim3(8, 64), 128, gemf_smem>>>(ch, cl, w3, bo, out);
}